// round 7
// baseline (speedup 1.0000x reference)
#include <cuda_runtime.h>
#include <math.h>

// Problem constants
#define Bc  2
#define Sc  2048
#define Ec  1024
#define Hc  16
#define Dc  64
#define FFc 4096

// ---------------------------------------------------------------------------
// Scratch (static device globals; allocation inside kernel_launch is banned)
// ---------------------------------------------------------------------------
__device__ float g_attn[(size_t)Bc * Sc * Ec];   // attention output (pre-Wo)
__device__ float g_x   [(size_t)Bc * Sc * Ec];   // LN1 output
__device__ float g_t   [(size_t)Bc * Sc * Ec];   // pre-LN buffer (reused)
__device__ float g_h   [(size_t)Bc * Sc * FFc];  // FFN hidden (64MB)
__device__ float g_part[Bc * 16 * Ec];           // column-mean partials
__device__ float g_xavg[Bc * Ec];
__device__ float g_gpart[8 * Bc * Ec];           // gate GEMV partials
__device__ float g_gate[Bc * Ec];

// ---------------------------------------------------------------------------
// Column mean of query over sequence axis: xavg[b][e] = mean_s q[b,s,e]
// ---------------------------------------------------------------------------
__global__ void colmean_part_kernel(const float* __restrict__ q, float* __restrict__ part)
{
    const int b = blockIdx.x;      // 0..Bc-1
    const int p = blockIdx.y;      // 0..15 (s-slice of 128 rows)
    const int tid = threadIdx.x;   // 256 threads, float4 each -> 1024 cols
    const float* base = q + (size_t)b * Sc * Ec + (size_t)p * 128 * Ec;
    float4 acc = make_float4(0.f, 0.f, 0.f, 0.f);
#pragma unroll 4
    for (int s = 0; s < 128; ++s) {
        float4 v = ((const float4*)(base + (size_t)s * Ec))[tid];
        acc.x += v.x; acc.y += v.y; acc.z += v.z; acc.w += v.w;
    }
    ((float4*)(part + (size_t)(b * 16 + p) * Ec))[tid] = acc;
}

__global__ void colmean_fin_kernel(const float* __restrict__ part, float* __restrict__ xavg)
{
    const int b = blockIdx.x;
    const int tid = threadIdx.x;
    float4 acc = make_float4(0.f, 0.f, 0.f, 0.f);
#pragma unroll
    for (int p = 0; p < 16; ++p) {
        float4 v = ((const float4*)(part + (size_t)(b * 16 + p) * Ec))[tid];
        acc.x += v.x; acc.y += v.y; acc.z += v.z; acc.w += v.w;
    }
    const float inv = 1.0f / (float)Sc;
    ((float4*)(xavg + (size_t)b * Ec))[tid] =
        make_float4(acc.x * inv, acc.y * inv, acc.z * inv, acc.w * inv);
}

// ---------------------------------------------------------------------------
// Gate: sigmoid(xavg @ Wg + bg)   (split-K GEMV)
// ---------------------------------------------------------------------------
__global__ void gate_part_kernel(const float* __restrict__ xavg, const float* __restrict__ Wg,
                                 float* __restrict__ gp)
{
    const int idx = blockIdx.x * 256 + threadIdx.x;   // 0..Bc*Ec-1
    const int b = idx >> 10;
    const int e = idx & (Ec - 1);
    const int k0 = blockIdx.y * 128;
    const float* xa = xavg + (size_t)b * Ec;
    float acc = 0.f;
#pragma unroll 8
    for (int k = 0; k < 128; ++k)
        acc = fmaf(xa[k0 + k], Wg[(size_t)(k0 + k) * Ec + e], acc);
    gp[(size_t)blockIdx.y * (Bc * Ec) + idx] = acc;
}

__global__ void gate_fin_kernel(const float* __restrict__ gp, const float* __restrict__ bg,
                                float* __restrict__ gate)
{
    const int idx = blockIdx.x * 256 + threadIdx.x;
    const int e = idx & (Ec - 1);
    float acc = bg[e];
#pragma unroll
    for (int ky = 0; ky < 8; ++ky) acc += gp[(size_t)ky * (Bc * Ec) + idx];
    gate[idx] = 1.0f / (1.0f + expf(-acc));
}

// ---------------------------------------------------------------------------
// Causal flash attention (fp32). Block = 256 thr, 64x64 Q/K tiles, D=64.
// Heads are contiguous 64-wide slices of E. Scale applied after mask
// (equivalent: masked entries -> p = 0).
// ---------------------------------------------------------------------------
#define FAP 68   // smem pitch (floats)

__global__ __launch_bounds__(256)
void flash_attn_kernel(const float* __restrict__ Q, const float* __restrict__ K,
                       const float* __restrict__ V, float* __restrict__ O)
{
    extern __shared__ float sm[];
    float* Qs = sm;                  // [64][FAP] transposed: Qs[d][i]
    float* Ks = sm + 64 * FAP;       // transposed: Ks[d][j]
    float* Vs = sm + 2 * 64 * FAP;   // natural:    Vs[j][n]
    float* Ps = sm + 3 * 64 * FAP;   // natural:    Ps[i][j]

    const int qt = blockIdx.x;           // q tile (0..31)
    const int bh = blockIdx.y;           // b*H + h (0..31)
    const int b = bh >> 4, h = bh & 15;
    const int tid = threadIdx.x;
    const int ty = tid >> 4, tx = tid & 15;
    const size_t headoff = (size_t)b * Sc * Ec + (size_t)h * Dc;

    // Load Q tile, transposed into smem
    {
        const float* Qp = Q + headoff + (size_t)(qt * 64) * Ec;
        for (int t = tid; t < 1024; t += 256) {
            int r = t >> 4, c = (t & 15) * 4;
            float4 v = *(const float4*)(Qp + (size_t)r * Ec + c);
            Qs[(c + 0) * FAP + r] = v.x;
            Qs[(c + 1) * FAP + r] = v.y;
            Qs[(c + 2) * FAP + r] = v.z;
            Qs[(c + 3) * FAP + r] = v.w;
        }
    }

    float o[4][4];
    float mrow[4], lrow[4];
#pragma unroll
    for (int i = 0; i < 4; ++i) {
        mrow[i] = -1e30f; lrow[i] = 0.f;
#pragma unroll
        for (int j = 0; j < 4; ++j) o[i][j] = 0.f;
    }
    __syncthreads();

    for (int kt = 0; kt <= qt; ++kt) {
        __syncthreads();  // prev iteration's PV done reading Ks/Vs/Ps
        {
            const float* Kp = K + headoff + (size_t)(kt * 64) * Ec;
            const float* Vp = V + headoff + (size_t)(kt * 64) * Ec;
            for (int t = tid; t < 1024; t += 256) {
                int r = t >> 4, c = (t & 15) * 4;
                float4 kv = *(const float4*)(Kp + (size_t)r * Ec + c);
                Ks[(c + 0) * FAP + r] = kv.x;
                Ks[(c + 1) * FAP + r] = kv.y;
                Ks[(c + 2) * FAP + r] = kv.z;
                Ks[(c + 3) * FAP + r] = kv.w;
                float4 vv = *(const float4*)(Vp + (size_t)r * Ec + c);
                *(float4*)&Vs[r * FAP + c] = vv;
            }
        }
        __syncthreads();

        // S = Q K^T  (64x64, 4x4 per thread)
        float sc[4][4];
#pragma unroll
        for (int i = 0; i < 4; ++i)
#pragma unroll
            for (int j = 0; j < 4; ++j) sc[i][j] = 0.f;

#pragma unroll
        for (int d = 0; d < 64; ++d) {
            float4 aq = *(const float4*)&Qs[d * FAP + ty * 4];
            float4 bk = *(const float4*)&Ks[d * FAP + tx * 4];
            float a[4] = {aq.x, aq.y, aq.z, aq.w};
            float bb[4] = {bk.x, bk.y, bk.z, bk.w};
#pragma unroll
            for (int i = 0; i < 4; ++i)
#pragma unroll
                for (int j = 0; j < 4; ++j)
                    sc[i][j] = fmaf(a[i], bb[j], sc[i][j]);
        }

        const bool diag = (kt == qt);
#pragma unroll
        for (int i = 0; i < 4; ++i) {
#pragma unroll
            for (int j = 0; j < 4; ++j) {
                float v = sc[i][j] * 0.125f;                  // 1/sqrt(64)
                if (diag && (tx * 4 + j > ty * 4 + i)) v = -1e30f;
                sc[i][j] = v;
            }
            // row max across the 16-lane group owning this row
            float mx = fmaxf(fmaxf(sc[i][0], sc[i][1]), fmaxf(sc[i][2], sc[i][3]));
#pragma unroll
            for (int ofs = 8; ofs > 0; ofs >>= 1)
                mx = fmaxf(mx, __shfl_xor_sync(0xffffffffu, mx, ofs));
            float mn = fmaxf(mrow[i], mx);
            float corr = __expf(mrow[i] - mn);
            float rs = 0.f;
#pragma unroll
            for (int j = 0; j < 4; ++j) {
                float p = __expf(sc[i][j] - mn);
                sc[i][j] = p; rs += p;
            }
#pragma unroll
            for (int ofs = 8; ofs > 0; ofs >>= 1)
                rs += __shfl_xor_sync(0xffffffffu, rs, ofs);
            lrow[i] = lrow[i] * corr + rs;
            mrow[i] = mn;
#pragma unroll
            for (int j = 0; j < 4; ++j) o[i][j] *= corr;
        }

        // Write P to smem
#pragma unroll
        for (int i = 0; i < 4; ++i)
            *(float4*)&Ps[(ty * 4 + i) * FAP + tx * 4] =
                make_float4(sc[i][0], sc[i][1], sc[i][2], sc[i][3]);
        __syncthreads();

        // O += P @ V
#pragma unroll 8
        for (int j = 0; j < 64; ++j) {
            float av[4];
#pragma unroll
            for (int i = 0; i < 4; ++i) av[i] = Ps[(ty * 4 + i) * FAP + j];
            float4 bv = *(const float4*)&Vs[j * FAP + tx * 4];
            float bb[4] = {bv.x, bv.y, bv.z, bv.w};
#pragma unroll
            for (int i = 0; i < 4; ++i)
#pragma unroll
                for (int jj = 0; jj < 4; ++jj)
                    o[i][jj] = fmaf(av[i], bb[jj], o[i][jj]);
        }
    }

    // Normalize and store
    float* Op = O + headoff + (size_t)(qt * 64) * Ec;
#pragma unroll
    for (int i = 0; i < 4; ++i) {
        float inv = 1.0f / lrow[i];
        *(float4*)(Op + (size_t)(ty * 4 + i) * Ec + tx * 4) =
            make_float4(o[i][0] * inv, o[i][1] * inv, o[i][2] * inv, o[i][3] * inv);
    }
}

// ---------------------------------------------------------------------------
// SGEMM 128x128, BK=8, 256 threads, 8x8/thread, double-buffered smem.
// Row-major A(MxK) @ B(KxN) -> C(MxN). M,N,K multiples of 128/128/8.
// EPI 0: C = gate[b][n]*(acc + bias[n]) + aux2[m*N+n]   (Wo + gate + residual)
// EPI 1: C = gelu_exact(acc + bias[n])
// EPI 2: C = acc + bias[n] + aux1[m*N+n]                (W2 + residual)
// ---------------------------------------------------------------------------
template <int EPI>
__global__ __launch_bounds__(256)
void sgemm128(const float* __restrict__ A, const float* __restrict__ B,
              float* __restrict__ C, int M, int N, int K,
              const float* __restrict__ bias,
              const float* __restrict__ aux1, const float* __restrict__ aux2)
{
    __shared__ float As[2][8][128];  // transposed: As[k][m]
    __shared__ float Bs[2][8][128];  // natural:    Bs[k][n]

    const int tid = threadIdx.x;
    const int ty = tid >> 4, tx = tid & 15;
    const int bm = blockIdx.y * 128, bn = blockIdx.x * 128;

    const int ar = tid >> 1,  ak = (tid & 1) * 4;   // A loader: 128 rows x 8 cols
    const int br = tid >> 5,  bc = (tid & 31) * 4;  // B loader: 8 rows x 128 cols

    const float* Aptr = A + (size_t)(bm + ar) * K + ak;
    const float* Bptr = B + (size_t)br * N + bn + bc;

    // preload tile 0
    {
        float4 av = *(const float4*)Aptr;
        float4 bv = *(const float4*)Bptr;
        As[0][ak + 0][ar] = av.x;
        As[0][ak + 1][ar] = av.y;
        As[0][ak + 2][ar] = av.z;
        As[0][ak + 3][ar] = av.w;
        *(float4*)&Bs[0][br][bc] = bv;
    }
    __syncthreads();

    float acc[8][8];
#pragma unroll
    for (int i = 0; i < 8; ++i)
#pragma unroll
        for (int j = 0; j < 8; ++j) acc[i][j] = 0.f;

    const int nt = K >> 3;
    int cur = 0;
    for (int t = 0; t < nt; ++t) {
        float4 an, bnv;
        const bool more = (t + 1 < nt);
        if (more) {
            an  = *(const float4*)(Aptr + (size_t)(t + 1) * 8);
            bnv = *(const float4*)(Bptr + (size_t)(t + 1) * 8 * N);
        }
#pragma unroll
        for (int k = 0; k < 8; ++k) {
            float a[8], bb[8];
            *(float4*)&a[0] = *(const float4*)&As[cur][k][ty * 4];
            *(float4*)&a[4] = *(const float4*)&As[cur][k][64 + ty * 4];
            *(float4*)&bb[0] = *(const float4*)&Bs[cur][k][tx * 4];
            *(float4*)&bb[4] = *(const float4*)&Bs[cur][k][64 + tx * 4];
#pragma unroll
            for (int i = 0; i < 8; ++i)
#pragma unroll
                for (int j = 0; j < 8; ++j)
                    acc[i][j] = fmaf(a[i], bb[j], acc[i][j]);
        }
        if (more) {
            const int nx = cur ^ 1;
            As[nx][ak + 0][ar] = an.x;
            As[nx][ak + 1][ar] = an.y;
            As[nx][ak + 2][ar] = an.z;
            As[nx][ak + 3][ar] = an.w;
            *(float4*)&Bs[nx][br][bc] = bnv;
        }
        __syncthreads();
        cur ^= 1;
    }

    // Epilogue
#pragma unroll
    for (int i = 0; i < 8; ++i) {
        const int gr = bm + ((i < 4) ? (ty * 4 + i) : (60 + ty * 4 + i));
#pragma unroll
        for (int jh = 0; jh < 2; ++jh) {
            const int gc = bn + jh * 64 + tx * 4;
            float outv[4];
#pragma unroll
            for (int j = 0; j < 4; ++j) {
                float v = acc[i][jh * 4 + j];
                const int c = gc + j;
                if (EPI == 0) {
                    float gt = aux1[((gr >> 11) << 10) + c];   // gate[b][c]
                    v = gt * (v + bias[c]) + aux2[(size_t)gr * N + c];
                } else if (EPI == 1) {
                    float x = v + bias[c];
                    v = 0.5f * x * (1.0f + erff(x * 0.70710678118654752f));
                } else {
                    v = v + bias[c] + aux1[(size_t)gr * N + c];
                }
                outv[j] = v;
            }
            *(float4*)(C + (size_t)gr * N + gc) =
                make_float4(outv[0], outv[1], outv[2], outv[3]);
        }
    }
}

// ---------------------------------------------------------------------------
// LayerNorm over last dim (1024), one row per block, 256 threads (float4 each)
// ---------------------------------------------------------------------------
__global__ void ln1024_kernel(const float* __restrict__ in, const float* __restrict__ g,
                              const float* __restrict__ be, float* __restrict__ out)
{
    __shared__ float red[16];
    const int row = blockIdx.x;
    const int tid = threadIdx.x;
    float4 v = ((const float4*)(in + (size_t)row * Ec))[tid];
    float s = v.x + v.y + v.z + v.w;
    float q = v.x * v.x + v.y * v.y + v.z * v.z + v.w * v.w;
#pragma unroll
    for (int ofs = 16; ofs > 0; ofs >>= 1) {
        s += __shfl_xor_sync(0xffffffffu, s, ofs);
        q += __shfl_xor_sync(0xffffffffu, q, ofs);
    }
    const int w = tid >> 5;
    if ((tid & 31) == 0) { red[w] = s; red[8 + w] = q; }
    __syncthreads();
    s = 0.f; q = 0.f;
#pragma unroll
    for (int i = 0; i < 8; ++i) { s += red[i]; q += red[8 + i]; }
    const float mu = s * (1.0f / 1024.0f);
    const float var = q * (1.0f / 1024.0f) - mu * mu;
    const float rs = rsqrtf(var + 1e-5f);
    float4 gg = ((const float4*)g)[tid];
    float4 bb = ((const float4*)be)[tid];
    float4 o;
    o.x = (v.x - mu) * rs * gg.x + bb.x;
    o.y = (v.y - mu) * rs * gg.y + bb.y;
    o.z = (v.z - mu) * rs * gg.z + bb.z;
    o.w = (v.w - mu) * rs * gg.w + bb.w;
    ((float4*)(out + (size_t)row * Ec))[tid] = o;
}

// ---------------------------------------------------------------------------
// kernel_launch
// ---------------------------------------------------------------------------
extern "C" void kernel_launch(void* const* d_in, const int* in_sizes, int n_in,
                              void* d_out, int out_size)
{
    (void)in_sizes; (void)n_in; (void)out_size;
    const float* Vv  = (const float*)d_in[0];
    const float* Kk  = (const float*)d_in[1];
    const float* Qq  = (const float*)d_in[2];
    // d_in[3] = mask (int32 causal tril) — structure known, not needed
    const float* Wo  = (const float*)d_in[4];
    const float* bo  = (const float*)d_in[5];
    const float* Wg  = (const float*)d_in[6];
    const float* bg  = (const float*)d_in[7];
    const float* g1  = (const float*)d_in[8];
    const float* b1  = (const float*)d_in[9];
    const float* g2  = (const float*)d_in[10];
    const float* b2  = (const float*)d_in[11];
    const float* W1  = (const float*)d_in[12];
    const float* bf1 = (const float*)d_in[13];
    const float* W2  = (const float*)d_in[14];
    const float* bf2 = (const float*)d_in[15];
    float* out = (float*)d_out;

    float *p_attn, *p_x, *p_t, *p_h, *p_part, *p_xavg, *p_gpart, *p_gate;
    cudaGetSymbolAddress((void**)&p_attn,  g_attn);
    cudaGetSymbolAddress((void**)&p_x,     g_x);
    cudaGetSymbolAddress((void**)&p_t,     g_t);
    cudaGetSymbolAddress((void**)&p_h,     g_h);
    cudaGetSymbolAddress((void**)&p_part,  g_part);
    cudaGetSymbolAddress((void**)&p_xavg,  g_xavg);
    cudaGetSymbolAddress((void**)&p_gpart, g_gpart);
    cudaGetSymbolAddress((void**)&p_gate,  g_gate);

    const int fa_smem = 4 * 64 * FAP * (int)sizeof(float);  // 69632 B
    cudaFuncSetAttribute(flash_attn_kernel,
                         cudaFuncAttributeMaxDynamicSharedMemorySize, fa_smem);

    // gate path (tiny, off critical compute path)
    colmean_part_kernel<<<dim3(Bc, 16), 256>>>(Qq, p_part);
    colmean_fin_kernel<<<Bc, 256>>>(p_part, p_xavg);
    gate_part_kernel<<<dim3(Bc * Ec / 256, 8), 256>>>(p_xavg, Wg, p_gpart);
    gate_fin_kernel<<<Bc * Ec / 256, 256>>>(p_gpart, bg, p_gate);

    // causal attention
    flash_attn_kernel<<<dim3(Sc / 64, Bc * Hc), 256, fa_smem>>>(Qq, Kk, Vv, p_attn);

    // fc_out + gate*(.)+query residual -> LN1
    sgemm128<0><<<dim3(Ec / 128, Bc * Sc / 128), 256>>>(
        p_attn, Wo, p_t, Bc * Sc, Ec, Ec, bo, p_gate, Qq);
    ln1024_kernel<<<Bc * Sc, 256>>>(p_t, g1, b1, p_x);

    // FFN
    sgemm128<1><<<dim3(FFc / 128, Bc * Sc / 128), 256>>>(
        p_x, W1, p_h, Bc * Sc, FFc, Ec, bf1, nullptr, nullptr);
    sgemm128<2><<<dim3(Ec / 128, Bc * Sc / 128), 256>>>(
        p_h, W2, p_t, Bc * Sc, Ec, FFc, bf2, p_x, nullptr);

    ln1024_kernel<<<Bc * Sc, 256>>>(p_t, g2, b2, out);
}

// round 12
// speedup vs baseline: 1.6001x; 1.6001x over previous
#include <cuda_runtime.h>
#include <cuda_bf16.h>
#include <math.h>
#include <stdint.h>

// Problem constants
#define Bc  2
#define Sc  2048
#define Ec  1024
#define Hc  16
#define Dc  64
#define FFc 4096
#define Mrows (Bc * Sc)   // 4096

// tcgen05 is an arch-accelerated ('a') feature; only emit it when the device
// pass actually targets sm_103a-family. Otherwise use mma.sync (sm_80+ PTX).
#if defined(__CUDA_ARCH__) && defined(__CUDA_ARCH_FEAT_SM103_ALL)
#define TGEMM_TCGEN05 1
#else
#define TGEMM_TCGEN05 0
#endif

// ---------------------------------------------------------------------------
// PTX helpers
// ---------------------------------------------------------------------------
__device__ __forceinline__ uint32_t smem_to_u32(const void* p) {
    uint32_t a;
    asm("{ .reg .u64 t; cvta.to.shared.u64 t, %1; cvt.u32.u64 %0, t; }" : "=r"(a) : "l"(p));
    return a;
}
__device__ __forceinline__ uint32_t elect_one_pred() {
    uint32_t pred;
    asm volatile("{\n\t.reg .pred p;\n\telect.sync _|p, 0xFFFFFFFF;\n\tselp.b32 %0, 1, 0, p;\n\t}" : "=r"(pred));
    return pred;
}
#define MBARRIER_INIT(addr, cnt) \
    asm volatile("mbarrier.init.shared.b64 [%0], %1;" :: "r"((uint32_t)(addr)), "r"((uint32_t)(cnt)) : "memory")
#define MBARRIER_WAIT_PARITY(addr, par) do {                                   \
    uint32_t _m = (uint32_t)(addr), _p = (uint32_t)(par), _d;                  \
    asm volatile("{\n\t.reg .pred p;\n\t"                                      \
        "mbarrier.try_wait.parity.acquire.cta.shared::cta.b64 p, [%1], %2;\n\t" \
        "selp.b32 %0, 1, 0, p;\n\t}" : "=r"(_d) : "r"(_m), "r"(_p) : "memory"); \
    if (!_d) {                                                                 \
        asm volatile("{\n\t.reg .pred P1;\n\t"                                 \
            "WL_%=:\n\t"                                                       \
            "mbarrier.try_wait.parity.acquire.cta.shared::cta.b64 P1, [%0], %1, 0x989680;\n\t" \
            "@P1 bra.uni WD_%=;\n\tbra.uni WL_%=;\n\tWD_%=:\n\t}"              \
            :: "r"(_m), "r"(_p) : "memory");                                   \
    } } while (0)

#if TGEMM_TCGEN05
#define TCGEN05_ALLOC(sm_addr, n) \
    asm volatile("tcgen05.alloc.cta_group::1.sync.aligned.shared::cta.b32 [%0], %1;" \
                 :: "r"((uint32_t)(sm_addr)), "r"((uint32_t)(n)) : "memory")
#define TCGEN05_DEALLOC(tm, n) \
    asm volatile("tcgen05.dealloc.cta_group::1.sync.aligned.b32 %0, %1;" :: "r"(tm), "r"((uint32_t)(n)))
#define TCGEN05_RELINQ() \
    asm volatile("tcgen05.relinquish_alloc_permit.cta_group::1.sync.aligned;")
#define TCGEN05_COMMIT(mb) \
    asm volatile("tcgen05.commit.cta_group::1.mbarrier::arrive::one.shared::cluster.b64 [%0];" \
                 :: "r"((uint32_t)(mb)) : "memory")
#define TCGEN05_WAIT_LD()  asm volatile("tcgen05.wait::ld.sync.aligned;" ::: "memory")
#define TCGEN05_FENCE_AFTER()  asm volatile("tcgen05.fence::after_thread_sync;" ::: "memory")
#define TCGEN05_FENCE_BEFORE() asm volatile("tcgen05.fence::before_thread_sync;" ::: "memory")
#define FENCE_PROXY_ASYNC() asm volatile("fence.proxy.async.shared::cta;" ::: "memory")
#define TCGEN05_LD_X32(r, tm) \
    asm volatile("tcgen05.ld.sync.aligned.32x32b.x32.b32 " \
        "{%0, %1, %2, %3, %4, %5, %6, %7, %8, %9, %10, %11, %12, %13, %14, %15, " \
        " %16, %17, %18, %19, %20, %21, %22, %23, %24, %25, %26, %27, %28, %29, %30, %31}, [%32];" \
        : "=r"((r)[0]), "=r"((r)[1]), "=r"((r)[2]), "=r"((r)[3]), "=r"((r)[4]), "=r"((r)[5]), \
          "=r"((r)[6]), "=r"((r)[7]), "=r"((r)[8]), "=r"((r)[9]), "=r"((r)[10]), "=r"((r)[11]), \
          "=r"((r)[12]), "=r"((r)[13]), "=r"((r)[14]), "=r"((r)[15]), "=r"((r)[16]), "=r"((r)[17]), \
          "=r"((r)[18]), "=r"((r)[19]), "=r"((r)[20]), "=r"((r)[21]), "=r"((r)[22]), "=r"((r)[23]), \
          "=r"((r)[24]), "=r"((r)[25]), "=r"((r)[26]), "=r"((r)[27]), "=r"((r)[28]), "=r"((r)[29]), \
          "=r"((r)[30]), "=r"((r)[31]) : "r"(tm))

static __device__ __forceinline__ uint64_t make_desc(uint32_t addr) {
    const uint64_t base = (uint64_t(2) << 61) | (uint64_t(1) << 46)
                        | (uint64_t(64) << 32) | (uint64_t(1) << 16);
    return base | ((uint64_t)(addr >> 4) & 0x3FFF);
}
// idesc kind::f16: dtype=F32, atype=btype=BF16, N=128, M=128 (cg1)
#define GEMM_IDESC (0x490u | (16u << 17) | (8u << 24))

__device__ __forceinline__ void mma_f16_ss_cg1(uint32_t d, uint64_t ad, uint64_t bd,
                                               uint32_t idesc, uint32_t en) {
    asm volatile("{\n\t.reg .pred p;\n\tsetp.ne.u32 p, %5, 0;\n\t"
        "tcgen05.mma.cta_group::1.kind::f16 [%0], %1, %2, %3, {%4, %4, %4, %4}, p;\n\t}"
        :: "r"(d), "l"(ad), "l"(bd), "r"(idesc), "r"(0u), "r"(en) : "memory");
}
#endif  // TGEMM_TCGEN05

// mma.sync fallback primitive (sm_80+): D = A@B + D, bf16 in / f32 acc
__device__ __forceinline__ void mma_bf16(float* d, const uint32_t* a, const uint32_t* b) {
    asm volatile("mma.sync.aligned.m16n8k16.row.col.f32.bf16.bf16.f32 "
        "{%0,%1,%2,%3}, {%4,%5,%6,%7}, {%8,%9}, {%0,%1,%2,%3};"
        : "+f"(d[0]), "+f"(d[1]), "+f"(d[2]), "+f"(d[3])
        : "r"(a[0]), "r"(a[1]), "r"(a[2]), "r"(a[3]), "r"(b[0]), "r"(b[1]));
}

__device__ __forceinline__ uint32_t pack2bf(float a, float b) {
    __nv_bfloat162 p = __floats2bfloat162_rn(a, b);
    return *(uint32_t*)&p;
}

// ---------------------------------------------------------------------------
// Scratch (static device globals)
// ---------------------------------------------------------------------------
__device__ __nv_bfloat16 g_a_hi[(size_t)Mrows * Ec];
__device__ __nv_bfloat16 g_a_lo[(size_t)Mrows * Ec];
__device__ float         g_x   [(size_t)Mrows * Ec];
__device__ __nv_bfloat16 g_x_hi[(size_t)Mrows * Ec];
__device__ __nv_bfloat16 g_x_lo[(size_t)Mrows * Ec];
__device__ float         g_t   [(size_t)Mrows * Ec];
__device__ __nv_bfloat16 g_h_hi[(size_t)Mrows * FFc];
__device__ __nv_bfloat16 g_h_lo[(size_t)Mrows * FFc];
__device__ __nv_bfloat16 g_wot_hi[(size_t)Ec * Ec];
__device__ __nv_bfloat16 g_wot_lo[(size_t)Ec * Ec];
__device__ __nv_bfloat16 g_w1t_hi[(size_t)FFc * Ec];
__device__ __nv_bfloat16 g_w1t_lo[(size_t)FFc * Ec];
__device__ __nv_bfloat16 g_w2t_hi[(size_t)Ec * FFc];
__device__ __nv_bfloat16 g_w2t_lo[(size_t)Ec * FFc];
__device__ float g_part[Bc * 16 * Ec];
__device__ float g_xavg[Bc * Ec];
__device__ float g_gpart[8 * Bc * Ec];
__device__ float g_gate[Bc * Ec];

// ---------------------------------------------------------------------------
// Weight transpose + bf16 split:  W[K,N] fp32 -> Wt_hi/lo[N,K] bf16
// ---------------------------------------------------------------------------
__global__ void wtrans_kernel(const float* __restrict__ W,
                              __nv_bfloat16* __restrict__ Th,
                              __nv_bfloat16* __restrict__ Tl, int K, int N)
{
    __shared__ float tt[32][33];
    const int tid = threadIdx.x;
    const int tx = tid & 31, ty8 = tid >> 5;
    const int k0 = blockIdx.y * 32, n0 = blockIdx.x * 32;
#pragma unroll
    for (int i = 0; i < 4; ++i) {
        int row = ty8 + i * 8;
        tt[row][tx] = W[(size_t)(k0 + row) * N + n0 + tx];
    }
    __syncthreads();
#pragma unroll
    for (int i = 0; i < 4; ++i) {
        int n = ty8 + i * 8;
        float v = tt[tx][n];
        __nv_bfloat16 hi = __float2bfloat16(v);
        float lo = v - __bfloat162float(hi);
        size_t o = (size_t)(n0 + n) * K + k0 + tx;
        Th[o] = hi;
        Tl[o] = __float2bfloat16(lo);
    }
}

// ---------------------------------------------------------------------------
// Gate path
// ---------------------------------------------------------------------------
__global__ void colmean_part_kernel(const float* __restrict__ q, float* __restrict__ part)
{
    const int b = blockIdx.x, p = blockIdx.y, tid = threadIdx.x;
    const float* base = q + (size_t)b * Sc * Ec + (size_t)p * 128 * Ec;
    float4 acc = make_float4(0.f, 0.f, 0.f, 0.f);
#pragma unroll 4
    for (int s = 0; s < 128; ++s) {
        float4 v = ((const float4*)(base + (size_t)s * Ec))[tid];
        acc.x += v.x; acc.y += v.y; acc.z += v.z; acc.w += v.w;
    }
    ((float4*)(part + (size_t)(b * 16 + p) * Ec))[tid] = acc;
}
__global__ void colmean_fin_kernel(const float* __restrict__ part, float* __restrict__ xavg)
{
    const int b = blockIdx.x, tid = threadIdx.x;
    float4 acc = make_float4(0.f, 0.f, 0.f, 0.f);
#pragma unroll
    for (int p = 0; p < 16; ++p) {
        float4 v = ((const float4*)(part + (size_t)(b * 16 + p) * Ec))[tid];
        acc.x += v.x; acc.y += v.y; acc.z += v.z; acc.w += v.w;
    }
    const float inv = 1.0f / (float)Sc;
    ((float4*)(xavg + (size_t)b * Ec))[tid] =
        make_float4(acc.x * inv, acc.y * inv, acc.z * inv, acc.w * inv);
}
__global__ void gate_part_kernel(const float* __restrict__ xavg, const float* __restrict__ Wg,
                                 float* __restrict__ gp)
{
    const int idx = blockIdx.x * 256 + threadIdx.x;
    const int b = idx >> 10, e = idx & (Ec - 1);
    const int k0 = blockIdx.y * 128;
    const float* xa = xavg + (size_t)b * Ec;
    float acc = 0.f;
#pragma unroll 8
    for (int k = 0; k < 128; ++k)
        acc = fmaf(xa[k0 + k], Wg[(size_t)(k0 + k) * Ec + e], acc);
    gp[(size_t)blockIdx.y * (Bc * Ec) + idx] = acc;
}
__global__ void gate_fin_kernel(const float* __restrict__ gp, const float* __restrict__ bg,
                                float* __restrict__ gate)
{
    const int idx = blockIdx.x * 256 + threadIdx.x;
    const int e = idx & (Ec - 1);
    float acc = bg[e];
#pragma unroll
    for (int ky = 0; ky < 8; ++ky) acc += gp[(size_t)ky * (Bc * Ec) + idx];
    gate[idx] = 1.0f / (1.0f + expf(-acc));
}

// ---------------------------------------------------------------------------
// Causal flash attention (fp32), emits split bf16 output directly
// ---------------------------------------------------------------------------
#define FAP 68

__global__ __launch_bounds__(256)
void flash_attn_kernel(const float* __restrict__ Q, const float* __restrict__ K,
                       const float* __restrict__ V,
                       __nv_bfloat16* __restrict__ Ohi, __nv_bfloat16* __restrict__ Olo)
{
    extern __shared__ float sm[];
    float* Qs = sm;
    float* Ks = sm + 64 * FAP;
    float* Vs = sm + 2 * 64 * FAP;
    float* Ps = sm + 3 * 64 * FAP;

    const int qt = blockIdx.x;
    const int bh = blockIdx.y;
    const int b = bh >> 4, h = bh & 15;
    const int tid = threadIdx.x;
    const int ty = tid >> 4, tx = tid & 15;
    const size_t headoff = (size_t)b * Sc * Ec + (size_t)h * Dc;

    {
        const float* Qp = Q + headoff + (size_t)(qt * 64) * Ec;
        for (int t = tid; t < 1024; t += 256) {
            int r = t >> 4, c = (t & 15) * 4;
            float4 v = *(const float4*)(Qp + (size_t)r * Ec + c);
            Qs[(c + 0) * FAP + r] = v.x; Qs[(c + 1) * FAP + r] = v.y;
            Qs[(c + 2) * FAP + r] = v.z; Qs[(c + 3) * FAP + r] = v.w;
        }
    }
    float o[4][4], mrow[4], lrow[4];
#pragma unroll
    for (int i = 0; i < 4; ++i) {
        mrow[i] = -1e30f; lrow[i] = 0.f;
#pragma unroll
        for (int j = 0; j < 4; ++j) o[i][j] = 0.f;
    }
    __syncthreads();

    for (int kt = 0; kt <= qt; ++kt) {
        __syncthreads();
        {
            const float* Kp = K + headoff + (size_t)(kt * 64) * Ec;
            const float* Vp = V + headoff + (size_t)(kt * 64) * Ec;
            for (int t = tid; t < 1024; t += 256) {
                int r = t >> 4, c = (t & 15) * 4;
                float4 kv = *(const float4*)(Kp + (size_t)r * Ec + c);
                Ks[(c + 0) * FAP + r] = kv.x; Ks[(c + 1) * FAP + r] = kv.y;
                Ks[(c + 2) * FAP + r] = kv.z; Ks[(c + 3) * FAP + r] = kv.w;
                float4 vv = *(const float4*)(Vp + (size_t)r * Ec + c);
                *(float4*)&Vs[r * FAP + c] = vv;
            }
        }
        __syncthreads();

        float sc[4][4];
#pragma unroll
        for (int i = 0; i < 4; ++i)
#pragma unroll
            for (int j = 0; j < 4; ++j) sc[i][j] = 0.f;
#pragma unroll
        for (int d = 0; d < 64; ++d) {
            float4 aq = *(const float4*)&Qs[d * FAP + ty * 4];
            float4 bk = *(const float4*)&Ks[d * FAP + tx * 4];
            float a[4] = {aq.x, aq.y, aq.z, aq.w};
            float bb[4] = {bk.x, bk.y, bk.z, bk.w};
#pragma unroll
            for (int i = 0; i < 4; ++i)
#pragma unroll
                for (int j = 0; j < 4; ++j)
                    sc[i][j] = fmaf(a[i], bb[j], sc[i][j]);
        }

        const bool diag = (kt == qt);
#pragma unroll
        for (int i = 0; i < 4; ++i) {
#pragma unroll
            for (int j = 0; j < 4; ++j) {
                float v = sc[i][j] * 0.125f;
                if (diag && (tx * 4 + j > ty * 4 + i)) v = -1e30f;
                sc[i][j] = v;
            }
            float mx = fmaxf(fmaxf(sc[i][0], sc[i][1]), fmaxf(sc[i][2], sc[i][3]));
#pragma unroll
            for (int ofs = 8; ofs > 0; ofs >>= 1)
                mx = fmaxf(mx, __shfl_xor_sync(0xffffffffu, mx, ofs));
            float mn = fmaxf(mrow[i], mx);
            float corr = __expf(mrow[i] - mn);
            float rs = 0.f;
#pragma unroll
            for (int j = 0; j < 4; ++j) {
                float p = __expf(sc[i][j] - mn);
                sc[i][j] = p; rs += p;
            }
#pragma unroll
            for (int ofs = 8; ofs > 0; ofs >>= 1)
                rs += __shfl_xor_sync(0xffffffffu, rs, ofs);
            lrow[i] = lrow[i] * corr + rs;
            mrow[i] = mn;
#pragma unroll
            for (int j = 0; j < 4; ++j) o[i][j] *= corr;
        }
#pragma unroll
        for (int i = 0; i < 4; ++i)
            *(float4*)&Ps[(ty * 4 + i) * FAP + tx * 4] =
                make_float4(sc[i][0], sc[i][1], sc[i][2], sc[i][3]);
        __syncthreads();
#pragma unroll 8
        for (int j = 0; j < 64; ++j) {
            float av[4];
#pragma unroll
            for (int i = 0; i < 4; ++i) av[i] = Ps[(ty * 4 + i) * FAP + j];
            float4 bv = *(const float4*)&Vs[j * FAP + tx * 4];
            float bb[4] = {bv.x, bv.y, bv.z, bv.w};
#pragma unroll
            for (int i = 0; i < 4; ++i)
#pragma unroll
                for (int jj = 0; jj < 4; ++jj)
                    o[i][jj] = fmaf(av[i], bb[jj], o[i][jj]);
        }
    }

#pragma unroll
    for (int i = 0; i < 4; ++i) {
        float inv = 1.0f / lrow[i];
        size_t off = headoff + (size_t)(qt * 64 + ty * 4 + i) * Ec + tx * 4;
        float v[4], lo[4];
        uint32_t hp[2], lp[2];
#pragma unroll
        for (int j = 0; j < 4; ++j) {
            v[j] = o[i][j] * inv;
            __nv_bfloat16 h16 = __float2bfloat16(v[j]);
            lo[j] = v[j] - __bfloat162float(h16);
        }
        hp[0] = pack2bf(v[0], v[1]);  hp[1] = pack2bf(v[2], v[3]);
        lp[0] = pack2bf(lo[0], lo[1]); lp[1] = pack2bf(lo[2], lo[3]);
        *(uint2*)(Ohi + off) = make_uint2(hp[0], hp[1]);
        *(uint2*)(Olo + off) = make_uint2(lp[0], lp[1]);
    }
}

// ---------------------------------------------------------------------------
// bf16-split GEMM: C(M x N) = A(M x K) @ Bt(N x K)^T, fp32 accumulate.
// 3 products: Ah*Bh + Ah*Bl + Al*Bh. 128x128 tile.
// tcgen05 path when sm_103a feature target is available, else mma.sync.
// EPI 0: Cf = gate[b][n]*(acc+bias[n]) + aux2[m*N+n]
// EPI 1: (Chi,Clo) = split_bf16( gelu(acc + bias[n]) )
// EPI 2: Cf = acc + bias[n] + aux1[m*N+n]
// ---------------------------------------------------------------------------
#define STAGE_BYTES 65536
#define TAIL_OFF    131072
#define TG_SMEM     (TAIL_OFF + 64)

#if TGEMM_TCGEN05
__device__ __forceinline__ void load_tile(const __nv_bfloat16* __restrict__ g, int ldK,
                                          char* s, int tid)
{
#pragma unroll
    for (int i = 0; i < 4; ++i) {
        int v = tid + 256 * i;         // 0..1023
        int row = v >> 3;
        int cb = (v & 7) * 16;         // byte col within 128B row
        uint4 val = *(const uint4*)((const char*)g + (size_t)row * ldK * 2 + cb);
        uint32_t off = (uint32_t)(row * 128 + cb);
        off ^= (off >> 3) & 0x70;      // SW128
        *(uint4*)(s + off) = val;
    }
}
#endif

template <int EPI>
__global__ __launch_bounds__(256)
void tgemm_kernel(const __nv_bfloat16* __restrict__ Ah, const __nv_bfloat16* __restrict__ Al,
                  const __nv_bfloat16* __restrict__ Bh, const __nv_bfloat16* __restrict__ Bl,
                  int N, int K,
                  const float* __restrict__ bias,
                  const float* __restrict__ aux1, const float* __restrict__ aux2,
                  float* __restrict__ Cf,
                  __nv_bfloat16* __restrict__ Chi, __nv_bfloat16* __restrict__ Clo)
{
#if TGEMM_TCGEN05
    // ---------------- tcgen05 path (sm_103a cubin) ----------------
    extern __shared__ __align__(1024) char smc[];
    const uint32_t smem_base = smem_to_u32(smc);
    const int tid = threadIdx.x;
    const int wid = tid >> 5, lid = tid & 31;
    const int bm = blockIdx.y * 128, bn = blockIdx.x * 128;

    const uint32_t tail = smem_base + TAIL_OFF;
    if (tid == 0) {
        MBARRIER_INIT(tail + 16, 1);
        MBARRIER_INIT(tail + 24, 1);
    }
    if (wid == 0) {
        TCGEN05_ALLOC(tail, 128);
        TCGEN05_RELINQ();
    }
    __syncthreads();
    uint32_t tmem;
    asm volatile("ld.shared.b32 %0, [%1];" : "=r"(tmem) : "r"(tail));

    const __nv_bfloat16* Ahp = Ah + (size_t)bm * K;
    const __nv_bfloat16* Alp = Al + (size_t)bm * K;
    const __nv_bfloat16* Bhp = Bh + (size_t)bn * K;
    const __nv_bfloat16* Blp = Bl + (size_t)bn * K;

    const int nt = K >> 6;
    int ph[2] = {0, 0};

    for (int kc = 0; kc < nt; ++kc) {
        const int st = kc & 1;
        if (kc >= 2) {
            MBARRIER_WAIT_PARITY(tail + 16 + st * 8, ph[st]);
            ph[st] ^= 1;
        }
        char* sb = smc + st * STAGE_BYTES;
        load_tile(Ahp + kc * 64, K, sb,         tid);
        load_tile(Alp + kc * 64, K, sb + 16384, tid);
        load_tile(Bhp + kc * 64, K, sb + 32768, tid);
        load_tile(Blp + kc * 64, K, sb + 49152, tid);
        FENCE_PROXY_ASYNC();
        __syncthreads();

        if (wid == 4 && elect_one_pred()) {
            const uint32_t b32 = smem_base + st * STAGE_BYTES;
            uint64_t dAh = make_desc(b32);
            uint64_t dAl = make_desc(b32 + 16384);
            uint64_t dBh = make_desc(b32 + 32768);
            uint64_t dBl = make_desc(b32 + 49152);
#pragma unroll
            for (int k = 0; k < 4; ++k)
                mma_f16_ss_cg1(tmem, dAh + k * 2, dBh + k * 2, GEMM_IDESC,
                               (kc > 0) || (k > 0));
#pragma unroll
            for (int k = 0; k < 4; ++k)
                mma_f16_ss_cg1(tmem, dAh + k * 2, dBl + k * 2, GEMM_IDESC, 1);
#pragma unroll
            for (int k = 0; k < 4; ++k)
                mma_f16_ss_cg1(tmem, dAl + k * 2, dBh + k * 2, GEMM_IDESC, 1);
            TCGEN05_COMMIT(tail + 16 + st * 8);
        }
    }

    const int fl = (nt - 1) & 1;
    MBARRIER_WAIT_PARITY(tail + 16 + fl * 8, ph[fl]);
    TCGEN05_FENCE_AFTER();

    if (wid < 4) {
        const int gr = bm + wid * 32 + lid;
        for (int cb = 0; cb < 128; cb += 32) {
            uint32_t r[32];
            TCGEN05_LD_X32(r, tmem + cb);
            TCGEN05_WAIT_LD();
            const int c0 = bn + cb;
            if (EPI == 0) {
                const float* qrow = aux2 + (size_t)gr * N;
                const float* grow = aux1 + ((gr >> 11) << 10);
#pragma unroll
                for (int j = 0; j < 32; j += 4) {
                    int c = c0 + j;
                    float4 ov;
                    ov.x = grow[c + 0] * (__uint_as_float(r[j + 0]) + bias[c + 0]) + qrow[c + 0];
                    ov.y = grow[c + 1] * (__uint_as_float(r[j + 1]) + bias[c + 1]) + qrow[c + 1];
                    ov.z = grow[c + 2] * (__uint_as_float(r[j + 2]) + bias[c + 2]) + qrow[c + 2];
                    ov.w = grow[c + 3] * (__uint_as_float(r[j + 3]) + bias[c + 3]) + qrow[c + 3];
                    *(float4*)(Cf + (size_t)gr * N + c) = ov;
                }
            } else if (EPI == 1) {
#pragma unroll
                for (int j = 0; j < 32; j += 8) {
                    int c = c0 + j;
                    float v[8], lo[8];
#pragma unroll
                    for (int q = 0; q < 8; ++q) {
                        float x = __uint_as_float(r[j + q]) + bias[c + q];
                        v[q] = 0.5f * x * (1.0f + erff(x * 0.70710678118654752f));
                        __nv_bfloat16 h16 = __float2bfloat16(v[q]);
                        lo[q] = v[q] - __bfloat162float(h16);
                    }
                    uint4 hp = make_uint4(pack2bf(v[0], v[1]), pack2bf(v[2], v[3]),
                                          pack2bf(v[4], v[5]), pack2bf(v[6], v[7]));
                    uint4 lp = make_uint4(pack2bf(lo[0], lo[1]), pack2bf(lo[2], lo[3]),
                                          pack2bf(lo[4], lo[5]), pack2bf(lo[6], lo[7]));
                    *(uint4*)(Chi + (size_t)gr * N + c) = hp;
                    *(uint4*)(Clo + (size_t)gr * N + c) = lp;
                }
            } else {
                const float* xrow = aux1 + (size_t)gr * N;
#pragma unroll
                for (int j = 0; j < 32; j += 4) {
                    int c = c0 + j;
                    float4 ov;
                    ov.x = __uint_as_float(r[j + 0]) + bias[c + 0] + xrow[c + 0];
                    ov.y = __uint_as_float(r[j + 1]) + bias[c + 1] + xrow[c + 1];
                    ov.z = __uint_as_float(r[j + 2]) + bias[c + 2] + xrow[c + 2];
                    ov.w = __uint_as_float(r[j + 3]) + bias[c + 3] + xrow[c + 3];
                    *(float4*)(Cf + (size_t)gr * N + c) = ov;
                }
            }
        }
        TCGEN05_FENCE_BEFORE();
    }
    __syncthreads();
    if (wid == 0) TCGEN05_DEALLOC(tmem, 128);

#else
    // ---------------- mma.sync fallback (base sm_103 PTX) ----------------
    // Smem per stage: 4 buffers (Ah, Al, Bh, Bl), each 128 rows x 32 bf16,
    // pitch 40 bf16 (80B) -> 10240B per buffer, 40960B per stage, 2 stages.
    extern __shared__ __align__(1024) char smc[];
    const uint32_t smem_base = smem_to_u32(smc);
    const int tid = threadIdx.x;
    const int wid = tid >> 5, lid = tid & 31;
    const int g = lid >> 2, t = lid & 3;
    const int wm = wid & 3, wn = wid >> 2;          // warp tile: 32(m) x 64(n)
    const int bm = blockIdx.y * 128, bn = blockIdx.x * 128;

    const char* g0 = (const char*)(Ah + (size_t)bm * K);
    const char* g1 = (const char*)(Al + (size_t)bm * K);
    const char* g2 = (const char*)(Bh + (size_t)bn * K);
    const char* g3 = (const char*)(Bl + (size_t)bn * K);

    auto issue_stage = [&](int st, int kc) {
#pragma unroll
        for (int j = 0; j < 8; ++j) {
            const int linear = j * 256 + tid;         // 0..2047
            const int buf = linear >> 9;              // 0..3
            const int rem = linear & 511;
            const int row = rem >> 2, c16 = rem & 3;
            const char* gb = (buf == 0) ? g0 : (buf == 1) ? g1 : (buf == 2) ? g2 : g3;
            const char* src = gb + ((size_t)row * K) * 2 + (size_t)kc * 64 + c16 * 16;
            const uint32_t dst = smem_base + st * 40960 + buf * 10240 + row * 80 + c16 * 16;
            asm volatile("cp.async.cg.shared.global [%0], [%1], 16;"
                         :: "r"(dst), "l"(src) : "memory");
        }
        asm volatile("cp.async.commit_group;" ::: "memory");
    };

    float acc[2][8][4];
#pragma unroll
    for (int mi = 0; mi < 2; ++mi)
#pragma unroll
        for (int ni = 0; ni < 8; ++ni)
#pragma unroll
            for (int q = 0; q < 4; ++q) acc[mi][ni][q] = 0.f;

    const int nt = K >> 5;  // K/32 slabs
    issue_stage(0, 0);
    asm volatile("cp.async.wait_group 0;" ::: "memory");
    __syncthreads();

    for (int kc = 0; kc < nt; ++kc) {
        const int st = kc & 1;
        if (kc + 1 < nt) issue_stage(st ^ 1, kc + 1);
        const char* sb = smc + st * 40960;
#pragma unroll
        for (int ks = 0; ks < 2; ++ks) {
            const int ko = (ks * 16 + 2 * t) * 2;     // byte offset within row
            uint32_t bhf[8][2], blf[8][2];
#pragma unroll
            for (int ni = 0; ni < 8; ++ni) {
                const int rB = (wn * 64 + ni * 8 + g) * 80 + ko;
                bhf[ni][0] = *(const uint32_t*)(sb + 20480 + rB);
                bhf[ni][1] = *(const uint32_t*)(sb + 20480 + rB + 16);
                blf[ni][0] = *(const uint32_t*)(sb + 30720 + rB);
                blf[ni][1] = *(const uint32_t*)(sb + 30720 + rB + 16);
            }
#pragma unroll
            for (int mi = 0; mi < 2; ++mi) {
                const int rA = (wm * 32 + mi * 16 + g) * 80 + ko;
                uint32_t ahf[4], alf[4];
                ahf[0] = *(const uint32_t*)(sb + rA);
                ahf[1] = *(const uint32_t*)(sb + rA + 8 * 80);
                ahf[2] = *(const uint32_t*)(sb + rA + 16);
                ahf[3] = *(const uint32_t*)(sb + rA + 8 * 80 + 16);
                alf[0] = *(const uint32_t*)(sb + 10240 + rA);
                alf[1] = *(const uint32_t*)(sb + 10240 + rA + 8 * 80);
                alf[2] = *(const uint32_t*)(sb + 10240 + rA + 16);
                alf[3] = *(const uint32_t*)(sb + 10240 + rA + 8 * 80 + 16);
#pragma unroll
                for (int ni = 0; ni < 8; ++ni) {
                    mma_bf16(acc[mi][ni], ahf, bhf[ni]);
                    mma_bf16(acc[mi][ni], ahf, blf[ni]);
                    mma_bf16(acc[mi][ni], alf, bhf[ni]);
                }
            }
        }
        if (kc + 1 < nt) asm volatile("cp.async.wait_group 0;" ::: "memory");
        __syncthreads();
    }

    // Epilogue: thread holds D[g][2t], D[g][2t+1], D[g+8][2t], D[g+8][2t+1]
#pragma unroll
    for (int mi = 0; mi < 2; ++mi) {
#pragma unroll
        for (int ni = 0; ni < 8; ++ni) {
            const int r0 = bm + wm * 32 + mi * 16 + g;
            const int c  = bn + wn * 64 + ni * 8 + 2 * t;
#pragma unroll
            for (int hh = 0; hh < 2; ++hh) {
                const int r = r0 + hh * 8;
                const float v0 = acc[mi][ni][hh * 2 + 0];
                const float v1 = acc[mi][ni][hh * 2 + 1];
                if (EPI == 0) {
                    const float* grow = aux1 + ((r >> 11) << 10);
                    float2 ov;
                    ov.x = grow[c + 0] * (v0 + bias[c + 0]) + aux2[(size_t)r * N + c + 0];
                    ov.y = grow[c + 1] * (v1 + bias[c + 1]) + aux2[(size_t)r * N + c + 1];
                    *(float2*)(Cf + (size_t)r * N + c) = ov;
                } else if (EPI == 1) {
                    float x0 = v0 + bias[c + 0];
                    float x1 = v1 + bias[c + 1];
                    float y0 = 0.5f * x0 * (1.0f + erff(x0 * 0.70710678118654752f));
                    float y1 = 0.5f * x1 * (1.0f + erff(x1 * 0.70710678118654752f));
                    __nv_bfloat16 h0 = __float2bfloat16(y0);
                    __nv_bfloat16 h1 = __float2bfloat16(y1);
                    float l0 = y0 - __bfloat162float(h0);
                    float l1 = y1 - __bfloat162float(h1);
                    *(uint32_t*)(Chi + (size_t)r * N + c) = pack2bf(y0, y1);
                    *(uint32_t*)(Clo + (size_t)r * N + c) = pack2bf(l0, l1);
                } else {
                    float2 ov;
                    ov.x = v0 + bias[c + 0] + aux1[(size_t)r * N + c + 0];
                    ov.y = v1 + bias[c + 1] + aux1[(size_t)r * N + c + 1];
                    *(float2*)(Cf + (size_t)r * N + c) = ov;
                }
            }
        }
    }
#endif
}

// ---------------------------------------------------------------------------
// LayerNorm(1024); optionally emits bf16 split alongside fp32
// ---------------------------------------------------------------------------
template <int EMIT>
__global__ void ln1024_kernel(const float* __restrict__ in, const float* __restrict__ g,
                              const float* __restrict__ be, float* __restrict__ out,
                              __nv_bfloat16* __restrict__ ohi, __nv_bfloat16* __restrict__ olo)
{
    __shared__ float red[16];
    const int row = blockIdx.x, tid = threadIdx.x;
    float4 v = ((const float4*)(in + (size_t)row * Ec))[tid];
    float s = v.x + v.y + v.z + v.w;
    float q = v.x * v.x + v.y * v.y + v.z * v.z + v.w * v.w;
#pragma unroll
    for (int ofs = 16; ofs > 0; ofs >>= 1) {
        s += __shfl_xor_sync(0xffffffffu, s, ofs);
        q += __shfl_xor_sync(0xffffffffu, q, ofs);
    }
    const int w = tid >> 5;
    if ((tid & 31) == 0) { red[w] = s; red[8 + w] = q; }
    __syncthreads();
    s = 0.f; q = 0.f;
#pragma unroll
    for (int i = 0; i < 8; ++i) { s += red[i]; q += red[8 + i]; }
    const float mu = s * (1.0f / 1024.0f);
    const float var = q * (1.0f / 1024.0f) - mu * mu;
    const float rs = rsqrtf(var + 1e-5f);
    float4 gg = ((const float4*)g)[tid];
    float4 bb = ((const float4*)be)[tid];
    float4 o;
    o.x = (v.x - mu) * rs * gg.x + bb.x;
    o.y = (v.y - mu) * rs * gg.y + bb.y;
    o.z = (v.z - mu) * rs * gg.z + bb.z;
    o.w = (v.w - mu) * rs * gg.w + bb.w;
    ((float4*)(out + (size_t)row * Ec))[tid] = o;
    if (EMIT) {
        float vv[4] = {o.x, o.y, o.z, o.w}, lo[4];
#pragma unroll
        for (int j = 0; j < 4; ++j) {
            __nv_bfloat16 h16 = __float2bfloat16(vv[j]);
            lo[j] = vv[j] - __bfloat162float(h16);
        }
        size_t off = (size_t)row * Ec + tid * 4;
        *(uint2*)(ohi + off) = make_uint2(pack2bf(vv[0], vv[1]), pack2bf(vv[2], vv[3]));
        *(uint2*)(olo + off) = make_uint2(pack2bf(lo[0], lo[1]), pack2bf(lo[2], lo[3]));
    }
}

// ---------------------------------------------------------------------------
// kernel_launch
// ---------------------------------------------------------------------------
extern "C" void kernel_launch(void* const* d_in, const int* in_sizes, int n_in,
                              void* d_out, int out_size)
{
    (void)in_sizes; (void)n_in; (void)out_size;
    const float* Vv  = (const float*)d_in[0];
    const float* Kk  = (const float*)d_in[1];
    const float* Qq  = (const float*)d_in[2];
    const float* Wo  = (const float*)d_in[4];
    const float* bo  = (const float*)d_in[5];
    const float* Wg  = (const float*)d_in[6];
    const float* bg  = (const float*)d_in[7];
    const float* g1  = (const float*)d_in[8];
    const float* b1  = (const float*)d_in[9];
    const float* g2  = (const float*)d_in[10];
    const float* b2  = (const float*)d_in[11];
    const float* W1  = (const float*)d_in[12];
    const float* bf1 = (const float*)d_in[13];
    const float* W2  = (const float*)d_in[14];
    const float* bf2 = (const float*)d_in[15];
    float* out = (float*)d_out;

    __nv_bfloat16 *p_ahi, *p_alo, *p_xhi, *p_xlo, *p_hhi, *p_hlo;
    __nv_bfloat16 *p_wothi, *p_wotlo, *p_w1thi, *p_w1tlo, *p_w2thi, *p_w2tlo;
    float *p_x, *p_t, *p_part, *p_xavg, *p_gpart, *p_gate;
    cudaGetSymbolAddress((void**)&p_ahi, g_a_hi);
    cudaGetSymbolAddress((void**)&p_alo, g_a_lo);
    cudaGetSymbolAddress((void**)&p_x,   g_x);
    cudaGetSymbolAddress((void**)&p_xhi, g_x_hi);
    cudaGetSymbolAddress((void**)&p_xlo, g_x_lo);
    cudaGetSymbolAddress((void**)&p_t,   g_t);
    cudaGetSymbolAddress((void**)&p_hhi, g_h_hi);
    cudaGetSymbolAddress((void**)&p_hlo, g_h_lo);
    cudaGetSymbolAddress((void**)&p_wothi, g_wot_hi);
    cudaGetSymbolAddress((void**)&p_wotlo, g_wot_lo);
    cudaGetSymbolAddress((void**)&p_w1thi, g_w1t_hi);
    cudaGetSymbolAddress((void**)&p_w1tlo, g_w1t_lo);
    cudaGetSymbolAddress((void**)&p_w2thi, g_w2t_hi);
    cudaGetSymbolAddress((void**)&p_w2tlo, g_w2t_lo);
    cudaGetSymbolAddress((void**)&p_part,  g_part);
    cudaGetSymbolAddress((void**)&p_xavg,  g_xavg);
    cudaGetSymbolAddress((void**)&p_gpart, g_gpart);
    cudaGetSymbolAddress((void**)&p_gate,  g_gate);

    const int fa_smem = 4 * 64 * FAP * (int)sizeof(float);
    cudaFuncSetAttribute(flash_attn_kernel,
                         cudaFuncAttributeMaxDynamicSharedMemorySize, fa_smem);
    cudaFuncSetAttribute(tgemm_kernel<0>,
                         cudaFuncAttributeMaxDynamicSharedMemorySize, TG_SMEM);
    cudaFuncSetAttribute(tgemm_kernel<1>,
                         cudaFuncAttributeMaxDynamicSharedMemorySize, TG_SMEM);
    cudaFuncSetAttribute(tgemm_kernel<2>,
                         cudaFuncAttributeMaxDynamicSharedMemorySize, TG_SMEM);

    // weight transpose + split
    wtrans_kernel<<<dim3(Ec / 32,  Ec / 32),  256>>>(Wo, p_wothi, p_wotlo, Ec,  Ec);
    wtrans_kernel<<<dim3(FFc / 32, Ec / 32),  256>>>(W1, p_w1thi, p_w1tlo, Ec,  FFc);
    wtrans_kernel<<<dim3(Ec / 32,  FFc / 32), 256>>>(W2, p_w2thi, p_w2tlo, FFc, Ec);

    // gate path
    colmean_part_kernel<<<dim3(Bc, 16), 256>>>(Qq, p_part);
    colmean_fin_kernel<<<Bc, 256>>>(p_part, p_xavg);
    gate_part_kernel<<<dim3(Bc * Ec / 256, 8), 256>>>(p_xavg, Wg, p_gpart);
    gate_fin_kernel<<<Bc * Ec / 256, 256>>>(p_gpart, bg, p_gate);

    // attention -> split bf16
    flash_attn_kernel<<<dim3(Sc / 64, Bc * Hc), 256, fa_smem>>>(Qq, Kk, Vv, p_ahi, p_alo);

    // Wo proj + gate + residual -> g_t -> LN1 -> x (fp32 + split)
    tgemm_kernel<0><<<dim3(Ec / 128, Mrows / 128), 256, TG_SMEM>>>(
        p_ahi, p_alo, p_wothi, p_wotlo, Ec, Ec, bo, p_gate, Qq, p_t, nullptr, nullptr);
    ln1024_kernel<1><<<Mrows, 256>>>(p_t, g1, b1, p_x, p_xhi, p_xlo);

    // FFN
    tgemm_kernel<1><<<dim3(FFc / 128, Mrows / 128), 256, TG_SMEM>>>(
        p_xhi, p_xlo, p_w1thi, p_w1tlo, FFc, Ec, bf1, nullptr, nullptr,
        nullptr, p_hhi, p_hlo);
    tgemm_kernel<2><<<dim3(Ec / 128, Mrows / 128), 256, TG_SMEM>>>(
        p_hhi, p_hlo, p_w2thi, p_w2tlo, Ec, FFc, bf2, p_x, nullptr, p_t, nullptr, nullptr);

    ln1024_kernel<0><<<Mrows, 256>>>(p_t, g2, b2, out, nullptr, nullptr);
}

// round 13
// speedup vs baseline: 1.9617x; 1.2260x over previous
#include <cuda_runtime.h>
#include <cuda_bf16.h>
#include <math.h>
#include <stdint.h>

// Problem constants
#define Bc  2
#define Sc  2048
#define Ec  1024
#define Hc  16
#define Dc  64
#define FFc 4096
#define Mrows (Bc * Sc)   // 4096

// tcgen05 is an arch-accelerated ('a') feature; only emit it when the device
// pass actually targets sm_103a-family. Otherwise use mma.sync (sm_80+ PTX).
#if defined(__CUDA_ARCH__) && defined(__CUDA_ARCH_FEAT_SM103_ALL)
#define TGEMM_TCGEN05 1
#else
#define TGEMM_TCGEN05 0
#endif

// ---------------------------------------------------------------------------
// PTX helpers
// ---------------------------------------------------------------------------
__device__ __forceinline__ uint32_t smem_to_u32(const void* p) {
    uint32_t a;
    asm("{ .reg .u64 t; cvta.to.shared.u64 t, %1; cvt.u32.u64 %0, t; }" : "=r"(a) : "l"(p));
    return a;
}
__device__ __forceinline__ uint32_t elect_one_pred() {
    uint32_t pred;
    asm volatile("{\n\t.reg .pred p;\n\telect.sync _|p, 0xFFFFFFFF;\n\tselp.b32 %0, 1, 0, p;\n\t}" : "=r"(pred));
    return pred;
}
#define MBARRIER_INIT(addr, cnt) \
    asm volatile("mbarrier.init.shared.b64 [%0], %1;" :: "r"((uint32_t)(addr)), "r"((uint32_t)(cnt)) : "memory")
#define MBARRIER_WAIT_PARITY(addr, par) do {                                   \
    uint32_t _m = (uint32_t)(addr), _p = (uint32_t)(par), _d;                  \
    asm volatile("{\n\t.reg .pred p;\n\t"                                      \
        "mbarrier.try_wait.parity.acquire.cta.shared::cta.b64 p, [%1], %2;\n\t" \
        "selp.b32 %0, 1, 0, p;\n\t}" : "=r"(_d) : "r"(_m), "r"(_p) : "memory"); \
    if (!_d) {                                                                 \
        asm volatile("{\n\t.reg .pred P1;\n\t"                                 \
            "WL_%=:\n\t"                                                       \
            "mbarrier.try_wait.parity.acquire.cta.shared::cta.b64 P1, [%0], %1, 0x989680;\n\t" \
            "@P1 bra.uni WD_%=;\n\tbra.uni WL_%=;\n\tWD_%=:\n\t}"              \
            :: "r"(_m), "r"(_p) : "memory");                                   \
    } } while (0)

#if TGEMM_TCGEN05
#define TCGEN05_ALLOC(sm_addr, n) \
    asm volatile("tcgen05.alloc.cta_group::1.sync.aligned.shared::cta.b32 [%0], %1;" \
                 :: "r"((uint32_t)(sm_addr)), "r"((uint32_t)(n)) : "memory")
#define TCGEN05_DEALLOC(tm, n) \
    asm volatile("tcgen05.dealloc.cta_group::1.sync.aligned.b32 %0, %1;" :: "r"(tm), "r"((uint32_t)(n)))
#define TCGEN05_RELINQ() \
    asm volatile("tcgen05.relinquish_alloc_permit.cta_group::1.sync.aligned;")
#define TCGEN05_COMMIT(mb) \
    asm volatile("tcgen05.commit.cta_group::1.mbarrier::arrive::one.shared::cluster.b64 [%0];" \
                 :: "r"((uint32_t)(mb)) : "memory")
#define TCGEN05_WAIT_LD()  asm volatile("tcgen05.wait::ld.sync.aligned;" ::: "memory")
#define TCGEN05_FENCE_AFTER()  asm volatile("tcgen05.fence::after_thread_sync;" ::: "memory")
#define TCGEN05_FENCE_BEFORE() asm volatile("tcgen05.fence::before_thread_sync;" ::: "memory")
#define FENCE_PROXY_ASYNC() asm volatile("fence.proxy.async.shared::cta;" ::: "memory")
#define TCGEN05_LD_X32(r, tm) \
    asm volatile("tcgen05.ld.sync.aligned.32x32b.x32.b32 " \
        "{%0, %1, %2, %3, %4, %5, %6, %7, %8, %9, %10, %11, %12, %13, %14, %15, " \
        " %16, %17, %18, %19, %20, %21, %22, %23, %24, %25, %26, %27, %28, %29, %30, %31}, [%32];" \
        : "=r"((r)[0]), "=r"((r)[1]), "=r"((r)[2]), "=r"((r)[3]), "=r"((r)[4]), "=r"((r)[5]), \
          "=r"((r)[6]), "=r"((r)[7]), "=r"((r)[8]), "=r"((r)[9]), "=r"((r)[10]), "=r"((r)[11]), \
          "=r"((r)[12]), "=r"((r)[13]), "=r"((r)[14]), "=r"((r)[15]), "=r"((r)[16]), "=r"((r)[17]), \
          "=r"((r)[18]), "=r"((r)[19]), "=r"((r)[20]), "=r"((r)[21]), "=r"((r)[22]), "=r"((r)[23]), \
          "=r"((r)[24]), "=r"((r)[25]), "=r"((r)[26]), "=r"((r)[27]), "=r"((r)[28]), "=r"((r)[29]), \
          "=r"((r)[30]), "=r"((r)[31]) : "r"(tm))

static __device__ __forceinline__ uint64_t make_desc(uint32_t addr) {
    const uint64_t base = (uint64_t(2) << 61) | (uint64_t(1) << 46)
                        | (uint64_t(64) << 32) | (uint64_t(1) << 16);
    return base | ((uint64_t)(addr >> 4) & 0x3FFF);
}
#define GEMM_IDESC (0x490u | (16u << 17) | (8u << 24))

__device__ __forceinline__ void mma_f16_ss_cg1(uint32_t d, uint64_t ad, uint64_t bd,
                                               uint32_t idesc, uint32_t en) {
    asm volatile("{\n\t.reg .pred p;\n\tsetp.ne.u32 p, %5, 0;\n\t"
        "tcgen05.mma.cta_group::1.kind::f16 [%0], %1, %2, %3, {%4, %4, %4, %4}, p;\n\t}"
        :: "r"(d), "l"(ad), "l"(bd), "r"(idesc), "r"(0u), "r"(en) : "memory");
}
#endif  // TGEMM_TCGEN05

// mma.sync primitive (sm_80+): D += A@B, bf16 in / f32 acc
__device__ __forceinline__ void mma_bf16(float* d, const uint32_t* a, const uint32_t* b) {
    asm volatile("mma.sync.aligned.m16n8k16.row.col.f32.bf16.bf16.f32 "
        "{%0,%1,%2,%3}, {%4,%5,%6,%7}, {%8,%9}, {%0,%1,%2,%3};"
        : "+f"(d[0]), "+f"(d[1]), "+f"(d[2]), "+f"(d[3])
        : "r"(a[0]), "r"(a[1]), "r"(a[2]), "r"(a[3]), "r"(b[0]), "r"(b[1]));
}

__device__ __forceinline__ uint32_t pack2bf(float a, float b) {
    __nv_bfloat162 p = __floats2bfloat162_rn(a, b);
    return *(uint32_t*)&p;
}
__device__ __forceinline__ float bf16_hi(float v) {
    return __bfloat162float(__float2bfloat16(v));
}

// ---------------------------------------------------------------------------
// Scratch (static device globals)
// ---------------------------------------------------------------------------
__device__ __nv_bfloat16 g_a_hi[(size_t)Mrows * Ec];
__device__ __nv_bfloat16 g_a_lo[(size_t)Mrows * Ec];
__device__ float         g_x   [(size_t)Mrows * Ec];
__device__ __nv_bfloat16 g_x_hi[(size_t)Mrows * Ec];
__device__ __nv_bfloat16 g_x_lo[(size_t)Mrows * Ec];
__device__ float         g_t   [(size_t)Mrows * Ec];
__device__ __nv_bfloat16 g_h_hi[(size_t)Mrows * FFc];
__device__ __nv_bfloat16 g_h_lo[(size_t)Mrows * FFc];
__device__ __nv_bfloat16 g_wot_hi[(size_t)Ec * Ec];
__device__ __nv_bfloat16 g_wot_lo[(size_t)Ec * Ec];
__device__ __nv_bfloat16 g_w1t_hi[(size_t)FFc * Ec];
__device__ __nv_bfloat16 g_w1t_lo[(size_t)FFc * Ec];
__device__ __nv_bfloat16 g_w2t_hi[(size_t)Ec * FFc];
__device__ __nv_bfloat16 g_w2t_lo[(size_t)Ec * FFc];
__device__ float g_part[Bc * 16 * Ec];
__device__ float g_xavg[Bc * Ec];
__device__ float g_gpart[8 * Bc * Ec];
__device__ float g_gate[Bc * Ec];

// ---------------------------------------------------------------------------
// Weight transpose + bf16 split:  W[K,N] fp32 -> Wt_hi/lo[N,K] bf16
// ---------------------------------------------------------------------------
__global__ void wtrans_kernel(const float* __restrict__ W,
                              __nv_bfloat16* __restrict__ Th,
                              __nv_bfloat16* __restrict__ Tl, int K, int N)
{
    __shared__ float tt[32][33];
    const int tid = threadIdx.x;
    const int tx = tid & 31, ty8 = tid >> 5;
    const int k0 = blockIdx.y * 32, n0 = blockIdx.x * 32;
#pragma unroll
    for (int i = 0; i < 4; ++i) {
        int row = ty8 + i * 8;
        tt[row][tx] = W[(size_t)(k0 + row) * N + n0 + tx];
    }
    __syncthreads();
#pragma unroll
    for (int i = 0; i < 4; ++i) {
        int n = ty8 + i * 8;
        float v = tt[tx][n];
        __nv_bfloat16 hi = __float2bfloat16(v);
        float lo = v - __bfloat162float(hi);
        size_t o = (size_t)(n0 + n) * K + k0 + tx;
        Th[o] = hi;
        Tl[o] = __float2bfloat16(lo);
    }
}

// ---------------------------------------------------------------------------
// Gate path
// ---------------------------------------------------------------------------
__global__ void colmean_part_kernel(const float* __restrict__ q, float* __restrict__ part)
{
    const int b = blockIdx.x, p = blockIdx.y, tid = threadIdx.x;
    const float* base = q + (size_t)b * Sc * Ec + (size_t)p * 128 * Ec;
    float4 acc = make_float4(0.f, 0.f, 0.f, 0.f);
#pragma unroll 4
    for (int s = 0; s < 128; ++s) {
        float4 v = ((const float4*)(base + (size_t)s * Ec))[tid];
        acc.x += v.x; acc.y += v.y; acc.z += v.z; acc.w += v.w;
    }
    ((float4*)(part + (size_t)(b * 16 + p) * Ec))[tid] = acc;
}
__global__ void colmean_fin_kernel(const float* __restrict__ part, float* __restrict__ xavg)
{
    const int b = blockIdx.x, tid = threadIdx.x;
    float4 acc = make_float4(0.f, 0.f, 0.f, 0.f);
#pragma unroll
    for (int p = 0; p < 16; ++p) {
        float4 v = ((const float4*)(part + (size_t)(b * 16 + p) * Ec))[tid];
        acc.x += v.x; acc.y += v.y; acc.z += v.z; acc.w += v.w;
    }
    const float inv = 1.0f / (float)Sc;
    ((float4*)(xavg + (size_t)b * Ec))[tid] =
        make_float4(acc.x * inv, acc.y * inv, acc.z * inv, acc.w * inv);
}
__global__ void gate_part_kernel(const float* __restrict__ xavg, const float* __restrict__ Wg,
                                 float* __restrict__ gp)
{
    const int idx = blockIdx.x * 256 + threadIdx.x;
    const int b = idx >> 10, e = idx & (Ec - 1);
    const int k0 = blockIdx.y * 128;
    const float* xa = xavg + (size_t)b * Ec;
    float acc = 0.f;
#pragma unroll 8
    for (int k = 0; k < 128; ++k)
        acc = fmaf(xa[k0 + k], Wg[(size_t)(k0 + k) * Ec + e], acc);
    gp[(size_t)blockIdx.y * (Bc * Ec) + idx] = acc;
}
__global__ void gate_fin_kernel(const float* __restrict__ gp, const float* __restrict__ bg,
                                float* __restrict__ gate)
{
    const int idx = blockIdx.x * 256 + threadIdx.x;
    const int e = idx & (Ec - 1);
    float acc = bg[e];
#pragma unroll
    for (int ky = 0; ky < 8; ++ky) acc += gp[(size_t)ky * (Bc * Ec) + idx];
    gate[idx] = 1.0f / (1.0f + expf(-acc));
}

// ---------------------------------------------------------------------------
// Causal flash attention via mma.sync, bf16 3-product split, fp32 softmax.
// Block = 128 threads (4 warps x 16 q-rows), 64x64 tiles, D=64.
// Fragment<->thread mappings identical to the validated tgemm fallback.
// Emits split bf16 output (hi + lo) for the downstream Wo GEMM.
// ---------------------------------------------------------------------------
#define AP 72   // smem pitch in bf16 for K / Vt tiles (4g+t banks, conflict-free)

__global__ __launch_bounds__(128)
void flash_attn_mma_kernel(const float* __restrict__ Q, const float* __restrict__ K,
                           const float* __restrict__ V,
                           __nv_bfloat16* __restrict__ Ohi, __nv_bfloat16* __restrict__ Olo)
{
    __shared__ __align__(16) __nv_bfloat16 sKh[64 * AP];
    __shared__ __align__(16) __nv_bfloat16 sKl[64 * AP];
    __shared__ __align__(16) __nv_bfloat16 sVh[64 * AP];  // transposed: [d][kv]
    __shared__ __align__(16) __nv_bfloat16 sVl[64 * AP];

    const int qt = blockIdx.x;
    const int bh = blockIdx.y;
    const int b = bh >> 4, h = bh & 15;
    const int tid = threadIdx.x;
    const int w = tid >> 5, lane = tid & 31;
    const int g = lane >> 2, t = lane & 3;
    const size_t headoff = (size_t)b * Sc * Ec + (size_t)h * Dc;

    // --- Q fragments (hi/lo), resident in registers for the whole CTA ---
    uint32_t qh[4][4], ql[4][4];
    {
        const int r0 = qt * 64 + w * 16 + g;
#pragma unroll
        for (int ks = 0; ks < 4; ++ks) {
#pragma unroll
            for (int p = 0; p < 4; ++p) {
                const int row = r0 + (p & 1) * 8;
                const int k = ks * 16 + (p >> 1) * 8 + 2 * t;
                float2 qv = *(const float2*)(Q + headoff + (size_t)row * Ec + k);
                qh[ks][p] = pack2bf(qv.x, qv.y);
                ql[ks][p] = pack2bf(qv.x - bf16_hi(qv.x), qv.y - bf16_hi(qv.y));
            }
        }
    }

    float Oacc[8][4];
    float m0 = -1e30f, m1 = -1e30f, l0 = 0.f, l1 = 0.f;
#pragma unroll
    for (int ni = 0; ni < 8; ++ni)
#pragma unroll
        for (int q = 0; q < 4; ++q) Oacc[ni][q] = 0.f;

    const int r0g = qt * 64 + w * 16 + g;   // global q rows for this thread
    const int r1g = r0g + 8;

    for (int kt = 0; kt <= qt; ++kt) {
        __syncthreads();
        // --- cooperative load: K natural [kv][d], V transposed [d][kv], hi/lo ---
        {
            const float* Kp = K + headoff + (size_t)(kt * 64) * Ec;
            const float* Vp = V + headoff + (size_t)(kt * 64) * Ec;
#pragma unroll
            for (int i = 0; i < 8; ++i) {
                const int e = tid + 128 * i;          // 0..1023
                const int r = e >> 4, c4 = (e & 15) << 2;
                float4 kf = *(const float4*)(Kp + (size_t)r * Ec + c4);
                *(uint32_t*)&sKh[r * AP + c4]     = pack2bf(kf.x, kf.y);
                *(uint32_t*)&sKh[r * AP + c4 + 2] = pack2bf(kf.z, kf.w);
                *(uint32_t*)&sKl[r * AP + c4] =
                    pack2bf(kf.x - bf16_hi(kf.x), kf.y - bf16_hi(kf.y));
                *(uint32_t*)&sKl[r * AP + c4 + 2] =
                    pack2bf(kf.z - bf16_hi(kf.z), kf.w - bf16_hi(kf.w));
                float4 vf = *(const float4*)(Vp + (size_t)r * Ec + c4);
                float va[4] = {vf.x, vf.y, vf.z, vf.w};
#pragma unroll
                for (int j = 0; j < 4; ++j) {
                    __nv_bfloat16 hv = __float2bfloat16(va[j]);
                    sVh[(c4 + j) * AP + r] = hv;
                    sVl[(c4 + j) * AP + r] = __float2bfloat16(va[j] - __bfloat162float(hv));
                }
            }
        }
        __syncthreads();

        // --- S = Q K^T ---
        float Sacc[8][4];
#pragma unroll
        for (int ni = 0; ni < 8; ++ni)
#pragma unroll
            for (int q = 0; q < 4; ++q) Sacc[ni][q] = 0.f;

#pragma unroll
        for (int ks = 0; ks < 4; ++ks) {
#pragma unroll
            for (int ni = 0; ni < 8; ++ni) {
                const int bo = (ni * 8 + g) * AP + ks * 16 + 2 * t;
                uint32_t bhf[2], blf[2];
                bhf[0] = *(const uint32_t*)&sKh[bo];
                bhf[1] = *(const uint32_t*)&sKh[bo + 8];
                blf[0] = *(const uint32_t*)&sKl[bo];
                blf[1] = *(const uint32_t*)&sKl[bo + 8];
                mma_bf16(Sacc[ni], qh[ks], bhf);
                mma_bf16(Sacc[ni], qh[ks], blf);
                mma_bf16(Sacc[ni], ql[ks], bhf);
            }
        }

        // --- scale + causal mask ---
        const bool diag = (kt == qt);
#pragma unroll
        for (int ni = 0; ni < 8; ++ni) {
#pragma unroll
            for (int q = 0; q < 4; ++q) {
                float v = Sacc[ni][q] * 0.125f;
                if (diag) {
                    const int col = kt * 64 + ni * 8 + 2 * t + (q & 1);
                    const int row = (q < 2) ? r0g : r1g;
                    if (col > row) v = -1e30f;
                }
                Sacc[ni][q] = v;
            }
        }

        // --- online softmax (rows r0g, r1g per thread; reduce over t-quad) ---
        float mx0 = -1e30f, mx1 = -1e30f;
#pragma unroll
        for (int ni = 0; ni < 8; ++ni) {
            mx0 = fmaxf(mx0, fmaxf(Sacc[ni][0], Sacc[ni][1]));
            mx1 = fmaxf(mx1, fmaxf(Sacc[ni][2], Sacc[ni][3]));
        }
        mx0 = fmaxf(mx0, __shfl_xor_sync(0xffffffffu, mx0, 1));
        mx0 = fmaxf(mx0, __shfl_xor_sync(0xffffffffu, mx0, 2));
        mx1 = fmaxf(mx1, __shfl_xor_sync(0xffffffffu, mx1, 1));
        mx1 = fmaxf(mx1, __shfl_xor_sync(0xffffffffu, mx1, 2));
        const float mn0 = fmaxf(m0, mx0), mn1 = fmaxf(m1, mx1);
        const float corr0 = __expf(m0 - mn0), corr1 = __expf(m1 - mn1);
        float rs0 = 0.f, rs1 = 0.f;
        uint32_t PH[8][2], PL[8][2];
#pragma unroll
        for (int ni = 0; ni < 8; ++ni) {
            float p0 = __expf(Sacc[ni][0] - mn0);
            float p1 = __expf(Sacc[ni][1] - mn0);
            float p2 = __expf(Sacc[ni][2] - mn1);
            float p3 = __expf(Sacc[ni][3] - mn1);
            rs0 += p0 + p1; rs1 += p2 + p3;
            PH[ni][0] = pack2bf(p0, p1);
            PH[ni][1] = pack2bf(p2, p3);
            PL[ni][0] = pack2bf(p0 - bf16_hi(p0), p1 - bf16_hi(p1));
            PL[ni][1] = pack2bf(p2 - bf16_hi(p2), p3 - bf16_hi(p3));
        }
        rs0 += __shfl_xor_sync(0xffffffffu, rs0, 1);
        rs0 += __shfl_xor_sync(0xffffffffu, rs0, 2);
        rs1 += __shfl_xor_sync(0xffffffffu, rs1, 1);
        rs1 += __shfl_xor_sync(0xffffffffu, rs1, 2);
        l0 = l0 * corr0 + rs0;  m0 = mn0;
        l1 = l1 * corr1 + rs1;  m1 = mn1;
#pragma unroll
        for (int ni = 0; ni < 8; ++ni) {
            Oacc[ni][0] *= corr0; Oacc[ni][1] *= corr0;
            Oacc[ni][2] *= corr1; Oacc[ni][3] *= corr1;
        }

        // --- O += P V (P fragments assembled from S accumulators) ---
#pragma unroll
        for (int ks = 0; ks < 4; ++ks) {
            uint32_t aH[4] = {PH[2 * ks][0], PH[2 * ks][1], PH[2 * ks + 1][0], PH[2 * ks + 1][1]};
            uint32_t aL[4] = {PL[2 * ks][0], PL[2 * ks][1], PL[2 * ks + 1][0], PL[2 * ks + 1][1]};
#pragma unroll
            for (int ni = 0; ni < 8; ++ni) {
                const int bo = (ni * 8 + g) * AP + ks * 16 + 2 * t;
                uint32_t bhf[2], blf[2];
                bhf[0] = *(const uint32_t*)&sVh[bo];
                bhf[1] = *(const uint32_t*)&sVh[bo + 8];
                blf[0] = *(const uint32_t*)&sVl[bo];
                blf[1] = *(const uint32_t*)&sVl[bo + 8];
                mma_bf16(Oacc[ni], aH, bhf);
                mma_bf16(Oacc[ni], aH, blf);
                mma_bf16(Oacc[ni], aL, bhf);
            }
        }
    }

    // --- normalize + split bf16 store ---
    const float inv0 = 1.0f / l0, inv1 = 1.0f / l1;
#pragma unroll
    for (int ni = 0; ni < 8; ++ni) {
        const int c = ni * 8 + 2 * t;
        float y0 = Oacc[ni][0] * inv0, y1 = Oacc[ni][1] * inv0;
        float y2 = Oacc[ni][2] * inv1, y3 = Oacc[ni][3] * inv1;
        *(uint32_t*)(Ohi + headoff + (size_t)r0g * Ec + c) = pack2bf(y0, y1);
        *(uint32_t*)(Olo + headoff + (size_t)r0g * Ec + c) =
            pack2bf(y0 - bf16_hi(y0), y1 - bf16_hi(y1));
        *(uint32_t*)(Ohi + headoff + (size_t)r1g * Ec + c) = pack2bf(y2, y3);
        *(uint32_t*)(Olo + headoff + (size_t)r1g * Ec + c) =
            pack2bf(y2 - bf16_hi(y2), y3 - bf16_hi(y3));
    }
}

// ---------------------------------------------------------------------------
// bf16-split GEMM: C(M x N) = A(M x K) @ Bt(N x K)^T, fp32 accumulate.
// 3 products: Ah*Bh + Ah*Bl + Al*Bh. 128x128 tile.
// tcgen05 path when sm_103a feature target is available, else mma.sync.
// EPI 0: Cf = gate[b][n]*(acc+bias[n]) + aux2[m*N+n]
// EPI 1: (Chi,Clo) = split_bf16( gelu(acc + bias[n]) )
// EPI 2: Cf = acc + bias[n] + aux1[m*N+n]
// ---------------------------------------------------------------------------
#define STAGE_BYTES 65536
#define TAIL_OFF    131072
#define TG_SMEM     (TAIL_OFF + 64)

#if TGEMM_TCGEN05
__device__ __forceinline__ void load_tile(const __nv_bfloat16* __restrict__ g, int ldK,
                                          char* s, int tid)
{
#pragma unroll
    for (int i = 0; i < 4; ++i) {
        int v = tid + 256 * i;
        int row = v >> 3;
        int cb = (v & 7) * 16;
        uint4 val = *(const uint4*)((const char*)g + (size_t)row * ldK * 2 + cb);
        uint32_t off = (uint32_t)(row * 128 + cb);
        off ^= (off >> 3) & 0x70;
        *(uint4*)(s + off) = val;
    }
}
#endif

template <int EPI>
__global__ __launch_bounds__(256)
void tgemm_kernel(const __nv_bfloat16* __restrict__ Ah, const __nv_bfloat16* __restrict__ Al,
                  const __nv_bfloat16* __restrict__ Bh, const __nv_bfloat16* __restrict__ Bl,
                  int N, int K,
                  const float* __restrict__ bias,
                  const float* __restrict__ aux1, const float* __restrict__ aux2,
                  float* __restrict__ Cf,
                  __nv_bfloat16* __restrict__ Chi, __nv_bfloat16* __restrict__ Clo)
{
#if TGEMM_TCGEN05
    extern __shared__ __align__(1024) char smc[];
    const uint32_t smem_base = smem_to_u32(smc);
    const int tid = threadIdx.x;
    const int wid = tid >> 5, lid = tid & 31;
    const int bm = blockIdx.y * 128, bn = blockIdx.x * 128;

    const uint32_t tail = smem_base + TAIL_OFF;
    if (tid == 0) {
        MBARRIER_INIT(tail + 16, 1);
        MBARRIER_INIT(tail + 24, 1);
    }
    if (wid == 0) {
        TCGEN05_ALLOC(tail, 128);
        TCGEN05_RELINQ();
    }
    __syncthreads();
    uint32_t tmem;
    asm volatile("ld.shared.b32 %0, [%1];" : "=r"(tmem) : "r"(tail));

    const __nv_bfloat16* Ahp = Ah + (size_t)bm * K;
    const __nv_bfloat16* Alp = Al + (size_t)bm * K;
    const __nv_bfloat16* Bhp = Bh + (size_t)bn * K;
    const __nv_bfloat16* Blp = Bl + (size_t)bn * K;

    const int nt = K >> 6;
    int ph[2] = {0, 0};

    for (int kc = 0; kc < nt; ++kc) {
        const int st = kc & 1;
        if (kc >= 2) {
            MBARRIER_WAIT_PARITY(tail + 16 + st * 8, ph[st]);
            ph[st] ^= 1;
        }
        char* sb = smc + st * STAGE_BYTES;
        load_tile(Ahp + kc * 64, K, sb,         tid);
        load_tile(Alp + kc * 64, K, sb + 16384, tid);
        load_tile(Bhp + kc * 64, K, sb + 32768, tid);
        load_tile(Blp + kc * 64, K, sb + 49152, tid);
        FENCE_PROXY_ASYNC();
        __syncthreads();

        if (wid == 4 && elect_one_pred()) {
            const uint32_t b32 = smem_base + st * STAGE_BYTES;
            uint64_t dAh = make_desc(b32);
            uint64_t dAl = make_desc(b32 + 16384);
            uint64_t dBh = make_desc(b32 + 32768);
            uint64_t dBl = make_desc(b32 + 49152);
#pragma unroll
            for (int k = 0; k < 4; ++k)
                mma_f16_ss_cg1(tmem, dAh + k * 2, dBh + k * 2, GEMM_IDESC,
                               (kc > 0) || (k > 0));
#pragma unroll
            for (int k = 0; k < 4; ++k)
                mma_f16_ss_cg1(tmem, dAh + k * 2, dBl + k * 2, GEMM_IDESC, 1);
#pragma unroll
            for (int k = 0; k < 4; ++k)
                mma_f16_ss_cg1(tmem, dAl + k * 2, dBh + k * 2, GEMM_IDESC, 1);
            TCGEN05_COMMIT(tail + 16 + st * 8);
        }
    }

    const int fl = (nt - 1) & 1;
    MBARRIER_WAIT_PARITY(tail + 16 + fl * 8, ph[fl]);
    TCGEN05_FENCE_AFTER();

    if (wid < 4) {
        const int gr = bm + wid * 32 + lid;
        for (int cb = 0; cb < 128; cb += 32) {
            uint32_t r[32];
            TCGEN05_LD_X32(r, tmem + cb);
            TCGEN05_WAIT_LD();
            const int c0 = bn + cb;
            if (EPI == 0) {
                const float* qrow = aux2 + (size_t)gr * N;
                const float* grow = aux1 + ((gr >> 11) << 10);
#pragma unroll
                for (int j = 0; j < 32; j += 4) {
                    int c = c0 + j;
                    float4 ov;
                    ov.x = grow[c + 0] * (__uint_as_float(r[j + 0]) + bias[c + 0]) + qrow[c + 0];
                    ov.y = grow[c + 1] * (__uint_as_float(r[j + 1]) + bias[c + 1]) + qrow[c + 1];
                    ov.z = grow[c + 2] * (__uint_as_float(r[j + 2]) + bias[c + 2]) + qrow[c + 2];
                    ov.w = grow[c + 3] * (__uint_as_float(r[j + 3]) + bias[c + 3]) + qrow[c + 3];
                    *(float4*)(Cf + (size_t)gr * N + c) = ov;
                }
            } else if (EPI == 1) {
#pragma unroll
                for (int j = 0; j < 32; j += 8) {
                    int c = c0 + j;
                    float v[8], lo[8];
#pragma unroll
                    for (int q = 0; q < 8; ++q) {
                        float x = __uint_as_float(r[j + q]) + bias[c + q];
                        v[q] = 0.5f * x * (1.0f + erff(x * 0.70710678118654752f));
                        __nv_bfloat16 h16 = __float2bfloat16(v[q]);
                        lo[q] = v[q] - __bfloat162float(h16);
                    }
                    uint4 hp = make_uint4(pack2bf(v[0], v[1]), pack2bf(v[2], v[3]),
                                          pack2bf(v[4], v[5]), pack2bf(v[6], v[7]));
                    uint4 lp = make_uint4(pack2bf(lo[0], lo[1]), pack2bf(lo[2], lo[3]),
                                          pack2bf(lo[4], lo[5]), pack2bf(lo[6], lo[7]));
                    *(uint4*)(Chi + (size_t)gr * N + c) = hp;
                    *(uint4*)(Clo + (size_t)gr * N + c) = lp;
                }
            } else {
                const float* xrow = aux1 + (size_t)gr * N;
#pragma unroll
                for (int j = 0; j < 32; j += 4) {
                    int c = c0 + j;
                    float4 ov;
                    ov.x = __uint_as_float(r[j + 0]) + bias[c + 0] + xrow[c + 0];
                    ov.y = __uint_as_float(r[j + 1]) + bias[c + 1] + xrow[c + 1];
                    ov.z = __uint_as_float(r[j + 2]) + bias[c + 2] + xrow[c + 2];
                    ov.w = __uint_as_float(r[j + 3]) + bias[c + 3] + xrow[c + 3];
                    *(float4*)(Cf + (size_t)gr * N + c) = ov;
                }
            }
        }
        TCGEN05_FENCE_BEFORE();
    }
    __syncthreads();
    if (wid == 0) TCGEN05_DEALLOC(tmem, 128);

#else
    // ---------------- mma.sync fallback (base sm_103 PTX) ----------------
    extern __shared__ __align__(1024) char smc[];
    const uint32_t smem_base = smem_to_u32(smc);
    const int tid = threadIdx.x;
    const int wid = tid >> 5, lid = tid & 31;
    const int g = lid >> 2, t = lid & 3;
    const int wm = wid & 3, wn = wid >> 2;
    const int bm = blockIdx.y * 128, bn = blockIdx.x * 128;

    const char* g0 = (const char*)(Ah + (size_t)bm * K);
    const char* g1 = (const char*)(Al + (size_t)bm * K);
    const char* g2 = (const char*)(Bh + (size_t)bn * K);
    const char* g3 = (const char*)(Bl + (size_t)bn * K);

    auto issue_stage = [&](int st, int kc) {
#pragma unroll
        for (int j = 0; j < 8; ++j) {
            const int linear = j * 256 + tid;
            const int buf = linear >> 9;
            const int rem = linear & 511;
            const int row = rem >> 2, c16 = rem & 3;
            const char* gb = (buf == 0) ? g0 : (buf == 1) ? g1 : (buf == 2) ? g2 : g3;
            const char* src = gb + ((size_t)row * K) * 2 + (size_t)kc * 64 + c16 * 16;
            const uint32_t dst = smem_base + st * 40960 + buf * 10240 + row * 80 + c16 * 16;
            asm volatile("cp.async.cg.shared.global [%0], [%1], 16;"
                         :: "r"(dst), "l"(src) : "memory");
        }
        asm volatile("cp.async.commit_group;" ::: "memory");
    };

    float acc[2][8][4];
#pragma unroll
    for (int mi = 0; mi < 2; ++mi)
#pragma unroll
        for (int ni = 0; ni < 8; ++ni)
#pragma unroll
            for (int q = 0; q < 4; ++q) acc[mi][ni][q] = 0.f;

    const int nt = K >> 5;
    issue_stage(0, 0);
    asm volatile("cp.async.wait_group 0;" ::: "memory");
    __syncthreads();

    for (int kc = 0; kc < nt; ++kc) {
        const int st = kc & 1;
        if (kc + 1 < nt) issue_stage(st ^ 1, kc + 1);
        const char* sb = smc + st * 40960;
#pragma unroll
        for (int ks = 0; ks < 2; ++ks) {
            const int ko = (ks * 16 + 2 * t) * 2;
            uint32_t bhf[8][2], blf[8][2];
#pragma unroll
            for (int ni = 0; ni < 8; ++ni) {
                const int rB = (wn * 64 + ni * 8 + g) * 80 + ko;
                bhf[ni][0] = *(const uint32_t*)(sb + 20480 + rB);
                bhf[ni][1] = *(const uint32_t*)(sb + 20480 + rB + 16);
                blf[ni][0] = *(const uint32_t*)(sb + 30720 + rB);
                blf[ni][1] = *(const uint32_t*)(sb + 30720 + rB + 16);
            }
#pragma unroll
            for (int mi = 0; mi < 2; ++mi) {
                const int rA = (wm * 32 + mi * 16 + g) * 80 + ko;
                uint32_t ahf[4], alf[4];
                ahf[0] = *(const uint32_t*)(sb + rA);
                ahf[1] = *(const uint32_t*)(sb + rA + 8 * 80);
                ahf[2] = *(const uint32_t*)(sb + rA + 16);
                ahf[3] = *(const uint32_t*)(sb + rA + 8 * 80 + 16);
                alf[0] = *(const uint32_t*)(sb + 10240 + rA);
                alf[1] = *(const uint32_t*)(sb + 10240 + rA + 8 * 80);
                alf[2] = *(const uint32_t*)(sb + 10240 + rA + 16);
                alf[3] = *(const uint32_t*)(sb + 10240 + rA + 8 * 80 + 16);
#pragma unroll
                for (int ni = 0; ni < 8; ++ni) {
                    mma_bf16(acc[mi][ni], ahf, bhf[ni]);
                    mma_bf16(acc[mi][ni], ahf, blf[ni]);
                    mma_bf16(acc[mi][ni], alf, bhf[ni]);
                }
            }
        }
        if (kc + 1 < nt) asm volatile("cp.async.wait_group 0;" ::: "memory");
        __syncthreads();
    }

#pragma unroll
    for (int mi = 0; mi < 2; ++mi) {
#pragma unroll
        for (int ni = 0; ni < 8; ++ni) {
            const int r0 = bm + wm * 32 + mi * 16 + g;
            const int c  = bn + wn * 64 + ni * 8 + 2 * t;
#pragma unroll
            for (int hh = 0; hh < 2; ++hh) {
                const int r = r0 + hh * 8;
                const float v0 = acc[mi][ni][hh * 2 + 0];
                const float v1 = acc[mi][ni][hh * 2 + 1];
                if (EPI == 0) {
                    const float* grow = aux1 + ((r >> 11) << 10);
                    float2 ov;
                    ov.x = grow[c + 0] * (v0 + bias[c + 0]) + aux2[(size_t)r * N + c + 0];
                    ov.y = grow[c + 1] * (v1 + bias[c + 1]) + aux2[(size_t)r * N + c + 1];
                    *(float2*)(Cf + (size_t)r * N + c) = ov;
                } else if (EPI == 1) {
                    float x0 = v0 + bias[c + 0];
                    float x1 = v1 + bias[c + 1];
                    float y0 = 0.5f * x0 * (1.0f + erff(x0 * 0.70710678118654752f));
                    float y1 = 0.5f * x1 * (1.0f + erff(x1 * 0.70710678118654752f));
                    __nv_bfloat16 h0 = __float2bfloat16(y0);
                    __nv_bfloat16 h1 = __float2bfloat16(y1);
                    float l0 = y0 - __bfloat162float(h0);
                    float l1 = y1 - __bfloat162float(h1);
                    *(uint32_t*)(Chi + (size_t)r * N + c) = pack2bf(y0, y1);
                    *(uint32_t*)(Clo + (size_t)r * N + c) = pack2bf(l0, l1);
                } else {
                    float2 ov;
                    ov.x = v0 + bias[c + 0] + aux1[(size_t)r * N + c + 0];
                    ov.y = v1 + bias[c + 1] + aux1[(size_t)r * N + c + 1];
                    *(float2*)(Cf + (size_t)r * N + c) = ov;
                }
            }
        }
    }
#endif
}

// ---------------------------------------------------------------------------
// LayerNorm(1024); optionally emits bf16 split alongside fp32
// ---------------------------------------------------------------------------
template <int EMIT>
__global__ void ln1024_kernel(const float* __restrict__ in, const float* __restrict__ g,
                              const float* __restrict__ be, float* __restrict__ out,
                              __nv_bfloat16* __restrict__ ohi, __nv_bfloat16* __restrict__ olo)
{
    __shared__ float red[16];
    const int row = blockIdx.x, tid = threadIdx.x;
    float4 v = ((const float4*)(in + (size_t)row * Ec))[tid];
    float s = v.x + v.y + v.z + v.w;
    float q = v.x * v.x + v.y * v.y + v.z * v.z + v.w * v.w;
#pragma unroll
    for (int ofs = 16; ofs > 0; ofs >>= 1) {
        s += __shfl_xor_sync(0xffffffffu, s, ofs);
        q += __shfl_xor_sync(0xffffffffu, q, ofs);
    }
    const int w = tid >> 5;
    if ((tid & 31) == 0) { red[w] = s; red[8 + w] = q; }
    __syncthreads();
    s = 0.f; q = 0.f;
#pragma unroll
    for (int i = 0; i < 8; ++i) { s += red[i]; q += red[8 + i]; }
    const float mu = s * (1.0f / 1024.0f);
    const float var = q * (1.0f / 1024.0f) - mu * mu;
    const float rs = rsqrtf(var + 1e-5f);
    float4 gg = ((const float4*)g)[tid];
    float4 bb = ((const float4*)be)[tid];
    float4 o;
    o.x = (v.x - mu) * rs * gg.x + bb.x;
    o.y = (v.y - mu) * rs * gg.y + bb.y;
    o.z = (v.z - mu) * rs * gg.z + bb.z;
    o.w = (v.w - mu) * rs * gg.w + bb.w;
    ((float4*)(out + (size_t)row * Ec))[tid] = o;
    if (EMIT) {
        float vv[4] = {o.x, o.y, o.z, o.w}, lo[4];
#pragma unroll
        for (int j = 0; j < 4; ++j) {
            __nv_bfloat16 h16 = __float2bfloat16(vv[j]);
            lo[j] = vv[j] - __bfloat162float(h16);
        }
        size_t off = (size_t)row * Ec + tid * 4;
        *(uint2*)(ohi + off) = make_uint2(pack2bf(vv[0], vv[1]), pack2bf(vv[2], vv[3]));
        *(uint2*)(olo + off) = make_uint2(pack2bf(lo[0], lo[1]), pack2bf(lo[2], lo[3]));
    }
}

// ---------------------------------------------------------------------------
// kernel_launch
// ---------------------------------------------------------------------------
extern "C" void kernel_launch(void* const* d_in, const int* in_sizes, int n_in,
                              void* d_out, int out_size)
{
    (void)in_sizes; (void)n_in; (void)out_size;
    const float* Vv  = (const float*)d_in[0];
    const float* Kk  = (const float*)d_in[1];
    const float* Qq  = (const float*)d_in[2];
    const float* Wo  = (const float*)d_in[4];
    const float* bo  = (const float*)d_in[5];
    const float* Wg  = (const float*)d_in[6];
    const float* bg  = (const float*)d_in[7];
    const float* g1  = (const float*)d_in[8];
    const float* b1  = (const float*)d_in[9];
    const float* g2  = (const float*)d_in[10];
    const float* b2  = (const float*)d_in[11];
    const float* W1  = (const float*)d_in[12];
    const float* bf1 = (const float*)d_in[13];
    const float* W2  = (const float*)d_in[14];
    const float* bf2 = (const float*)d_in[15];
    float* out = (float*)d_out;

    __nv_bfloat16 *p_ahi, *p_alo, *p_xhi, *p_xlo, *p_hhi, *p_hlo;
    __nv_bfloat16 *p_wothi, *p_wotlo, *p_w1thi, *p_w1tlo, *p_w2thi, *p_w2tlo;
    float *p_x, *p_t, *p_part, *p_xavg, *p_gpart, *p_gate;
    cudaGetSymbolAddress((void**)&p_ahi, g_a_hi);
    cudaGetSymbolAddress((void**)&p_alo, g_a_lo);
    cudaGetSymbolAddress((void**)&p_x,   g_x);
    cudaGetSymbolAddress((void**)&p_xhi, g_x_hi);
    cudaGetSymbolAddress((void**)&p_xlo, g_x_lo);
    cudaGetSymbolAddress((void**)&p_t,   g_t);
    cudaGetSymbolAddress((void**)&p_hhi, g_h_hi);
    cudaGetSymbolAddress((void**)&p_hlo, g_h_lo);
    cudaGetSymbolAddress((void**)&p_wothi, g_wot_hi);
    cudaGetSymbolAddress((void**)&p_wotlo, g_wot_lo);
    cudaGetSymbolAddress((void**)&p_w1thi, g_w1t_hi);
    cudaGetSymbolAddress((void**)&p_w1tlo, g_w1t_lo);
    cudaGetSymbolAddress((void**)&p_w2thi, g_w2t_hi);
    cudaGetSymbolAddress((void**)&p_w2tlo, g_w2t_lo);
    cudaGetSymbolAddress((void**)&p_part,  g_part);
    cudaGetSymbolAddress((void**)&p_xavg,  g_xavg);
    cudaGetSymbolAddress((void**)&p_gpart, g_gpart);
    cudaGetSymbolAddress((void**)&p_gate,  g_gate);

    cudaFuncSetAttribute(tgemm_kernel<0>,
                         cudaFuncAttributeMaxDynamicSharedMemorySize, TG_SMEM);
    cudaFuncSetAttribute(tgemm_kernel<1>,
                         cudaFuncAttributeMaxDynamicSharedMemorySize, TG_SMEM);
    cudaFuncSetAttribute(tgemm_kernel<2>,
                         cudaFuncAttributeMaxDynamicSharedMemorySize, TG_SMEM);

    // weight transpose + split
    wtrans_kernel<<<dim3(Ec / 32,  Ec / 32),  256>>>(Wo, p_wothi, p_wotlo, Ec,  Ec);
    wtrans_kernel<<<dim3(FFc / 32, Ec / 32),  256>>>(W1, p_w1thi, p_w1tlo, Ec,  FFc);
    wtrans_kernel<<<dim3(Ec / 32,  FFc / 32), 256>>>(W2, p_w2thi, p_w2tlo, FFc, Ec);

    // gate path
    colmean_part_kernel<<<dim3(Bc, 16), 256>>>(Qq, p_part);
    colmean_fin_kernel<<<Bc, 256>>>(p_part, p_xavg);
    gate_part_kernel<<<dim3(Bc * Ec / 256, 8), 256>>>(p_xavg, Wg, p_gpart);
    gate_fin_kernel<<<Bc * Ec / 256, 256>>>(p_gpart, bg, p_gate);

    // attention (mma.sync bf16-split) -> split bf16
    flash_attn_mma_kernel<<<dim3(Sc / 64, Bc * Hc), 128>>>(Qq, Kk, Vv, p_ahi, p_alo);

    // Wo proj + gate + residual -> g_t -> LN1 -> x (fp32 + split)
    tgemm_kernel<0><<<dim3(Ec / 128, Mrows / 128), 256, TG_SMEM>>>(
        p_ahi, p_alo, p_wothi, p_wotlo, Ec, Ec, bo, p_gate, Qq, p_t, nullptr, nullptr);
    ln1024_kernel<1><<<Mrows, 256>>>(p_t, g1, b1, p_x, p_xhi, p_xlo);

    // FFN
    tgemm_kernel<1><<<dim3(FFc / 128, Mrows / 128), 256, TG_SMEM>>>(
        p_xhi, p_xlo, p_w1thi, p_w1tlo, FFc, Ec, bf1, nullptr, nullptr,
        nullptr, p_hhi, p_hlo);
    tgemm_kernel<2><<<dim3(Ec / 128, Mrows / 128), 256, TG_SMEM>>>(
        p_hhi, p_hlo, p_w2thi, p_w2tlo, Ec, FFc, bf2, p_x, nullptr, p_t, nullptr, nullptr);

    ln1024_kernel<0><<<Mrows, 256>>>(p_t, g2, b2, out, nullptr, nullptr);
}

// round 14
// speedup vs baseline: 2.2528x; 1.1484x over previous
#include <cuda_runtime.h>
#include <cuda_bf16.h>
#include <math.h>
#include <stdint.h>

// Problem constants
#define Bc  2
#define Sc  2048
#define Ec  1024
#define Hc  16
#define Dc  64
#define FFc 4096
#define Mrows (Bc * Sc)   // 4096

// ---------------------------------------------------------------------------
// PTX helpers
// ---------------------------------------------------------------------------
__device__ __forceinline__ uint32_t smem_to_u32(const void* p) {
    uint32_t a;
    asm("{ .reg .u64 t; cvta.to.shared.u64 t, %1; cvt.u32.u64 %0, t; }" : "=r"(a) : "l"(p));
    return a;
}

// mma.sync primitive (sm_80+): D += A@B, bf16 in / f32 acc
__device__ __forceinline__ void mma_bf16(float* d, const uint32_t* a, const uint32_t* b) {
    asm volatile("mma.sync.aligned.m16n8k16.row.col.f32.bf16.bf16.f32 "
        "{%0,%1,%2,%3}, {%4,%5,%6,%7}, {%8,%9}, {%0,%1,%2,%3};"
        : "+f"(d[0]), "+f"(d[1]), "+f"(d[2]), "+f"(d[3])
        : "r"(a[0]), "r"(a[1]), "r"(a[2]), "r"(a[3]), "r"(b[0]), "r"(b[1]));
}

__device__ __forceinline__ void ldm_x4(uint32_t& r0, uint32_t& r1, uint32_t& r2,
                                       uint32_t& r3, uint32_t addr) {
    asm volatile("ldmatrix.sync.aligned.m8n8.x4.shared.b16 {%0,%1,%2,%3}, [%4];"
                 : "=r"(r0), "=r"(r1), "=r"(r2), "=r"(r3) : "r"(addr));
}

__device__ __forceinline__ uint32_t pack2bf(float a, float b) {
    __nv_bfloat162 p = __floats2bfloat162_rn(a, b);
    return *(uint32_t*)&p;
}
__device__ __forceinline__ float bf16_hi(float v) {
    return __bfloat162float(__float2bfloat16(v));
}

// ---------------------------------------------------------------------------
// Scratch (static device globals)
// ---------------------------------------------------------------------------
__device__ __nv_bfloat16 g_a_hi[(size_t)Mrows * Ec];
__device__ __nv_bfloat16 g_a_lo[(size_t)Mrows * Ec];
__device__ float         g_x   [(size_t)Mrows * Ec];
__device__ __nv_bfloat16 g_x_hi[(size_t)Mrows * Ec];
__device__ __nv_bfloat16 g_x_lo[(size_t)Mrows * Ec];
__device__ float         g_t   [(size_t)Mrows * Ec];
__device__ __nv_bfloat16 g_h_hi[(size_t)Mrows * FFc];
__device__ __nv_bfloat16 g_h_lo[(size_t)Mrows * FFc];
__device__ __nv_bfloat16 g_wot_hi[(size_t)Ec * Ec];
__device__ __nv_bfloat16 g_wot_lo[(size_t)Ec * Ec];
__device__ __nv_bfloat16 g_w1t_hi[(size_t)FFc * Ec];
__device__ __nv_bfloat16 g_w1t_lo[(size_t)FFc * Ec];
__device__ __nv_bfloat16 g_w2t_hi[(size_t)Ec * FFc];
__device__ __nv_bfloat16 g_w2t_lo[(size_t)Ec * FFc];
__device__ float g_part[Bc * 64 * Ec];
__device__ float g_xavg[Bc * Ec];
__device__ float g_gpart[8 * Bc * Ec];
__device__ float g_gate[Bc * Ec];

// ---------------------------------------------------------------------------
// Weight transpose + bf16 split:  W[K,N] fp32 -> Wt_hi/lo[N,K] bf16
// ---------------------------------------------------------------------------
__global__ void wtrans_kernel(const float* __restrict__ W,
                              __nv_bfloat16* __restrict__ Th,
                              __nv_bfloat16* __restrict__ Tl, int K, int N)
{
    __shared__ float tt[32][33];
    const int tid = threadIdx.x;
    const int tx = tid & 31, ty8 = tid >> 5;
    const int k0 = blockIdx.y * 32, n0 = blockIdx.x * 32;
#pragma unroll
    for (int i = 0; i < 4; ++i) {
        int row = ty8 + i * 8;
        tt[row][tx] = W[(size_t)(k0 + row) * N + n0 + tx];
    }
    __syncthreads();
#pragma unroll
    for (int i = 0; i < 4; ++i) {
        int n = ty8 + i * 8;
        float v = tt[tx][n];
        __nv_bfloat16 hi = __float2bfloat16(v);
        float lo = v - __bfloat162float(hi);
        size_t o = (size_t)(n0 + n) * K + k0 + tx;
        Th[o] = hi;
        Tl[o] = __float2bfloat16(lo);
    }
}

// ---------------------------------------------------------------------------
// Gate path
// ---------------------------------------------------------------------------
__global__ void colmean_part_kernel(const float* __restrict__ q, float* __restrict__ part)
{
    const int b = blockIdx.x, p = blockIdx.y, tid = threadIdx.x;
    const float* base = q + (size_t)b * Sc * Ec + (size_t)p * 32 * Ec;
    float4 acc = make_float4(0.f, 0.f, 0.f, 0.f);
#pragma unroll 4
    for (int s = 0; s < 32; ++s) {
        float4 v = ((const float4*)(base + (size_t)s * Ec))[tid];
        acc.x += v.x; acc.y += v.y; acc.z += v.z; acc.w += v.w;
    }
    ((float4*)(part + (size_t)(b * 64 + p) * Ec))[tid] = acc;
}
__global__ void colmean_fin_kernel(const float* __restrict__ part, float* __restrict__ xavg)
{
    const int b = blockIdx.x, tid = threadIdx.x;
    float4 acc = make_float4(0.f, 0.f, 0.f, 0.f);
#pragma unroll
    for (int p = 0; p < 64; ++p) {
        float4 v = ((const float4*)(part + (size_t)(b * 64 + p) * Ec))[tid];
        acc.x += v.x; acc.y += v.y; acc.z += v.z; acc.w += v.w;
    }
    const float inv = 1.0f / (float)Sc;
    ((float4*)(xavg + (size_t)b * Ec))[tid] =
        make_float4(acc.x * inv, acc.y * inv, acc.z * inv, acc.w * inv);
}
__global__ void gate_part_kernel(const float* __restrict__ xavg, const float* __restrict__ Wg,
                                 float* __restrict__ gp)
{
    const int idx = blockIdx.x * 256 + threadIdx.x;
    const int b = idx >> 10, e = idx & (Ec - 1);
    const int k0 = blockIdx.y * 128;
    const float* xa = xavg + (size_t)b * Ec;
    float acc = 0.f;
#pragma unroll 8
    for (int k = 0; k < 128; ++k)
        acc = fmaf(xa[k0 + k], Wg[(size_t)(k0 + k) * Ec + e], acc);
    gp[(size_t)blockIdx.y * (Bc * Ec) + idx] = acc;
}
__global__ void gate_fin_kernel(const float* __restrict__ gp, const float* __restrict__ bg,
                                float* __restrict__ gate)
{
    const int idx = blockIdx.x * 256 + threadIdx.x;
    const int e = idx & (Ec - 1);
    float acc = bg[e];
#pragma unroll
    for (int ky = 0; ky < 8; ++ky) acc += gp[(size_t)ky * (Bc * Ec) + idx];
    gate[idx] = 1.0f / (1.0f + expf(-acc));
}

// ---------------------------------------------------------------------------
// Causal flash attention via mma.sync, bf16 3-product split, fp32 softmax.
// Block = 128 threads (4 warps x 16 q-rows), 64x64 tiles, D=64.
// ---------------------------------------------------------------------------
#define AP 72   // smem pitch in bf16 for K / Vt tiles

__global__ __launch_bounds__(128)
void flash_attn_mma_kernel(const float* __restrict__ Q, const float* __restrict__ K,
                           const float* __restrict__ V,
                           __nv_bfloat16* __restrict__ Ohi, __nv_bfloat16* __restrict__ Olo)
{
    __shared__ __align__(16) __nv_bfloat16 sKh[64 * AP];
    __shared__ __align__(16) __nv_bfloat16 sKl[64 * AP];
    __shared__ __align__(16) __nv_bfloat16 sVh[64 * AP];  // transposed: [d][kv]
    __shared__ __align__(16) __nv_bfloat16 sVl[64 * AP];

    const int qt = blockIdx.x;
    const int bh = blockIdx.y;
    const int b = bh >> 4, h = bh & 15;
    const int tid = threadIdx.x;
    const int w = tid >> 5, lane = tid & 31;
    const int g = lane >> 2, t = lane & 3;
    const size_t headoff = (size_t)b * Sc * Ec + (size_t)h * Dc;

    // --- Q fragments (hi/lo), resident in registers for the whole CTA ---
    uint32_t qh[4][4], ql[4][4];
    {
        const int r0 = qt * 64 + w * 16 + g;
#pragma unroll
        for (int ks = 0; ks < 4; ++ks) {
#pragma unroll
            for (int p = 0; p < 4; ++p) {
                const int row = r0 + (p & 1) * 8;
                const int k = ks * 16 + (p >> 1) * 8 + 2 * t;
                float2 qv = *(const float2*)(Q + headoff + (size_t)row * Ec + k);
                qh[ks][p] = pack2bf(qv.x, qv.y);
                ql[ks][p] = pack2bf(qv.x - bf16_hi(qv.x), qv.y - bf16_hi(qv.y));
            }
        }
    }

    float Oacc[8][4];
    float m0 = -1e30f, m1 = -1e30f, l0 = 0.f, l1 = 0.f;
#pragma unroll
    for (int ni = 0; ni < 8; ++ni)
#pragma unroll
        for (int q = 0; q < 4; ++q) Oacc[ni][q] = 0.f;

    const int r0g = qt * 64 + w * 16 + g;
    const int r1g = r0g + 8;

    for (int kt = 0; kt <= qt; ++kt) {
        __syncthreads();
        {
            const float* Kp = K + headoff + (size_t)(kt * 64) * Ec;
            const float* Vp = V + headoff + (size_t)(kt * 64) * Ec;
#pragma unroll
            for (int i = 0; i < 8; ++i) {
                const int e = tid + 128 * i;
                const int r = e >> 4, c4 = (e & 15) << 2;
                float4 kf = *(const float4*)(Kp + (size_t)r * Ec + c4);
                *(uint32_t*)&sKh[r * AP + c4]     = pack2bf(kf.x, kf.y);
                *(uint32_t*)&sKh[r * AP + c4 + 2] = pack2bf(kf.z, kf.w);
                *(uint32_t*)&sKl[r * AP + c4] =
                    pack2bf(kf.x - bf16_hi(kf.x), kf.y - bf16_hi(kf.y));
                *(uint32_t*)&sKl[r * AP + c4 + 2] =
                    pack2bf(kf.z - bf16_hi(kf.z), kf.w - bf16_hi(kf.w));
                float4 vf = *(const float4*)(Vp + (size_t)r * Ec + c4);
                float va[4] = {vf.x, vf.y, vf.z, vf.w};
#pragma unroll
                for (int j = 0; j < 4; ++j) {
                    __nv_bfloat16 hv = __float2bfloat16(va[j]);
                    sVh[(c4 + j) * AP + r] = hv;
                    sVl[(c4 + j) * AP + r] = __float2bfloat16(va[j] - __bfloat162float(hv));
                }
            }
        }
        __syncthreads();

        float Sacc[8][4];
#pragma unroll
        for (int ni = 0; ni < 8; ++ni)
#pragma unroll
            for (int q = 0; q < 4; ++q) Sacc[ni][q] = 0.f;

#pragma unroll
        for (int ks = 0; ks < 4; ++ks) {
#pragma unroll
            for (int ni = 0; ni < 8; ++ni) {
                const int bo = (ni * 8 + g) * AP + ks * 16 + 2 * t;
                uint32_t bhf[2], blf[2];
                bhf[0] = *(const uint32_t*)&sKh[bo];
                bhf[1] = *(const uint32_t*)&sKh[bo + 8];
                blf[0] = *(const uint32_t*)&sKl[bo];
                blf[1] = *(const uint32_t*)&sKl[bo + 8];
                mma_bf16(Sacc[ni], qh[ks], bhf);
                mma_bf16(Sacc[ni], qh[ks], blf);
                mma_bf16(Sacc[ni], ql[ks], bhf);
            }
        }

        const bool diag = (kt == qt);
#pragma unroll
        for (int ni = 0; ni < 8; ++ni) {
#pragma unroll
            for (int q = 0; q < 4; ++q) {
                float v = Sacc[ni][q] * 0.125f;
                if (diag) {
                    const int col = kt * 64 + ni * 8 + 2 * t + (q & 1);
                    const int row = (q < 2) ? r0g : r1g;
                    if (col > row) v = -1e30f;
                }
                Sacc[ni][q] = v;
            }
        }

        float mx0 = -1e30f, mx1 = -1e30f;
#pragma unroll
        for (int ni = 0; ni < 8; ++ni) {
            mx0 = fmaxf(mx0, fmaxf(Sacc[ni][0], Sacc[ni][1]));
            mx1 = fmaxf(mx1, fmaxf(Sacc[ni][2], Sacc[ni][3]));
        }
        mx0 = fmaxf(mx0, __shfl_xor_sync(0xffffffffu, mx0, 1));
        mx0 = fmaxf(mx0, __shfl_xor_sync(0xffffffffu, mx0, 2));
        mx1 = fmaxf(mx1, __shfl_xor_sync(0xffffffffu, mx1, 1));
        mx1 = fmaxf(mx1, __shfl_xor_sync(0xffffffffu, mx1, 2));
        const float mn0 = fmaxf(m0, mx0), mn1 = fmaxf(m1, mx1);
        const float corr0 = __expf(m0 - mn0), corr1 = __expf(m1 - mn1);
        float rs0 = 0.f, rs1 = 0.f;
        uint32_t PH[8][2], PL[8][2];
#pragma unroll
        for (int ni = 0; ni < 8; ++ni) {
            float p0 = __expf(Sacc[ni][0] - mn0);
            float p1 = __expf(Sacc[ni][1] - mn0);
            float p2 = __expf(Sacc[ni][2] - mn1);
            float p3 = __expf(Sacc[ni][3] - mn1);
            rs0 += p0 + p1; rs1 += p2 + p3;
            PH[ni][0] = pack2bf(p0, p1);
            PH[ni][1] = pack2bf(p2, p3);
            PL[ni][0] = pack2bf(p0 - bf16_hi(p0), p1 - bf16_hi(p1));
            PL[ni][1] = pack2bf(p2 - bf16_hi(p2), p3 - bf16_hi(p3));
        }
        rs0 += __shfl_xor_sync(0xffffffffu, rs0, 1);
        rs0 += __shfl_xor_sync(0xffffffffu, rs0, 2);
        rs1 += __shfl_xor_sync(0xffffffffu, rs1, 1);
        rs1 += __shfl_xor_sync(0xffffffffu, rs1, 2);
        l0 = l0 * corr0 + rs0;  m0 = mn0;
        l1 = l1 * corr1 + rs1;  m1 = mn1;
#pragma unroll
        for (int ni = 0; ni < 8; ++ni) {
            Oacc[ni][0] *= corr0; Oacc[ni][1] *= corr0;
            Oacc[ni][2] *= corr1; Oacc[ni][3] *= corr1;
        }

#pragma unroll
        for (int ks = 0; ks < 4; ++ks) {
            uint32_t aH[4] = {PH[2 * ks][0], PH[2 * ks][1], PH[2 * ks + 1][0], PH[2 * ks + 1][1]};
            uint32_t aL[4] = {PL[2 * ks][0], PL[2 * ks][1], PL[2 * ks + 1][0], PL[2 * ks + 1][1]};
#pragma unroll
            for (int ni = 0; ni < 8; ++ni) {
                const int bo = (ni * 8 + g) * AP + ks * 16 + 2 * t;
                uint32_t bhf[2], blf[2];
                bhf[0] = *(const uint32_t*)&sVh[bo];
                bhf[1] = *(const uint32_t*)&sVh[bo + 8];
                blf[0] = *(const uint32_t*)&sVl[bo];
                blf[1] = *(const uint32_t*)&sVl[bo + 8];
                mma_bf16(Oacc[ni], aH, bhf);
                mma_bf16(Oacc[ni], aH, blf);
                mma_bf16(Oacc[ni], aL, bhf);
            }
        }
    }

    const float inv0 = 1.0f / l0, inv1 = 1.0f / l1;
#pragma unroll
    for (int ni = 0; ni < 8; ++ni) {
        const int c = ni * 8 + 2 * t;
        float y0 = Oacc[ni][0] * inv0, y1 = Oacc[ni][1] * inv0;
        float y2 = Oacc[ni][2] * inv1, y3 = Oacc[ni][3] * inv1;
        *(uint32_t*)(Ohi + headoff + (size_t)r0g * Ec + c) = pack2bf(y0, y1);
        *(uint32_t*)(Olo + headoff + (size_t)r0g * Ec + c) =
            pack2bf(y0 - bf16_hi(y0), y1 - bf16_hi(y1));
        *(uint32_t*)(Ohi + headoff + (size_t)r1g * Ec + c) = pack2bf(y2, y3);
        *(uint32_t*)(Olo + headoff + (size_t)r1g * Ec + c) =
            pack2bf(y2 - bf16_hi(y2), y3 - bf16_hi(y3));
    }
}

// ---------------------------------------------------------------------------
// bf16-split GEMM via mma.sync + ldmatrix: C(M x N) = A(M x K) @ Bt(N x K)^T.
// 3 products: Ah*Bh + Ah*Bl + Al*Bh, fp32 accumulate. 128x128 tile,
// K-slab 32 double-buffered cp.async. 2 CTAs/SM (smem 80KB, <=128 regs).
// Smem per stage: Ah@0, Al@10240, Bh@20480, Bl@30720 (128 rows x 80B pitch).
// EPI 0: Cf = gate[b][n]*(acc+bias[n]) + aux2[m*N+n]
// EPI 1: (Chi,Clo) = split_bf16( gelu(acc + bias[n]) )
// EPI 2: Cf = acc + bias[n] + aux1[m*N+n]
// ---------------------------------------------------------------------------
#define TG_STAGE 40960
#define TG_SMEM  (2 * TG_STAGE)   // 81920

template <int EPI>
__global__ __launch_bounds__(256, 2)
void tgemm_kernel(const __nv_bfloat16* __restrict__ Ah, const __nv_bfloat16* __restrict__ Al,
                  const __nv_bfloat16* __restrict__ Bh, const __nv_bfloat16* __restrict__ Bl,
                  int N, int K,
                  const float* __restrict__ bias,
                  const float* __restrict__ aux1, const float* __restrict__ aux2,
                  float* __restrict__ Cf,
                  __nv_bfloat16* __restrict__ Chi, __nv_bfloat16* __restrict__ Clo)
{
    extern __shared__ __align__(1024) char smc[];
    const uint32_t smem_base = smem_to_u32(smc);
    const int tid = threadIdx.x;
    const int wid = tid >> 5, lid = tid & 31;
    const int g = lid >> 2, t = lid & 3;
    const int wm = wid & 3, wn = wid >> 2;      // warp tile 32(m) x 64(n)
    const int bm = blockIdx.y * 128, bn = blockIdx.x * 128;

    const char* g0 = (const char*)(Ah + (size_t)bm * K);
    const char* g1 = (const char*)(Al + (size_t)bm * K);
    const char* g2 = (const char*)(Bh + (size_t)bn * K);
    const char* g3 = (const char*)(Bl + (size_t)bn * K);

    auto issue_stage = [&](int st, int kc) {
#pragma unroll
        for (int j = 0; j < 8; ++j) {
            const int linear = j * 256 + tid;         // 0..2047
            const int buf = linear >> 9;
            const int rem = linear & 511;
            const int row = rem >> 2, c16 = rem & 3;
            const char* gb = (buf == 0) ? g0 : (buf == 1) ? g1 : (buf == 2) ? g2 : g3;
            const char* src = gb + ((size_t)row * K) * 2 + (size_t)kc * 64 + c16 * 16;
            const uint32_t dst = smem_base + st * TG_STAGE + buf * 10240 + row * 80 + c16 * 16;
            asm volatile("cp.async.cg.shared.global [%0], [%1], 16;"
                         :: "r"(dst), "l"(src) : "memory");
        }
        asm volatile("cp.async.commit_group;" ::: "memory");
    };

    float acc[2][8][4];
#pragma unroll
    for (int mi = 0; mi < 2; ++mi)
#pragma unroll
        for (int ni = 0; ni < 8; ++ni)
#pragma unroll
            for (int q = 0; q < 4; ++q) acc[mi][ni][q] = 0.f;

    const int nt = K >> 5;
    issue_stage(0, 0);
    asm volatile("cp.async.wait_group 0;" ::: "memory");
    __syncthreads();

    for (int kc = 0; kc < nt; ++kc) {
        const int st = kc & 1;
        if (kc + 1 < nt) issue_stage(st ^ 1, kc + 1);
        const uint32_t sb = smem_base + st * TG_STAGE;
#pragma unroll
        for (int ks = 0; ks < 2; ++ks) {
            // B fragments: 8x (b0,b1) per hi/lo via ldmatrix.x4 (4 ops each)
            uint32_t bh_[8][2], bl_[8][2];
#pragma unroll
            for (int p = 0; p < 4; ++p) {
                const uint32_t baddr = sb + 20480 +
                    (uint32_t)(wn * 64 + p * 16 + (lid & 7) + ((lid >> 4) & 1) * 8) * 80 +
                    (uint32_t)(ks * 32 + ((lid >> 3) & 1) * 16);
                ldm_x4(bh_[2 * p][0], bh_[2 * p][1], bh_[2 * p + 1][0], bh_[2 * p + 1][1],
                       baddr);
                ldm_x4(bl_[2 * p][0], bl_[2 * p][1], bl_[2 * p + 1][0], bl_[2 * p + 1][1],
                       baddr + 10240);
            }
#pragma unroll
            for (int mi = 0; mi < 2; ++mi) {
                const uint32_t aaddr = sb +
                    (uint32_t)(wm * 32 + mi * 16 + (lid & 15)) * 80 +
                    (uint32_t)(ks * 32 + ((lid >> 4) & 1) * 16);
                uint32_t ah_[4], al_[4];
                ldm_x4(ah_[0], ah_[1], ah_[2], ah_[3], aaddr);
                ldm_x4(al_[0], al_[1], al_[2], al_[3], aaddr + 10240);
#pragma unroll
                for (int ni = 0; ni < 8; ++ni) {
                    mma_bf16(acc[mi][ni], ah_, bh_[ni]);
                    mma_bf16(acc[mi][ni], ah_, bl_[ni]);
                    mma_bf16(acc[mi][ni], al_, bh_[ni]);
                }
            }
        }
        if (kc + 1 < nt) asm volatile("cp.async.wait_group 0;" ::: "memory");
        __syncthreads();
    }

    // Epilogue: thread holds D[g][2t..2t+1] (rows g, g+8 per fragment half)
#pragma unroll
    for (int mi = 0; mi < 2; ++mi) {
#pragma unroll
        for (int ni = 0; ni < 8; ++ni) {
            const int r0 = bm + wm * 32 + mi * 16 + g;
            const int c  = bn + wn * 64 + ni * 8 + 2 * t;
#pragma unroll
            for (int hh = 0; hh < 2; ++hh) {
                const int r = r0 + hh * 8;
                const float v0 = acc[mi][ni][hh * 2 + 0];
                const float v1 = acc[mi][ni][hh * 2 + 1];
                if (EPI == 0) {
                    const float* grow = aux1 + ((r >> 11) << 10);
                    float2 ov;
                    ov.x = grow[c + 0] * (v0 + bias[c + 0]) + aux2[(size_t)r * N + c + 0];
                    ov.y = grow[c + 1] * (v1 + bias[c + 1]) + aux2[(size_t)r * N + c + 1];
                    *(float2*)(Cf + (size_t)r * N + c) = ov;
                } else if (EPI == 1) {
                    float x0 = v0 + bias[c + 0];
                    float x1 = v1 + bias[c + 1];
                    float y0 = 0.5f * x0 * (1.0f + erff(x0 * 0.70710678118654752f));
                    float y1 = 0.5f * x1 * (1.0f + erff(x1 * 0.70710678118654752f));
                    float l0 = y0 - bf16_hi(y0);
                    float l1 = y1 - bf16_hi(y1);
                    *(uint32_t*)(Chi + (size_t)r * N + c) = pack2bf(y0, y1);
                    *(uint32_t*)(Clo + (size_t)r * N + c) = pack2bf(l0, l1);
                } else {
                    float2 ov;
                    ov.x = v0 + bias[c + 0] + aux1[(size_t)r * N + c + 0];
                    ov.y = v1 + bias[c + 1] + aux1[(size_t)r * N + c + 1];
                    *(float2*)(Cf + (size_t)r * N + c) = ov;
                }
            }
        }
    }
}

// ---------------------------------------------------------------------------
// LayerNorm(1024); optionally emits bf16 split alongside fp32
// ---------------------------------------------------------------------------
template <int EMIT>
__global__ void ln1024_kernel(const float* __restrict__ in, const float* __restrict__ g,
                              const float* __restrict__ be, float* __restrict__ out,
                              __nv_bfloat16* __restrict__ ohi, __nv_bfloat16* __restrict__ olo)
{
    __shared__ float red[16];
    const int row = blockIdx.x, tid = threadIdx.x;
    float4 v = ((const float4*)(in + (size_t)row * Ec))[tid];
    float s = v.x + v.y + v.z + v.w;
    float q = v.x * v.x + v.y * v.y + v.z * v.z + v.w * v.w;
#pragma unroll
    for (int ofs = 16; ofs > 0; ofs >>= 1) {
        s += __shfl_xor_sync(0xffffffffu, s, ofs);
        q += __shfl_xor_sync(0xffffffffu, q, ofs);
    }
    const int w = tid >> 5;
    if ((tid & 31) == 0) { red[w] = s; red[8 + w] = q; }
    __syncthreads();
    s = 0.f; q = 0.f;
#pragma unroll
    for (int i = 0; i < 8; ++i) { s += red[i]; q += red[8 + i]; }
    const float mu = s * (1.0f / 1024.0f);
    const float var = q * (1.0f / 1024.0f) - mu * mu;
    const float rs = rsqrtf(var + 1e-5f);
    float4 gg = ((const float4*)g)[tid];
    float4 bb = ((const float4*)be)[tid];
    float4 o;
    o.x = (v.x - mu) * rs * gg.x + bb.x;
    o.y = (v.y - mu) * rs * gg.y + bb.y;
    o.z = (v.z - mu) * rs * gg.z + bb.z;
    o.w = (v.w - mu) * rs * gg.w + bb.w;
    ((float4*)(out + (size_t)row * Ec))[tid] = o;
    if (EMIT) {
        float vv[4] = {o.x, o.y, o.z, o.w}, lo[4];
#pragma unroll
        for (int j = 0; j < 4; ++j) {
            lo[j] = vv[j] - bf16_hi(vv[j]);
        }
        size_t off = (size_t)row * Ec + tid * 4;
        *(uint2*)(ohi + off) = make_uint2(pack2bf(vv[0], vv[1]), pack2bf(vv[2], vv[3]));
        *(uint2*)(olo + off) = make_uint2(pack2bf(lo[0], lo[1]), pack2bf(lo[2], lo[3]));
    }
}

// ---------------------------------------------------------------------------
// kernel_launch
// ---------------------------------------------------------------------------
extern "C" void kernel_launch(void* const* d_in, const int* in_sizes, int n_in,
                              void* d_out, int out_size)
{
    (void)in_sizes; (void)n_in; (void)out_size;
    const float* Vv  = (const float*)d_in[0];
    const float* Kk  = (const float*)d_in[1];
    const float* Qq  = (const float*)d_in[2];
    const float* Wo  = (const float*)d_in[4];
    const float* bo  = (const float*)d_in[5];
    const float* Wg  = (const float*)d_in[6];
    const float* bg  = (const float*)d_in[7];
    const float* g1  = (const float*)d_in[8];
    const float* b1  = (const float*)d_in[9];
    const float* g2  = (const float*)d_in[10];
    const float* b2  = (const float*)d_in[11];
    const float* W1  = (const float*)d_in[12];
    const float* bf1 = (const float*)d_in[13];
    const float* W2  = (const float*)d_in[14];
    const float* bf2 = (const float*)d_in[15];
    float* out = (float*)d_out;

    __nv_bfloat16 *p_ahi, *p_alo, *p_xhi, *p_xlo, *p_hhi, *p_hlo;
    __nv_bfloat16 *p_wothi, *p_wotlo, *p_w1thi, *p_w1tlo, *p_w2thi, *p_w2tlo;
    float *p_x, *p_t, *p_part, *p_xavg, *p_gpart, *p_gate;
    cudaGetSymbolAddress((void**)&p_ahi, g_a_hi);
    cudaGetSymbolAddress((void**)&p_alo, g_a_lo);
    cudaGetSymbolAddress((void**)&p_x,   g_x);
    cudaGetSymbolAddress((void**)&p_xhi, g_x_hi);
    cudaGetSymbolAddress((void**)&p_xlo, g_x_lo);
    cudaGetSymbolAddress((void**)&p_t,   g_t);
    cudaGetSymbolAddress((void**)&p_hhi, g_h_hi);
    cudaGetSymbolAddress((void**)&p_hlo, g_h_lo);
    cudaGetSymbolAddress((void**)&p_wothi, g_wot_hi);
    cudaGetSymbolAddress((void**)&p_wotlo, g_wot_lo);
    cudaGetSymbolAddress((void**)&p_w1thi, g_w1t_hi);
    cudaGetSymbolAddress((void**)&p_w1tlo, g_w1t_lo);
    cudaGetSymbolAddress((void**)&p_w2thi, g_w2t_hi);
    cudaGetSymbolAddress((void**)&p_w2tlo, g_w2t_lo);
    cudaGetSymbolAddress((void**)&p_part,  g_part);
    cudaGetSymbolAddress((void**)&p_xavg,  g_xavg);
    cudaGetSymbolAddress((void**)&p_gpart, g_gpart);
    cudaGetSymbolAddress((void**)&p_gate,  g_gate);

    cudaFuncSetAttribute(tgemm_kernel<0>,
                         cudaFuncAttributeMaxDynamicSharedMemorySize, TG_SMEM);
    cudaFuncSetAttribute(tgemm_kernel<1>,
                         cudaFuncAttributeMaxDynamicSharedMemorySize, TG_SMEM);
    cudaFuncSetAttribute(tgemm_kernel<2>,
                         cudaFuncAttributeMaxDynamicSharedMemorySize, TG_SMEM);

    // weight transpose + split
    wtrans_kernel<<<dim3(Ec / 32,  Ec / 32),  256>>>(Wo, p_wothi, p_wotlo, Ec,  Ec);
    wtrans_kernel<<<dim3(FFc / 32, Ec / 32),  256>>>(W1, p_w1thi, p_w1tlo, Ec,  FFc);
    wtrans_kernel<<<dim3(Ec / 32,  FFc / 32), 256>>>(W2, p_w2thi, p_w2tlo, FFc, Ec);

    // gate path
    colmean_part_kernel<<<dim3(Bc, 64), 256>>>(Qq, p_part);
    colmean_fin_kernel<<<Bc, 256>>>(p_part, p_xavg);
    gate_part_kernel<<<dim3(Bc * Ec / 256, 8), 256>>>(p_xavg, Wg, p_gpart);
    gate_fin_kernel<<<Bc * Ec / 256, 256>>>(p_gpart, bg, p_gate);

    // attention (mma.sync bf16-split) -> split bf16
    flash_attn_mma_kernel<<<dim3(Sc / 64, Bc * Hc), 128>>>(Qq, Kk, Vv, p_ahi, p_alo);

    // Wo proj + gate + residual -> g_t -> LN1 -> x (fp32 + split)
    tgemm_kernel<0><<<dim3(Ec / 128, Mrows / 128), 256, TG_SMEM>>>(
        p_ahi, p_alo, p_wothi, p_wotlo, Ec, Ec, bo, p_gate, Qq, p_t, nullptr, nullptr);
    ln1024_kernel<1><<<Mrows, 256>>>(p_t, g1, b1, p_x, p_xhi, p_xlo);

    // FFN
    tgemm_kernel<1><<<dim3(FFc / 128, Mrows / 128), 256, TG_SMEM>>>(
        p_xhi, p_xlo, p_w1thi, p_w1tlo, FFc, Ec, bf1, nullptr, nullptr,
        nullptr, p_hhi, p_hlo);
    tgemm_kernel<2><<<dim3(Ec / 128, Mrows / 128), 256, TG_SMEM>>>(
        p_hhi, p_hlo, p_w2thi, p_w2tlo, Ec, FFc, bf2, p_x, nullptr, p_t, nullptr, nullptr);

    ln1024_kernel<0><<<Mrows, 256>>>(p_t, g2, b2, out, nullptr, nullptr);
}

// round 15
// speedup vs baseline: 2.2531x; 1.0001x over previous
#include <cuda_runtime.h>
#include <cuda_bf16.h>
#include <math.h>
#include <stdint.h>

// Problem constants
#define Bc  2
#define Sc  2048
#define Ec  1024
#define Hc  16
#define Dc  64
#define FFc 4096
#define Mrows (Bc * Sc)   // 4096

// ---------------------------------------------------------------------------
// PTX helpers
// ---------------------------------------------------------------------------
__device__ __forceinline__ uint32_t smem_to_u32(const void* p) {
    uint32_t a;
    asm("{ .reg .u64 t; cvta.to.shared.u64 t, %1; cvt.u32.u64 %0, t; }" : "=r"(a) : "l"(p));
    return a;
}

// mma.sync primitive (sm_80+): D += A@B, bf16 in / f32 acc
__device__ __forceinline__ void mma_bf16(float* d, const uint32_t* a, const uint32_t* b) {
    asm volatile("mma.sync.aligned.m16n8k16.row.col.f32.bf16.bf16.f32 "
        "{%0,%1,%2,%3}, {%4,%5,%6,%7}, {%8,%9}, {%0,%1,%2,%3};"
        : "+f"(d[0]), "+f"(d[1]), "+f"(d[2]), "+f"(d[3])
        : "r"(a[0]), "r"(a[1]), "r"(a[2]), "r"(a[3]), "r"(b[0]), "r"(b[1]));
}

__device__ __forceinline__ void ldm_x4(uint32_t& r0, uint32_t& r1, uint32_t& r2,
                                       uint32_t& r3, uint32_t addr) {
    asm volatile("ldmatrix.sync.aligned.m8n8.x4.shared.b16 {%0,%1,%2,%3}, [%4];"
                 : "=r"(r0), "=r"(r1), "=r"(r2), "=r"(r3) : "r"(addr));
}

__device__ __forceinline__ uint32_t pack2bf(float a, float b) {
    __nv_bfloat162 p = __floats2bfloat162_rn(a, b);
    return *(uint32_t*)&p;
}
__device__ __forceinline__ float bf16_hi(float v) {
    return __bfloat162float(__float2bfloat16(v));
}

// ---------------------------------------------------------------------------
// Scratch (static device globals)
// ---------------------------------------------------------------------------
__device__ __nv_bfloat16 g_a_hi[(size_t)Mrows * Ec];
__device__ __nv_bfloat16 g_a_lo[(size_t)Mrows * Ec];
__device__ float         g_x   [(size_t)Mrows * Ec];
__device__ __nv_bfloat16 g_x_hi[(size_t)Mrows * Ec];
__device__ __nv_bfloat16 g_x_lo[(size_t)Mrows * Ec];
__device__ float         g_t   [(size_t)Mrows * Ec];
__device__ __nv_bfloat16 g_h_hi[(size_t)Mrows * FFc];
__device__ __nv_bfloat16 g_h_lo[(size_t)Mrows * FFc];
__device__ __nv_bfloat16 g_wot_hi[(size_t)Ec * Ec];
__device__ __nv_bfloat16 g_wot_lo[(size_t)Ec * Ec];
__device__ __nv_bfloat16 g_w1t_hi[(size_t)FFc * Ec];
__device__ __nv_bfloat16 g_w1t_lo[(size_t)FFc * Ec];
__device__ __nv_bfloat16 g_w2t_hi[(size_t)Ec * FFc];
__device__ __nv_bfloat16 g_w2t_lo[(size_t)Ec * FFc];
__device__ float g_part[Bc * 64 * Ec];
__device__ float g_xavg[Bc * Ec];
__device__ float g_gpart[8 * Bc * Ec];
__device__ float g_gate[Bc * Ec];

// ---------------------------------------------------------------------------
// Weight transpose + bf16 split:  W[K,N] fp32 -> Wt_hi/lo[N,K] bf16
// ---------------------------------------------------------------------------
__global__ void wtrans_kernel(const float* __restrict__ W,
                              __nv_bfloat16* __restrict__ Th,
                              __nv_bfloat16* __restrict__ Tl, int K, int N)
{
    __shared__ float tt[32][33];
    const int tid = threadIdx.x;
    const int tx = tid & 31, ty8 = tid >> 5;
    const int k0 = blockIdx.y * 32, n0 = blockIdx.x * 32;
#pragma unroll
    for (int i = 0; i < 4; ++i) {
        int row = ty8 + i * 8;
        tt[row][tx] = W[(size_t)(k0 + row) * N + n0 + tx];
    }
    __syncthreads();
#pragma unroll
    for (int i = 0; i < 4; ++i) {
        int n = ty8 + i * 8;
        float v = tt[tx][n];
        __nv_bfloat16 hi = __float2bfloat16(v);
        float lo = v - __bfloat162float(hi);
        size_t o = (size_t)(n0 + n) * K + k0 + tx;
        Th[o] = hi;
        Tl[o] = __float2bfloat16(lo);
    }
}

// ---------------------------------------------------------------------------
// Gate path
// ---------------------------------------------------------------------------
__global__ void colmean_part_kernel(const float* __restrict__ q, float* __restrict__ part)
{
    const int b = blockIdx.x, p = blockIdx.y, tid = threadIdx.x;
    const float* base = q + (size_t)b * Sc * Ec + (size_t)p * 32 * Ec;
    float4 acc = make_float4(0.f, 0.f, 0.f, 0.f);
#pragma unroll 4
    for (int s = 0; s < 32; ++s) {
        float4 v = ((const float4*)(base + (size_t)s * Ec))[tid];
        acc.x += v.x; acc.y += v.y; acc.z += v.z; acc.w += v.w;
    }
    ((float4*)(part + (size_t)(b * 64 + p) * Ec))[tid] = acc;
}
__global__ void colmean_fin_kernel(const float* __restrict__ part, float* __restrict__ xavg)
{
    const int b = blockIdx.x, tid = threadIdx.x;
    float4 acc = make_float4(0.f, 0.f, 0.f, 0.f);
#pragma unroll
    for (int p = 0; p < 64; ++p) {
        float4 v = ((const float4*)(part + (size_t)(b * 64 + p) * Ec))[tid];
        acc.x += v.x; acc.y += v.y; acc.z += v.z; acc.w += v.w;
    }
    const float inv = 1.0f / (float)Sc;
    ((float4*)(xavg + (size_t)b * Ec))[tid] =
        make_float4(acc.x * inv, acc.y * inv, acc.z * inv, acc.w * inv);
}
__global__ void gate_part_kernel(const float* __restrict__ xavg, const float* __restrict__ Wg,
                                 float* __restrict__ gp)
{
    const int idx = blockIdx.x * 256 + threadIdx.x;
    const int b = idx >> 10, e = idx & (Ec - 1);
    const int k0 = blockIdx.y * 128;
    const float* xa = xavg + (size_t)b * Ec;
    float acc = 0.f;
#pragma unroll 8
    for (int k = 0; k < 128; ++k)
        acc = fmaf(xa[k0 + k], Wg[(size_t)(k0 + k) * Ec + e], acc);
    gp[(size_t)blockIdx.y * (Bc * Ec) + idx] = acc;
}
__global__ void gate_fin_kernel(const float* __restrict__ gp, const float* __restrict__ bg,
                                float* __restrict__ gate)
{
    const int idx = blockIdx.x * 256 + threadIdx.x;
    const int e = idx & (Ec - 1);
    float acc = bg[e];
#pragma unroll
    for (int ky = 0; ky < 8; ++ky) acc += gp[(size_t)ky * (Bc * Ec) + idx];
    gate[idx] = 1.0f / (1.0f + expf(-acc));
}

// ---------------------------------------------------------------------------
// Causal flash attention via mma.sync, bf16 3-product split, fp32 softmax.
// Block = 128 threads (4 warps x 16 q-rows), 64x64 tiles, D=64.
// ---------------------------------------------------------------------------
#define AP 72   // smem pitch in bf16 for K / Vt tiles

__global__ __launch_bounds__(128)
void flash_attn_mma_kernel(const float* __restrict__ Q, const float* __restrict__ K,
                           const float* __restrict__ V,
                           __nv_bfloat16* __restrict__ Ohi, __nv_bfloat16* __restrict__ Olo)
{
    __shared__ __align__(16) __nv_bfloat16 sKh[64 * AP];
    __shared__ __align__(16) __nv_bfloat16 sKl[64 * AP];
    __shared__ __align__(16) __nv_bfloat16 sVh[64 * AP];  // transposed: [d][kv]
    __shared__ __align__(16) __nv_bfloat16 sVl[64 * AP];

    const int qt = blockIdx.x;
    const int bh = blockIdx.y;
    const int b = bh >> 4, h = bh & 15;
    const int tid = threadIdx.x;
    const int w = tid >> 5, lane = tid & 31;
    const int g = lane >> 2, t = lane & 3;
    const size_t headoff = (size_t)b * Sc * Ec + (size_t)h * Dc;

    // --- Q fragments (hi/lo), resident in registers for the whole CTA ---
    uint32_t qh[4][4], ql[4][4];
    {
        const int r0 = qt * 64 + w * 16 + g;
#pragma unroll
        for (int ks = 0; ks < 4; ++ks) {
#pragma unroll
            for (int p = 0; p < 4; ++p) {
                const int row = r0 + (p & 1) * 8;
                const int k = ks * 16 + (p >> 1) * 8 + 2 * t;
                float2 qv = *(const float2*)(Q + headoff + (size_t)row * Ec + k);
                qh[ks][p] = pack2bf(qv.x, qv.y);
                ql[ks][p] = pack2bf(qv.x - bf16_hi(qv.x), qv.y - bf16_hi(qv.y));
            }
        }
    }

    float Oacc[8][4];
    float m0 = -1e30f, m1 = -1e30f, l0 = 0.f, l1 = 0.f;
#pragma unroll
    for (int ni = 0; ni < 8; ++ni)
#pragma unroll
        for (int q = 0; q < 4; ++q) Oacc[ni][q] = 0.f;

    const int r0g = qt * 64 + w * 16 + g;
    const int r1g = r0g + 8;

    for (int kt = 0; kt <= qt; ++kt) {
        __syncthreads();
        {
            const float* Kp = K + headoff + (size_t)(kt * 64) * Ec;
            const float* Vp = V + headoff + (size_t)(kt * 64) * Ec;
#pragma unroll
            for (int i = 0; i < 8; ++i) {
                const int e = tid + 128 * i;
                const int r = e >> 4, c4 = (e & 15) << 2;
                float4 kf = *(const float4*)(Kp + (size_t)r * Ec + c4);
                *(uint32_t*)&sKh[r * AP + c4]     = pack2bf(kf.x, kf.y);
                *(uint32_t*)&sKh[r * AP + c4 + 2] = pack2bf(kf.z, kf.w);
                *(uint32_t*)&sKl[r * AP + c4] =
                    pack2bf(kf.x - bf16_hi(kf.x), kf.y - bf16_hi(kf.y));
                *(uint32_t*)&sKl[r * AP + c4 + 2] =
                    pack2bf(kf.z - bf16_hi(kf.z), kf.w - bf16_hi(kf.w));
                float4 vf = *(const float4*)(Vp + (size_t)r * Ec + c4);
                float va[4] = {vf.x, vf.y, vf.z, vf.w};
#pragma unroll
                for (int j = 0; j < 4; ++j) {
                    __nv_bfloat16 hv = __float2bfloat16(va[j]);
                    sVh[(c4 + j) * AP + r] = hv;
                    sVl[(c4 + j) * AP + r] = __float2bfloat16(va[j] - __bfloat162float(hv));
                }
            }
        }
        __syncthreads();

        float Sacc[8][4];
#pragma unroll
        for (int ni = 0; ni < 8; ++ni)
#pragma unroll
            for (int q = 0; q < 4; ++q) Sacc[ni][q] = 0.f;

#pragma unroll
        for (int ks = 0; ks < 4; ++ks) {
#pragma unroll
            for (int ni = 0; ni < 8; ++ni) {
                const int bo = (ni * 8 + g) * AP + ks * 16 + 2 * t;
                uint32_t bhf[2], blf[2];
                bhf[0] = *(const uint32_t*)&sKh[bo];
                bhf[1] = *(const uint32_t*)&sKh[bo + 8];
                blf[0] = *(const uint32_t*)&sKl[bo];
                blf[1] = *(const uint32_t*)&sKl[bo + 8];
                mma_bf16(Sacc[ni], qh[ks], bhf);
                mma_bf16(Sacc[ni], qh[ks], blf);
                mma_bf16(Sacc[ni], ql[ks], bhf);
            }
        }

        const bool diag = (kt == qt);
#pragma unroll
        for (int ni = 0; ni < 8; ++ni) {
#pragma unroll
            for (int q = 0; q < 4; ++q) {
                float v = Sacc[ni][q] * 0.125f;
                if (diag) {
                    const int col = kt * 64 + ni * 8 + 2 * t + (q & 1);
                    const int row = (q < 2) ? r0g : r1g;
                    if (col > row) v = -1e30f;
                }
                Sacc[ni][q] = v;
            }
        }

        float mx0 = -1e30f, mx1 = -1e30f;
#pragma unroll
        for (int ni = 0; ni < 8; ++ni) {
            mx0 = fmaxf(mx0, fmaxf(Sacc[ni][0], Sacc[ni][1]));
            mx1 = fmaxf(mx1, fmaxf(Sacc[ni][2], Sacc[ni][3]));
        }
        mx0 = fmaxf(mx0, __shfl_xor_sync(0xffffffffu, mx0, 1));
        mx0 = fmaxf(mx0, __shfl_xor_sync(0xffffffffu, mx0, 2));
        mx1 = fmaxf(mx1, __shfl_xor_sync(0xffffffffu, mx1, 1));
        mx1 = fmaxf(mx1, __shfl_xor_sync(0xffffffffu, mx1, 2));
        const float mn0 = fmaxf(m0, mx0), mn1 = fmaxf(m1, mx1);
        const float corr0 = __expf(m0 - mn0), corr1 = __expf(m1 - mn1);
        float rs0 = 0.f, rs1 = 0.f;
        uint32_t PH[8][2], PL[8][2];
#pragma unroll
        for (int ni = 0; ni < 8; ++ni) {
            float p0 = __expf(Sacc[ni][0] - mn0);
            float p1 = __expf(Sacc[ni][1] - mn0);
            float p2 = __expf(Sacc[ni][2] - mn1);
            float p3 = __expf(Sacc[ni][3] - mn1);
            rs0 += p0 + p1; rs1 += p2 + p3;
            PH[ni][0] = pack2bf(p0, p1);
            PH[ni][1] = pack2bf(p2, p3);
            PL[ni][0] = pack2bf(p0 - bf16_hi(p0), p1 - bf16_hi(p1));
            PL[ni][1] = pack2bf(p2 - bf16_hi(p2), p3 - bf16_hi(p3));
        }
        rs0 += __shfl_xor_sync(0xffffffffu, rs0, 1);
        rs0 += __shfl_xor_sync(0xffffffffu, rs0, 2);
        rs1 += __shfl_xor_sync(0xffffffffu, rs1, 1);
        rs1 += __shfl_xor_sync(0xffffffffu, rs1, 2);
        l0 = l0 * corr0 + rs0;  m0 = mn0;
        l1 = l1 * corr1 + rs1;  m1 = mn1;
#pragma unroll
        for (int ni = 0; ni < 8; ++ni) {
            Oacc[ni][0] *= corr0; Oacc[ni][1] *= corr0;
            Oacc[ni][2] *= corr1; Oacc[ni][3] *= corr1;
        }

#pragma unroll
        for (int ks = 0; ks < 4; ++ks) {
            uint32_t aH[4] = {PH[2 * ks][0], PH[2 * ks][1], PH[2 * ks + 1][0], PH[2 * ks + 1][1]};
            uint32_t aL[4] = {PL[2 * ks][0], PL[2 * ks][1], PL[2 * ks + 1][0], PL[2 * ks + 1][1]};
#pragma unroll
            for (int ni = 0; ni < 8; ++ni) {
                const int bo = (ni * 8 + g) * AP + ks * 16 + 2 * t;
                uint32_t bhf[2], blf[2];
                bhf[0] = *(const uint32_t*)&sVh[bo];
                bhf[1] = *(const uint32_t*)&sVh[bo + 8];
                blf[0] = *(const uint32_t*)&sVl[bo];
                blf[1] = *(const uint32_t*)&sVl[bo + 8];
                mma_bf16(Oacc[ni], aH, bhf);
                mma_bf16(Oacc[ni], aH, blf);
                mma_bf16(Oacc[ni], aL, bhf);
            }
        }
    }

    const float inv0 = 1.0f / l0, inv1 = 1.0f / l1;
#pragma unroll
    for (int ni = 0; ni < 8; ++ni) {
        const int c = ni * 8 + 2 * t;
        float y0 = Oacc[ni][0] * inv0, y1 = Oacc[ni][1] * inv0;
        float y2 = Oacc[ni][2] * inv1, y3 = Oacc[ni][3] * inv1;
        *(uint32_t*)(Ohi + headoff + (size_t)r0g * Ec + c) = pack2bf(y0, y1);
        *(uint32_t*)(Olo + headoff + (size_t)r0g * Ec + c) =
            pack2bf(y0 - bf16_hi(y0), y1 - bf16_hi(y1));
        *(uint32_t*)(Ohi + headoff + (size_t)r1g * Ec + c) = pack2bf(y2, y3);
        *(uint32_t*)(Olo + headoff + (size_t)r1g * Ec + c) =
            pack2bf(y2 - bf16_hi(y2), y3 - bf16_hi(y3));
    }
}

// ---------------------------------------------------------------------------
// bf16-split GEMM via mma.sync + ldmatrix: C(M x N) = A(M x K) @ Bt(N x K)^T.
// 3 products: Ah*Bh + Ah*Bl + Al*Bh, fp32 accumulate. 128x128 tile,
// K-slab 32 double-buffered cp.async. 2 CTAs/SM (smem 80KB, <=128 regs).
// Smem per stage: Ah@0, Al@10240, Bh@20480, Bl@30720 (128 rows x 80B pitch).
// EPI 0: Cf = gate[b][n]*(acc+bias[n]) + aux2[m*N+n]
// EPI 1: (Chi,Clo) = split_bf16( gelu(acc + bias[n]) )
// EPI 2: Cf = acc + bias[n] + aux1[m*N+n]
// ---------------------------------------------------------------------------
#define TG_STAGE 40960
#define TG_SMEM  (2 * TG_STAGE)   // 81920

template <int EPI>
__global__ __launch_bounds__(256, 2)
void tgemm_kernel(const __nv_bfloat16* __restrict__ Ah, const __nv_bfloat16* __restrict__ Al,
                  const __nv_bfloat16* __restrict__ Bh, const __nv_bfloat16* __restrict__ Bl,
                  int N, int K,
                  const float* __restrict__ bias,
                  const float* __restrict__ aux1, const float* __restrict__ aux2,
                  float* __restrict__ Cf,
                  __nv_bfloat16* __restrict__ Chi, __nv_bfloat16* __restrict__ Clo)
{
    extern __shared__ __align__(1024) char smc[];
    const uint32_t smem_base = smem_to_u32(smc);
    const int tid = threadIdx.x;
    const int wid = tid >> 5, lid = tid & 31;
    const int g = lid >> 2, t = lid & 3;
    const int wm = wid & 3, wn = wid >> 2;      // warp tile 32(m) x 64(n)
    const int bm = blockIdx.y * 128, bn = blockIdx.x * 128;

    const char* g0 = (const char*)(Ah + (size_t)bm * K);
    const char* g1 = (const char*)(Al + (size_t)bm * K);
    const char* g2 = (const char*)(Bh + (size_t)bn * K);
    const char* g3 = (const char*)(Bl + (size_t)bn * K);

    auto issue_stage = [&](int st, int kc) {
#pragma unroll
        for (int j = 0; j < 8; ++j) {
            const int linear = j * 256 + tid;         // 0..2047
            const int buf = linear >> 9;
            const int rem = linear & 511;
            const int row = rem >> 2, c16 = rem & 3;
            const char* gb = (buf == 0) ? g0 : (buf == 1) ? g1 : (buf == 2) ? g2 : g3;
            const char* src = gb + ((size_t)row * K) * 2 + (size_t)kc * 64 + c16 * 16;
            const uint32_t dst = smem_base + st * TG_STAGE + buf * 10240 + row * 80 + c16 * 16;
            asm volatile("cp.async.cg.shared.global [%0], [%1], 16;"
                         :: "r"(dst), "l"(src) : "memory");
        }
        asm volatile("cp.async.commit_group;" ::: "memory");
    };

    float acc[2][8][4];
#pragma unroll
    for (int mi = 0; mi < 2; ++mi)
#pragma unroll
        for (int ni = 0; ni < 8; ++ni)
#pragma unroll
            for (int q = 0; q < 4; ++q) acc[mi][ni][q] = 0.f;

    const int nt = K >> 5;
    issue_stage(0, 0);
    asm volatile("cp.async.wait_group 0;" ::: "memory");
    __syncthreads();

    for (int kc = 0; kc < nt; ++kc) {
        const int st = kc & 1;
        if (kc + 1 < nt) issue_stage(st ^ 1, kc + 1);
        const uint32_t sb = smem_base + st * TG_STAGE;
#pragma unroll
        for (int ks = 0; ks < 2; ++ks) {
            // B fragments: 8x (b0,b1) per hi/lo via ldmatrix.x4 (4 ops each)
            uint32_t bh_[8][2], bl_[8][2];
#pragma unroll
            for (int p = 0; p < 4; ++p) {
                const uint32_t baddr = sb + 20480 +
                    (uint32_t)(wn * 64 + p * 16 + (lid & 7) + ((lid >> 4) & 1) * 8) * 80 +
                    (uint32_t)(ks * 32 + ((lid >> 3) & 1) * 16);
                ldm_x4(bh_[2 * p][0], bh_[2 * p][1], bh_[2 * p + 1][0], bh_[2 * p + 1][1],
                       baddr);
                ldm_x4(bl_[2 * p][0], bl_[2 * p][1], bl_[2 * p + 1][0], bl_[2 * p + 1][1],
                       baddr + 10240);
            }
#pragma unroll
            for (int mi = 0; mi < 2; ++mi) {
                const uint32_t aaddr = sb +
                    (uint32_t)(wm * 32 + mi * 16 + (lid & 15)) * 80 +
                    (uint32_t)(ks * 32 + ((lid >> 4) & 1) * 16);
                uint32_t ah_[4], al_[4];
                ldm_x4(ah_[0], ah_[1], ah_[2], ah_[3], aaddr);
                ldm_x4(al_[0], al_[1], al_[2], al_[3], aaddr + 10240);
#pragma unroll
                for (int ni = 0; ni < 8; ++ni) {
                    mma_bf16(acc[mi][ni], ah_, bh_[ni]);
                    mma_bf16(acc[mi][ni], ah_, bl_[ni]);
                    mma_bf16(acc[mi][ni], al_, bh_[ni]);
                }
            }
        }
        if (kc + 1 < nt) asm volatile("cp.async.wait_group 0;" ::: "memory");
        __syncthreads();
    }

    // Epilogue: thread holds D[g][2t..2t+1] (rows g, g+8 per fragment half)
#pragma unroll
    for (int mi = 0; mi < 2; ++mi) {
#pragma unroll
        for (int ni = 0; ni < 8; ++ni) {
            const int r0 = bm + wm * 32 + mi * 16 + g;
            const int c  = bn + wn * 64 + ni * 8 + 2 * t;
#pragma unroll
            for (int hh = 0; hh < 2; ++hh) {
                const int r = r0 + hh * 8;
                const float v0 = acc[mi][ni][hh * 2 + 0];
                const float v1 = acc[mi][ni][hh * 2 + 1];
                if (EPI == 0) {
                    const float* grow = aux1 + ((r >> 11) << 10);
                    float2 ov;
                    ov.x = grow[c + 0] * (v0 + bias[c + 0]) + aux2[(size_t)r * N + c + 0];
                    ov.y = grow[c + 1] * (v1 + bias[c + 1]) + aux2[(size_t)r * N + c + 1];
                    *(float2*)(Cf + (size_t)r * N + c) = ov;
                } else if (EPI == 1) {
                    float x0 = v0 + bias[c + 0];
                    float x1 = v1 + bias[c + 1];
                    float y0 = 0.5f * x0 * (1.0f + erff(x0 * 0.70710678118654752f));
                    float y1 = 0.5f * x1 * (1.0f + erff(x1 * 0.70710678118654752f));
                    float l0 = y0 - bf16_hi(y0);
                    float l1 = y1 - bf16_hi(y1);
                    *(uint32_t*)(Chi + (size_t)r * N + c) = pack2bf(y0, y1);
                    *(uint32_t*)(Clo + (size_t)r * N + c) = pack2bf(l0, l1);
                } else {
                    float2 ov;
                    ov.x = v0 + bias[c + 0] + aux1[(size_t)r * N + c + 0];
                    ov.y = v1 + bias[c + 1] + aux1[(size_t)r * N + c + 1];
                    *(float2*)(Cf + (size_t)r * N + c) = ov;
                }
            }
        }
    }
}

// ---------------------------------------------------------------------------
// LayerNorm(1024); optionally emits bf16 split alongside fp32
// ---------------------------------------------------------------------------
template <int EMIT>
__global__ void ln1024_kernel(const float* __restrict__ in, const float* __restrict__ g,
                              const float* __restrict__ be, float* __restrict__ out,
                              __nv_bfloat16* __restrict__ ohi, __nv_bfloat16* __restrict__ olo)
{
    __shared__ float red[16];
    const int row = blockIdx.x, tid = threadIdx.x;
    float4 v = ((const float4*)(in + (size_t)row * Ec))[tid];
    float s = v.x + v.y + v.z + v.w;
    float q = v.x * v.x + v.y * v.y + v.z * v.z + v.w * v.w;
#pragma unroll
    for (int ofs = 16; ofs > 0; ofs >>= 1) {
        s += __shfl_xor_sync(0xffffffffu, s, ofs);
        q += __shfl_xor_sync(0xffffffffu, q, ofs);
    }
    const int w = tid >> 5;
    if ((tid & 31) == 0) { red[w] = s; red[8 + w] = q; }
    __syncthreads();
    s = 0.f; q = 0.f;
#pragma unroll
    for (int i = 0; i < 8; ++i) { s += red[i]; q += red[8 + i]; }
    const float mu = s * (1.0f / 1024.0f);
    const float var = q * (1.0f / 1024.0f) - mu * mu;
    const float rs = rsqrtf(var + 1e-5f);
    float4 gg = ((const float4*)g)[tid];
    float4 bb = ((const float4*)be)[tid];
    float4 o;
    o.x = (v.x - mu) * rs * gg.x + bb.x;
    o.y = (v.y - mu) * rs * gg.y + bb.y;
    o.z = (v.z - mu) * rs * gg.z + bb.z;
    o.w = (v.w - mu) * rs * gg.w + bb.w;
    ((float4*)(out + (size_t)row * Ec))[tid] = o;
    if (EMIT) {
        float vv[4] = {o.x, o.y, o.z, o.w}, lo[4];
#pragma unroll
        for (int j = 0; j < 4; ++j) {
            lo[j] = vv[j] - bf16_hi(vv[j]);
        }
        size_t off = (size_t)row * Ec + tid * 4;
        *(uint2*)(ohi + off) = make_uint2(pack2bf(vv[0], vv[1]), pack2bf(vv[2], vv[3]));
        *(uint2*)(olo + off) = make_uint2(pack2bf(lo[0], lo[1]), pack2bf(lo[2], lo[3]));
    }
}

// ---------------------------------------------------------------------------
// kernel_launch
// ---------------------------------------------------------------------------
extern "C" void kernel_launch(void* const* d_in, const int* in_sizes, int n_in,
                              void* d_out, int out_size)
{
    (void)in_sizes; (void)n_in; (void)out_size;
    const float* Vv  = (const float*)d_in[0];
    const float* Kk  = (const float*)d_in[1];
    const float* Qq  = (const float*)d_in[2];
    const float* Wo  = (const float*)d_in[4];
    const float* bo  = (const float*)d_in[5];
    const float* Wg  = (const float*)d_in[6];
    const float* bg  = (const float*)d_in[7];
    const float* g1  = (const float*)d_in[8];
    const float* b1  = (const float*)d_in[9];
    const float* g2  = (const float*)d_in[10];
    const float* b2  = (const float*)d_in[11];
    const float* W1  = (const float*)d_in[12];
    const float* bf1 = (const float*)d_in[13];
    const float* W2  = (const float*)d_in[14];
    const float* bf2 = (const float*)d_in[15];
    float* out = (float*)d_out;

    __nv_bfloat16 *p_ahi, *p_alo, *p_xhi, *p_xlo, *p_hhi, *p_hlo;
    __nv_bfloat16 *p_wothi, *p_wotlo, *p_w1thi, *p_w1tlo, *p_w2thi, *p_w2tlo;
    float *p_x, *p_t, *p_part, *p_xavg, *p_gpart, *p_gate;
    cudaGetSymbolAddress((void**)&p_ahi, g_a_hi);
    cudaGetSymbolAddress((void**)&p_alo, g_a_lo);
    cudaGetSymbolAddress((void**)&p_x,   g_x);
    cudaGetSymbolAddress((void**)&p_xhi, g_x_hi);
    cudaGetSymbolAddress((void**)&p_xlo, g_x_lo);
    cudaGetSymbolAddress((void**)&p_t,   g_t);
    cudaGetSymbolAddress((void**)&p_hhi, g_h_hi);
    cudaGetSymbolAddress((void**)&p_hlo, g_h_lo);
    cudaGetSymbolAddress((void**)&p_wothi, g_wot_hi);
    cudaGetSymbolAddress((void**)&p_wotlo, g_wot_lo);
    cudaGetSymbolAddress((void**)&p_w1thi, g_w1t_hi);
    cudaGetSymbolAddress((void**)&p_w1tlo, g_w1t_lo);
    cudaGetSymbolAddress((void**)&p_w2thi, g_w2t_hi);
    cudaGetSymbolAddress((void**)&p_w2tlo, g_w2t_lo);
    cudaGetSymbolAddress((void**)&p_part,  g_part);
    cudaGetSymbolAddress((void**)&p_xavg,  g_xavg);
    cudaGetSymbolAddress((void**)&p_gpart, g_gpart);
    cudaGetSymbolAddress((void**)&p_gate,  g_gate);

    cudaFuncSetAttribute(tgemm_kernel<0>,
                         cudaFuncAttributeMaxDynamicSharedMemorySize, TG_SMEM);
    cudaFuncSetAttribute(tgemm_kernel<1>,
                         cudaFuncAttributeMaxDynamicSharedMemorySize, TG_SMEM);
    cudaFuncSetAttribute(tgemm_kernel<2>,
                         cudaFuncAttributeMaxDynamicSharedMemorySize, TG_SMEM);

    // weight transpose + split
    wtrans_kernel<<<dim3(Ec / 32,  Ec / 32),  256>>>(Wo, p_wothi, p_wotlo, Ec,  Ec);
    wtrans_kernel<<<dim3(FFc / 32, Ec / 32),  256>>>(W1, p_w1thi, p_w1tlo, Ec,  FFc);
    wtrans_kernel<<<dim3(Ec / 32,  FFc / 32), 256>>>(W2, p_w2thi, p_w2tlo, FFc, Ec);

    // gate path
    colmean_part_kernel<<<dim3(Bc, 64), 256>>>(Qq, p_part);
    colmean_fin_kernel<<<Bc, 256>>>(p_part, p_xavg);
    gate_part_kernel<<<dim3(Bc * Ec / 256, 8), 256>>>(p_xavg, Wg, p_gpart);
    gate_fin_kernel<<<Bc * Ec / 256, 256>>>(p_gpart, bg, p_gate);

    // attention (mma.sync bf16-split) -> split bf16
    flash_attn_mma_kernel<<<dim3(Sc / 64, Bc * Hc), 128>>>(Qq, Kk, Vv, p_ahi, p_alo);

    // Wo proj + gate + residual -> g_t -> LN1 -> x (fp32 + split)
    tgemm_kernel<0><<<dim3(Ec / 128, Mrows / 128), 256, TG_SMEM>>>(
        p_ahi, p_alo, p_wothi, p_wotlo, Ec, Ec, bo, p_gate, Qq, p_t, nullptr, nullptr);
    ln1024_kernel<1><<<Mrows, 256>>>(p_t, g1, b1, p_x, p_xhi, p_xlo);

    // FFN
    tgemm_kernel<1><<<dim3(FFc / 128, Mrows / 128), 256, TG_SMEM>>>(
        p_xhi, p_xlo, p_w1thi, p_w1tlo, FFc, Ec, bf1, nullptr, nullptr,
        nullptr, p_hhi, p_hlo);
    tgemm_kernel<2><<<dim3(Ec / 128, Mrows / 128), 256, TG_SMEM>>>(
        p_hhi, p_hlo, p_w2thi, p_w2tlo, Ec, FFc, bf2, p_x, nullptr, p_t, nullptr, nullptr);

    ln1024_kernel<0><<<Mrows, 256>>>(p_t, g2, b2, out, nullptr, nullptr);
}

// round 16
// speedup vs baseline: 2.6520x; 1.1771x over previous
#include <cuda_runtime.h>
#include <cuda_bf16.h>
#include <cuda_fp16.h>
#include <math.h>
#include <stdint.h>

// Problem constants
#define Bc  2
#define Sc  2048
#define Ec  1024
#define Hc  16
#define Dc  64
#define FFc 4096
#define Mrows (Bc * Sc)   // 4096

// ---------------------------------------------------------------------------
// PTX helpers
// ---------------------------------------------------------------------------
__device__ __forceinline__ uint32_t smem_to_u32(const void* p) {
    uint32_t a;
    asm("{ .reg .u64 t; cvta.to.shared.u64 t, %1; cvt.u32.u64 %0, t; }" : "=r"(a) : "l"(p));
    return a;
}

// mma.sync bf16: D += A@B (f32 acc)
__device__ __forceinline__ void mma_bf16(float* d, const uint32_t* a, const uint32_t* b) {
    asm volatile("mma.sync.aligned.m16n8k16.row.col.f32.bf16.bf16.f32 "
        "{%0,%1,%2,%3}, {%4,%5,%6,%7}, {%8,%9}, {%0,%1,%2,%3};"
        : "+f"(d[0]), "+f"(d[1]), "+f"(d[2]), "+f"(d[3])
        : "r"(a[0]), "r"(a[1]), "r"(a[2]), "r"(a[3]), "r"(b[0]), "r"(b[1]));
}
// mma.sync f16: D += A@B (f32 acc)
__device__ __forceinline__ void mma_f16(float* d, const uint32_t* a, const uint32_t* b) {
    asm volatile("mma.sync.aligned.m16n8k16.row.col.f32.f16.f16.f32 "
        "{%0,%1,%2,%3}, {%4,%5,%6,%7}, {%8,%9}, {%0,%1,%2,%3};"
        : "+f"(d[0]), "+f"(d[1]), "+f"(d[2]), "+f"(d[3])
        : "r"(a[0]), "r"(a[1]), "r"(a[2]), "r"(a[3]), "r"(b[0]), "r"(b[1]));
}

__device__ __forceinline__ void ldm_x4(uint32_t& r0, uint32_t& r1, uint32_t& r2,
                                       uint32_t& r3, uint32_t addr) {
    asm volatile("ldmatrix.sync.aligned.m8n8.x4.shared.b16 {%0,%1,%2,%3}, [%4];"
                 : "=r"(r0), "=r"(r1), "=r"(r2), "=r"(r3) : "r"(addr));
}

__device__ __forceinline__ uint32_t pack2bf(float a, float b) {
    __nv_bfloat162 p = __floats2bfloat162_rn(a, b);
    return *(uint32_t*)&p;
}
__device__ __forceinline__ uint32_t pack2h(float a, float b) {
    __half2 p = __floats2half2_rn(a, b);
    return *(uint32_t*)&p;
}
__device__ __forceinline__ float bf16_hi(float v) {
    return __bfloat162float(__float2bfloat16(v));
}

// ---------------------------------------------------------------------------
// Scratch (static device globals)
// ---------------------------------------------------------------------------
__device__ __half g_a16 [(size_t)Mrows * Ec];   // attention out, fp16
__device__ float  g_x   [(size_t)Mrows * Ec];   // LN1 out fp32
__device__ __half g_x16 [(size_t)Mrows * Ec];   // LN1 out fp16
__device__ float  g_t   [(size_t)Mrows * Ec];   // pre-LN buffer
__device__ __half g_h16 [(size_t)Mrows * FFc];  // FFN hidden fp16
__device__ __half g_wot_h[(size_t)Ec * Ec];
__device__ __half g_wot_l[(size_t)Ec * Ec];
__device__ __half g_w1t_h[(size_t)FFc * Ec];
__device__ __half g_w1t_l[(size_t)FFc * Ec];
__device__ __half g_w2t_h[(size_t)Ec * FFc];
__device__ __half g_w2t_l[(size_t)Ec * FFc];
__device__ float g_part[Bc * 64 * Ec];
__device__ float g_xavg[Bc * Ec];
__device__ float g_gpart[8 * Bc * Ec];
__device__ float g_gate[Bc * Ec];

// ---------------------------------------------------------------------------
// Weight transpose + fp16 split:  W[K,N] fp32 -> Wt_h/l[N,K] fp16
// ---------------------------------------------------------------------------
__global__ void wtrans_kernel(const float* __restrict__ W,
                              __half* __restrict__ Th,
                              __half* __restrict__ Tl, int K, int N)
{
    __shared__ float tt[32][33];
    const int tid = threadIdx.x;
    const int tx = tid & 31, ty8 = tid >> 5;
    const int k0 = blockIdx.y * 32, n0 = blockIdx.x * 32;
#pragma unroll
    for (int i = 0; i < 4; ++i) {
        int row = ty8 + i * 8;
        tt[row][tx] = W[(size_t)(k0 + row) * N + n0 + tx];
    }
    __syncthreads();
#pragma unroll
    for (int i = 0; i < 4; ++i) {
        int n = ty8 + i * 8;
        float v = tt[tx][n];
        __half hi = __float2half_rn(v);
        float lo = v - __half2float(hi);
        size_t o = (size_t)(n0 + n) * K + k0 + tx;
        Th[o] = hi;
        Tl[o] = __float2half_rn(lo);
    }
}

// ---------------------------------------------------------------------------
// Gate path
// ---------------------------------------------------------------------------
__global__ void colmean_part_kernel(const float* __restrict__ q, float* __restrict__ part)
{
    const int b = blockIdx.x, p = blockIdx.y, tid = threadIdx.x;
    const float* base = q + (size_t)b * Sc * Ec + (size_t)p * 32 * Ec;
    float4 acc = make_float4(0.f, 0.f, 0.f, 0.f);
#pragma unroll 4
    for (int s = 0; s < 32; ++s) {
        float4 v = ((const float4*)(base + (size_t)s * Ec))[tid];
        acc.x += v.x; acc.y += v.y; acc.z += v.z; acc.w += v.w;
    }
    ((float4*)(part + (size_t)(b * 64 + p) * Ec))[tid] = acc;
}
__global__ void colmean_fin_kernel(const float* __restrict__ part, float* __restrict__ xavg)
{
    const int b = blockIdx.x, tid = threadIdx.x;
    float4 acc = make_float4(0.f, 0.f, 0.f, 0.f);
#pragma unroll
    for (int p = 0; p < 64; ++p) {
        float4 v = ((const float4*)(part + (size_t)(b * 64 + p) * Ec))[tid];
        acc.x += v.x; acc.y += v.y; acc.z += v.z; acc.w += v.w;
    }
    const float inv = 1.0f / (float)Sc;
    ((float4*)(xavg + (size_t)b * Ec))[tid] =
        make_float4(acc.x * inv, acc.y * inv, acc.z * inv, acc.w * inv);
}
__global__ void gate_part_kernel(const float* __restrict__ xavg, const float* __restrict__ Wg,
                                 float* __restrict__ gp)
{
    const int idx = blockIdx.x * 256 + threadIdx.x;
    const int b = idx >> 10, e = idx & (Ec - 1);
    const int k0 = blockIdx.y * 128;
    const float* xa = xavg + (size_t)b * Ec;
    float acc = 0.f;
#pragma unroll 8
    for (int k = 0; k < 128; ++k)
        acc = fmaf(xa[k0 + k], Wg[(size_t)(k0 + k) * Ec + e], acc);
    gp[(size_t)blockIdx.y * (Bc * Ec) + idx] = acc;
}
__global__ void gate_fin_kernel(const float* __restrict__ gp, const float* __restrict__ bg,
                                float* __restrict__ gate)
{
    const int idx = blockIdx.x * 256 + threadIdx.x;
    const int e = idx & (Ec - 1);
    float acc = bg[e];
#pragma unroll
    for (int ky = 0; ky < 8; ++ky) acc += gp[(size_t)ky * (Bc * Ec) + idx];
    gate[idx] = 1.0f / (1.0f + expf(-acc));
}

// ---------------------------------------------------------------------------
// Causal flash attention via mma.sync, bf16 3-product split, fp32 softmax.
// Block = 128 threads (4 warps x 16 q-rows), 64x64 tiles, D=64.
// Emits single fp16 output for the downstream Wo GEMM.
// ---------------------------------------------------------------------------
#define AP 72   // smem pitch in bf16 for K / Vt tiles

__global__ __launch_bounds__(128)
void flash_attn_mma_kernel(const float* __restrict__ Q, const float* __restrict__ K,
                           const float* __restrict__ V, __half* __restrict__ O)
{
    __shared__ __align__(16) __nv_bfloat16 sKh[64 * AP];
    __shared__ __align__(16) __nv_bfloat16 sKl[64 * AP];
    __shared__ __align__(16) __nv_bfloat16 sVh[64 * AP];  // transposed: [d][kv]
    __shared__ __align__(16) __nv_bfloat16 sVl[64 * AP];

    const int qt = blockIdx.x;
    const int bh = blockIdx.y;
    const int b = bh >> 4, h = bh & 15;
    const int tid = threadIdx.x;
    const int w = tid >> 5, lane = tid & 31;
    const int g = lane >> 2, t = lane & 3;
    const size_t headoff = (size_t)b * Sc * Ec + (size_t)h * Dc;

    uint32_t qh[4][4], ql[4][4];
    {
        const int r0 = qt * 64 + w * 16 + g;
#pragma unroll
        for (int ks = 0; ks < 4; ++ks) {
#pragma unroll
            for (int p = 0; p < 4; ++p) {
                const int row = r0 + (p & 1) * 8;
                const int k = ks * 16 + (p >> 1) * 8 + 2 * t;
                float2 qv = *(const float2*)(Q + headoff + (size_t)row * Ec + k);
                qh[ks][p] = pack2bf(qv.x, qv.y);
                ql[ks][p] = pack2bf(qv.x - bf16_hi(qv.x), qv.y - bf16_hi(qv.y));
            }
        }
    }

    float Oacc[8][4];
    float m0 = -1e30f, m1 = -1e30f, l0 = 0.f, l1 = 0.f;
#pragma unroll
    for (int ni = 0; ni < 8; ++ni)
#pragma unroll
        for (int q = 0; q < 4; ++q) Oacc[ni][q] = 0.f;

    const int r0g = qt * 64 + w * 16 + g;
    const int r1g = r0g + 8;

    for (int kt = 0; kt <= qt; ++kt) {
        __syncthreads();
        {
            const float* Kp = K + headoff + (size_t)(kt * 64) * Ec;
            const float* Vp = V + headoff + (size_t)(kt * 64) * Ec;
#pragma unroll
            for (int i = 0; i < 8; ++i) {
                const int e = tid + 128 * i;
                const int r = e >> 4, c4 = (e & 15) << 2;
                float4 kf = *(const float4*)(Kp + (size_t)r * Ec + c4);
                *(uint32_t*)&sKh[r * AP + c4]     = pack2bf(kf.x, kf.y);
                *(uint32_t*)&sKh[r * AP + c4 + 2] = pack2bf(kf.z, kf.w);
                *(uint32_t*)&sKl[r * AP + c4] =
                    pack2bf(kf.x - bf16_hi(kf.x), kf.y - bf16_hi(kf.y));
                *(uint32_t*)&sKl[r * AP + c4 + 2] =
                    pack2bf(kf.z - bf16_hi(kf.z), kf.w - bf16_hi(kf.w));
                float4 vf = *(const float4*)(Vp + (size_t)r * Ec + c4);
                float va[4] = {vf.x, vf.y, vf.z, vf.w};
#pragma unroll
                for (int j = 0; j < 4; ++j) {
                    __nv_bfloat16 hv = __float2bfloat16(va[j]);
                    sVh[(c4 + j) * AP + r] = hv;
                    sVl[(c4 + j) * AP + r] = __float2bfloat16(va[j] - __bfloat162float(hv));
                }
            }
        }
        __syncthreads();

        float Sacc[8][4];
#pragma unroll
        for (int ni = 0; ni < 8; ++ni)
#pragma unroll
            for (int q = 0; q < 4; ++q) Sacc[ni][q] = 0.f;

#pragma unroll
        for (int ks = 0; ks < 4; ++ks) {
#pragma unroll
            for (int ni = 0; ni < 8; ++ni) {
                const int bo = (ni * 8 + g) * AP + ks * 16 + 2 * t;
                uint32_t bhf[2], blf[2];
                bhf[0] = *(const uint32_t*)&sKh[bo];
                bhf[1] = *(const uint32_t*)&sKh[bo + 8];
                blf[0] = *(const uint32_t*)&sKl[bo];
                blf[1] = *(const uint32_t*)&sKl[bo + 8];
                mma_bf16(Sacc[ni], qh[ks], bhf);
                mma_bf16(Sacc[ni], qh[ks], blf);
                mma_bf16(Sacc[ni], ql[ks], bhf);
            }
        }

        const bool diag = (kt == qt);
#pragma unroll
        for (int ni = 0; ni < 8; ++ni) {
#pragma unroll
            for (int q = 0; q < 4; ++q) {
                float v = Sacc[ni][q] * 0.125f;
                if (diag) {
                    const int col = kt * 64 + ni * 8 + 2 * t + (q & 1);
                    const int row = (q < 2) ? r0g : r1g;
                    if (col > row) v = -1e30f;
                }
                Sacc[ni][q] = v;
            }
        }

        float mx0 = -1e30f, mx1 = -1e30f;
#pragma unroll
        for (int ni = 0; ni < 8; ++ni) {
            mx0 = fmaxf(mx0, fmaxf(Sacc[ni][0], Sacc[ni][1]));
            mx1 = fmaxf(mx1, fmaxf(Sacc[ni][2], Sacc[ni][3]));
        }
        mx0 = fmaxf(mx0, __shfl_xor_sync(0xffffffffu, mx0, 1));
        mx0 = fmaxf(mx0, __shfl_xor_sync(0xffffffffu, mx0, 2));
        mx1 = fmaxf(mx1, __shfl_xor_sync(0xffffffffu, mx1, 1));
        mx1 = fmaxf(mx1, __shfl_xor_sync(0xffffffffu, mx1, 2));
        const float mn0 = fmaxf(m0, mx0), mn1 = fmaxf(m1, mx1);
        const float corr0 = __expf(m0 - mn0), corr1 = __expf(m1 - mn1);
        float rs0 = 0.f, rs1 = 0.f;
        uint32_t PH[8][2], PL[8][2];
#pragma unroll
        for (int ni = 0; ni < 8; ++ni) {
            float p0 = __expf(Sacc[ni][0] - mn0);
            float p1 = __expf(Sacc[ni][1] - mn0);
            float p2 = __expf(Sacc[ni][2] - mn1);
            float p3 = __expf(Sacc[ni][3] - mn1);
            rs0 += p0 + p1; rs1 += p2 + p3;
            PH[ni][0] = pack2bf(p0, p1);
            PH[ni][1] = pack2bf(p2, p3);
            PL[ni][0] = pack2bf(p0 - bf16_hi(p0), p1 - bf16_hi(p1));
            PL[ni][1] = pack2bf(p2 - bf16_hi(p2), p3 - bf16_hi(p3));
        }
        rs0 += __shfl_xor_sync(0xffffffffu, rs0, 1);
        rs0 += __shfl_xor_sync(0xffffffffu, rs0, 2);
        rs1 += __shfl_xor_sync(0xffffffffu, rs1, 1);
        rs1 += __shfl_xor_sync(0xffffffffu, rs1, 2);
        l0 = l0 * corr0 + rs0;  m0 = mn0;
        l1 = l1 * corr1 + rs1;  m1 = mn1;
#pragma unroll
        for (int ni = 0; ni < 8; ++ni) {
            Oacc[ni][0] *= corr0; Oacc[ni][1] *= corr0;
            Oacc[ni][2] *= corr1; Oacc[ni][3] *= corr1;
        }

#pragma unroll
        for (int ks = 0; ks < 4; ++ks) {
            uint32_t aH[4] = {PH[2 * ks][0], PH[2 * ks][1], PH[2 * ks + 1][0], PH[2 * ks + 1][1]};
            uint32_t aL[4] = {PL[2 * ks][0], PL[2 * ks][1], PL[2 * ks + 1][0], PL[2 * ks + 1][1]};
#pragma unroll
            for (int ni = 0; ni < 8; ++ni) {
                const int bo = (ni * 8 + g) * AP + ks * 16 + 2 * t;
                uint32_t bhf[2], blf[2];
                bhf[0] = *(const uint32_t*)&sVh[bo];
                bhf[1] = *(const uint32_t*)&sVh[bo + 8];
                blf[0] = *(const uint32_t*)&sVl[bo];
                blf[1] = *(const uint32_t*)&sVl[bo + 8];
                mma_bf16(Oacc[ni], aH, bhf);
                mma_bf16(Oacc[ni], aH, blf);
                mma_bf16(Oacc[ni], aL, bhf);
            }
        }
    }

    const float inv0 = 1.0f / l0, inv1 = 1.0f / l1;
#pragma unroll
    for (int ni = 0; ni < 8; ++ni) {
        const int c = ni * 8 + 2 * t;
        *(uint32_t*)(O + headoff + (size_t)r0g * Ec + c) =
            pack2h(Oacc[ni][0] * inv0, Oacc[ni][1] * inv0);
        *(uint32_t*)(O + headoff + (size_t)r1g * Ec + c) =
            pack2h(Oacc[ni][2] * inv1, Oacc[ni][3] * inv1);
    }
}

// ---------------------------------------------------------------------------
// fp16 2-product GEMM via mma.sync + ldmatrix:
//   C(M x N) = A16(M x K) @ (Wh + Wl)(N x K)^T, fp32 accumulate.
// A rounded to fp16 (single buffer); weights split to 2x fp16 (~20 bits).
// 128x128 tile, K-slab 32, double-buffered cp.async, 2 CTAs/SM.
// Smem/stage: A@0, Bh@10240, Bl@20480 (128 rows x 80B pitch) = 30720 B.
// EPI 0: Cf = gate[b][n]*(acc+bias[n]) + aux2[m*N+n]
// EPI 1: Ch = fp16( gelu(acc + bias[n]) )
// EPI 2: Cf = acc + bias[n] + aux1[m*N+n]
// ---------------------------------------------------------------------------
#define TG_STAGE 30720
#define TG_SMEM  (2 * TG_STAGE)   // 61440

template <int EPI>
__global__ __launch_bounds__(256, 2)
void tgemm_kernel(const __half* __restrict__ A,
                  const __half* __restrict__ Bh, const __half* __restrict__ Bl,
                  int N, int K,
                  const float* __restrict__ bias,
                  const float* __restrict__ aux1, const float* __restrict__ aux2,
                  float* __restrict__ Cf, __half* __restrict__ Ch)
{
    extern __shared__ __align__(1024) char smc[];
    const uint32_t smem_base = smem_to_u32(smc);
    const int tid = threadIdx.x;
    const int wid = tid >> 5, lid = tid & 31;
    const int g = lid >> 2, t = lid & 3;
    const int wm = wid & 3, wn = wid >> 2;      // warp tile 32(m) x 64(n)
    const int bm = blockIdx.y * 128, bn = blockIdx.x * 128;

    const char* g0 = (const char*)(A  + (size_t)bm * K);
    const char* g1 = (const char*)(Bh + (size_t)bn * K);
    const char* g2 = (const char*)(Bl + (size_t)bn * K);

    auto issue_stage = [&](int st, int kc) {
#pragma unroll
        for (int j = 0; j < 6; ++j) {
            const int linear = j * 256 + tid;         // 0..1535
            const int buf = linear >> 9;              // 0..2
            const int rem = linear & 511;
            const int row = rem >> 2, c16 = rem & 3;
            const char* gb = (buf == 0) ? g0 : (buf == 1) ? g1 : g2;
            const char* src = gb + ((size_t)row * K) * 2 + (size_t)kc * 64 + c16 * 16;
            const uint32_t dst = smem_base + st * TG_STAGE + buf * 10240 + row * 80 + c16 * 16;
            asm volatile("cp.async.cg.shared.global [%0], [%1], 16;"
                         :: "r"(dst), "l"(src) : "memory");
        }
        asm volatile("cp.async.commit_group;" ::: "memory");
    };

    float acc[2][8][4];
#pragma unroll
    for (int mi = 0; mi < 2; ++mi)
#pragma unroll
        for (int ni = 0; ni < 8; ++ni)
#pragma unroll
            for (int q = 0; q < 4; ++q) acc[mi][ni][q] = 0.f;

    const int nt = K >> 5;
    issue_stage(0, 0);
    asm volatile("cp.async.wait_group 0;" ::: "memory");
    __syncthreads();

    for (int kc = 0; kc < nt; ++kc) {
        const int st = kc & 1;
        if (kc + 1 < nt) issue_stage(st ^ 1, kc + 1);
        const uint32_t sb = smem_base + st * TG_STAGE;
#pragma unroll
        for (int ks = 0; ks < 2; ++ks) {
            // B fragments: 8x (b0,b1) for hi and lo
            uint32_t bh_[8][2], bl_[8][2];
#pragma unroll
            for (int p = 0; p < 4; ++p) {
                const uint32_t baddr = sb + 10240 +
                    (uint32_t)(wn * 64 + p * 16 + (lid & 7) + ((lid >> 4) & 1) * 8) * 80 +
                    (uint32_t)(ks * 32 + ((lid >> 3) & 1) * 16);
                ldm_x4(bh_[2 * p][0], bh_[2 * p][1], bh_[2 * p + 1][0], bh_[2 * p + 1][1],
                       baddr);
                ldm_x4(bl_[2 * p][0], bl_[2 * p][1], bl_[2 * p + 1][0], bl_[2 * p + 1][1],
                       baddr + 10240);
            }
#pragma unroll
            for (int mi = 0; mi < 2; ++mi) {
                const uint32_t aaddr = sb +
                    (uint32_t)(wm * 32 + mi * 16 + (lid & 15)) * 80 +
                    (uint32_t)(ks * 32 + ((lid >> 4) & 1) * 16);
                uint32_t a_[4];
                ldm_x4(a_[0], a_[1], a_[2], a_[3], aaddr);
#pragma unroll
                for (int ni = 0; ni < 8; ++ni) {
                    mma_f16(acc[mi][ni], a_, bh_[ni]);
                    mma_f16(acc[mi][ni], a_, bl_[ni]);
                }
            }
        }
        if (kc + 1 < nt) asm volatile("cp.async.wait_group 0;" ::: "memory");
        __syncthreads();
    }

    // Epilogue
#pragma unroll
    for (int mi = 0; mi < 2; ++mi) {
#pragma unroll
        for (int ni = 0; ni < 8; ++ni) {
            const int r0 = bm + wm * 32 + mi * 16 + g;
            const int c  = bn + wn * 64 + ni * 8 + 2 * t;
#pragma unroll
            for (int hh = 0; hh < 2; ++hh) {
                const int r = r0 + hh * 8;
                const float v0 = acc[mi][ni][hh * 2 + 0];
                const float v1 = acc[mi][ni][hh * 2 + 1];
                if (EPI == 0) {
                    const float* grow = aux1 + ((r >> 11) << 10);
                    float2 ov;
                    ov.x = grow[c + 0] * (v0 + bias[c + 0]) + aux2[(size_t)r * N + c + 0];
                    ov.y = grow[c + 1] * (v1 + bias[c + 1]) + aux2[(size_t)r * N + c + 1];
                    *(float2*)(Cf + (size_t)r * N + c) = ov;
                } else if (EPI == 1) {
                    float x0 = v0 + bias[c + 0];
                    float x1 = v1 + bias[c + 1];
                    float y0 = 0.5f * x0 * (1.0f + erff(x0 * 0.70710678118654752f));
                    float y1 = 0.5f * x1 * (1.0f + erff(x1 * 0.70710678118654752f));
                    *(uint32_t*)(Ch + (size_t)r * N + c) = pack2h(y0, y1);
                } else {
                    float2 ov;
                    ov.x = v0 + bias[c + 0] + aux1[(size_t)r * N + c + 0];
                    ov.y = v1 + bias[c + 1] + aux1[(size_t)r * N + c + 1];
                    *(float2*)(Cf + (size_t)r * N + c) = ov;
                }
            }
        }
    }
}

// ---------------------------------------------------------------------------
// LayerNorm(1024); optionally emits fp16 alongside fp32
// ---------------------------------------------------------------------------
template <int EMIT>
__global__ void ln1024_kernel(const float* __restrict__ in, const float* __restrict__ g,
                              const float* __restrict__ be, float* __restrict__ out,
                              __half* __restrict__ o16)
{
    __shared__ float red[16];
    const int row = blockIdx.x, tid = threadIdx.x;
    float4 v = ((const float4*)(in + (size_t)row * Ec))[tid];
    float s = v.x + v.y + v.z + v.w;
    float q = v.x * v.x + v.y * v.y + v.z * v.z + v.w * v.w;
#pragma unroll
    for (int ofs = 16; ofs > 0; ofs >>= 1) {
        s += __shfl_xor_sync(0xffffffffu, s, ofs);
        q += __shfl_xor_sync(0xffffffffu, q, ofs);
    }
    const int w = tid >> 5;
    if ((tid & 31) == 0) { red[w] = s; red[8 + w] = q; }
    __syncthreads();
    s = 0.f; q = 0.f;
#pragma unroll
    for (int i = 0; i < 8; ++i) { s += red[i]; q += red[8 + i]; }
    const float mu = s * (1.0f / 1024.0f);
    const float var = q * (1.0f / 1024.0f) - mu * mu;
    const float rs = rsqrtf(var + 1e-5f);
    float4 gg = ((const float4*)g)[tid];
    float4 bb = ((const float4*)be)[tid];
    float4 o;
    o.x = (v.x - mu) * rs * gg.x + bb.x;
    o.y = (v.y - mu) * rs * gg.y + bb.y;
    o.z = (v.z - mu) * rs * gg.z + bb.z;
    o.w = (v.w - mu) * rs * gg.w + bb.w;
    ((float4*)(out + (size_t)row * Ec))[tid] = o;
    if (EMIT) {
        size_t off = (size_t)row * Ec + tid * 4;
        *(uint2*)(o16 + off) = make_uint2(pack2h(o.x, o.y), pack2h(o.z, o.w));
    }
}

// ---------------------------------------------------------------------------
// kernel_launch
// ---------------------------------------------------------------------------
extern "C" void kernel_launch(void* const* d_in, const int* in_sizes, int n_in,
                              void* d_out, int out_size)
{
    (void)in_sizes; (void)n_in; (void)out_size;
    const float* Vv  = (const float*)d_in[0];
    const float* Kk  = (const float*)d_in[1];
    const float* Qq  = (const float*)d_in[2];
    const float* Wo  = (const float*)d_in[4];
    const float* bo  = (const float*)d_in[5];
    const float* Wg  = (const float*)d_in[6];
    const float* bg  = (const float*)d_in[7];
    const float* g1  = (const float*)d_in[8];
    const float* b1  = (const float*)d_in[9];
    const float* g2  = (const float*)d_in[10];
    const float* b2  = (const float*)d_in[11];
    const float* W1  = (const float*)d_in[12];
    const float* bf1 = (const float*)d_in[13];
    const float* W2  = (const float*)d_in[14];
    const float* bf2 = (const float*)d_in[15];
    float* out = (float*)d_out;

    __half *p_a16, *p_x16, *p_h16;
    __half *p_woth, *p_wotl, *p_w1th, *p_w1tl, *p_w2th, *p_w2tl;
    float *p_x, *p_t, *p_part, *p_xavg, *p_gpart, *p_gate;
    cudaGetSymbolAddress((void**)&p_a16, g_a16);
    cudaGetSymbolAddress((void**)&p_x,   g_x);
    cudaGetSymbolAddress((void**)&p_x16, g_x16);
    cudaGetSymbolAddress((void**)&p_t,   g_t);
    cudaGetSymbolAddress((void**)&p_h16, g_h16);
    cudaGetSymbolAddress((void**)&p_woth, g_wot_h);
    cudaGetSymbolAddress((void**)&p_wotl, g_wot_l);
    cudaGetSymbolAddress((void**)&p_w1th, g_w1t_h);
    cudaGetSymbolAddress((void**)&p_w1tl, g_w1t_l);
    cudaGetSymbolAddress((void**)&p_w2th, g_w2t_h);
    cudaGetSymbolAddress((void**)&p_w2tl, g_w2t_l);
    cudaGetSymbolAddress((void**)&p_part,  g_part);
    cudaGetSymbolAddress((void**)&p_xavg,  g_xavg);
    cudaGetSymbolAddress((void**)&p_gpart, g_gpart);
    cudaGetSymbolAddress((void**)&p_gate,  g_gate);

    cudaFuncSetAttribute(tgemm_kernel<0>,
                         cudaFuncAttributeMaxDynamicSharedMemorySize, TG_SMEM);
    cudaFuncSetAttribute(tgemm_kernel<1>,
                         cudaFuncAttributeMaxDynamicSharedMemorySize, TG_SMEM);
    cudaFuncSetAttribute(tgemm_kernel<2>,
                         cudaFuncAttributeMaxDynamicSharedMemorySize, TG_SMEM);

    // weight transpose + fp16 split
    wtrans_kernel<<<dim3(Ec / 32,  Ec / 32),  256>>>(Wo, p_woth, p_wotl, Ec,  Ec);
    wtrans_kernel<<<dim3(FFc / 32, Ec / 32),  256>>>(W1, p_w1th, p_w1tl, Ec,  FFc);
    wtrans_kernel<<<dim3(Ec / 32,  FFc / 32), 256>>>(W2, p_w2th, p_w2tl, FFc, Ec);

    // gate path
    colmean_part_kernel<<<dim3(Bc, 64), 256>>>(Qq, p_part);
    colmean_fin_kernel<<<Bc, 256>>>(p_part, p_xavg);
    gate_part_kernel<<<dim3(Bc * Ec / 256, 8), 256>>>(p_xavg, Wg, p_gpart);
    gate_fin_kernel<<<Bc * Ec / 256, 256>>>(p_gpart, bg, p_gate);

    // attention (bf16 3-product) -> fp16
    flash_attn_mma_kernel<<<dim3(Sc / 64, Bc * Hc), 128>>>(Qq, Kk, Vv, p_a16);

    // Wo proj + gate + residual -> g_t -> LN1 -> x (fp32 + fp16)
    tgemm_kernel<0><<<dim3(Ec / 128, Mrows / 128), 256, TG_SMEM>>>(
        p_a16, p_woth, p_wotl, Ec, Ec, bo, p_gate, Qq, p_t, nullptr);
    ln1024_kernel<1><<<Mrows, 256>>>(p_t, g1, b1, p_x, p_x16);

    // FFN
    tgemm_kernel<1><<<dim3(FFc / 128, Mrows / 128), 256, TG_SMEM>>>(
        p_x16, p_w1th, p_w1tl, FFc, Ec, bf1, nullptr, nullptr, nullptr, p_h16);
    tgemm_kernel<2><<<dim3(Ec / 128, Mrows / 128), 256, TG_SMEM>>>(
        p_h16, p_w2th, p_w2tl, Ec, FFc, bf2, p_x, nullptr, p_t, nullptr);

    ln1024_kernel<0><<<Mrows, 256>>>(p_t, g2, b2, out, nullptr);
}

// round 17
// speedup vs baseline: 3.0564x; 1.1525x over previous
#include <cuda_runtime.h>
#include <cuda_bf16.h>
#include <cuda_fp16.h>
#include <math.h>
#include <stdint.h>

// Problem constants
#define Bc  2
#define Sc  2048
#define Ec  1024
#define Hc  16
#define Dc  64
#define FFc 4096
#define Mrows (Bc * Sc)   // 4096

// ---------------------------------------------------------------------------
// PTX helpers
// ---------------------------------------------------------------------------
__device__ __forceinline__ uint32_t smem_to_u32(const void* p) {
    uint32_t a;
    asm("{ .reg .u64 t; cvta.to.shared.u64 t, %1; cvt.u32.u64 %0, t; }" : "=r"(a) : "l"(p));
    return a;
}

// mma.sync f16: D += A@B (f32 acc)
__device__ __forceinline__ void mma_f16(float* d, const uint32_t* a, const uint32_t* b) {
    asm volatile("mma.sync.aligned.m16n8k16.row.col.f32.f16.f16.f32 "
        "{%0,%1,%2,%3}, {%4,%5,%6,%7}, {%8,%9}, {%0,%1,%2,%3};"
        : "+f"(d[0]), "+f"(d[1]), "+f"(d[2]), "+f"(d[3])
        : "r"(a[0]), "r"(a[1]), "r"(a[2]), "r"(a[3]), "r"(b[0]), "r"(b[1]));
}

__device__ __forceinline__ void ldm_x4(uint32_t& r0, uint32_t& r1, uint32_t& r2,
                                       uint32_t& r3, uint32_t addr) {
    asm volatile("ldmatrix.sync.aligned.m8n8.x4.shared.b16 {%0,%1,%2,%3}, [%4];"
                 : "=r"(r0), "=r"(r1), "=r"(r2), "=r"(r3) : "r"(addr));
}

__device__ __forceinline__ uint32_t pack2h(float a, float b) {
    __half2 p = __floats2half2_rn(a, b);
    return *(uint32_t*)&p;
}

// ---------------------------------------------------------------------------
// Scratch (static device globals)
// ---------------------------------------------------------------------------
__device__ __half g_a16 [(size_t)Mrows * Ec];   // attention out, fp16
__device__ float  g_x   [(size_t)Mrows * Ec];   // LN1 out fp32
__device__ __half g_x16 [(size_t)Mrows * Ec];   // LN1 out fp16
__device__ float  g_t   [(size_t)Mrows * Ec];   // pre-LN buffer
__device__ __half g_h16 [(size_t)Mrows * FFc];  // FFN hidden fp16
__device__ __half g_wot_h[(size_t)Ec * Ec];
__device__ __half g_wot_l[(size_t)Ec * Ec];
__device__ __half g_w1t_h[(size_t)FFc * Ec];
__device__ __half g_w1t_l[(size_t)FFc * Ec];
__device__ __half g_w2t_h[(size_t)Ec * FFc];
__device__ __half g_w2t_l[(size_t)Ec * FFc];
__device__ float g_part[Bc * 64 * Ec];
__device__ float g_xavg[Bc * Ec];
__device__ float g_gpart[8 * Bc * Ec];
__device__ float g_gate[Bc * Ec];

// ---------------------------------------------------------------------------
// Weight transpose + fp16 split:  W[K,N] fp32 -> Wt_h/l[N,K] fp16
// ---------------------------------------------------------------------------
__global__ void wtrans_kernel(const float* __restrict__ W,
                              __half* __restrict__ Th,
                              __half* __restrict__ Tl, int K, int N)
{
    __shared__ float tt[32][33];
    const int tid = threadIdx.x;
    const int tx = tid & 31, ty8 = tid >> 5;
    const int k0 = blockIdx.y * 32, n0 = blockIdx.x * 32;
#pragma unroll
    for (int i = 0; i < 4; ++i) {
        int row = ty8 + i * 8;
        tt[row][tx] = W[(size_t)(k0 + row) * N + n0 + tx];
    }
    __syncthreads();
#pragma unroll
    for (int i = 0; i < 4; ++i) {
        int n = ty8 + i * 8;
        float v = tt[tx][n];
        __half hi = __float2half_rn(v);
        float lo = v - __half2float(hi);
        size_t o = (size_t)(n0 + n) * K + k0 + tx;
        Th[o] = hi;
        Tl[o] = __float2half_rn(lo);
    }
}

// ---------------------------------------------------------------------------
// Gate path
// ---------------------------------------------------------------------------
__global__ void colmean_part_kernel(const float* __restrict__ q, float* __restrict__ part)
{
    const int b = blockIdx.x, p = blockIdx.y, tid = threadIdx.x;
    const float* base = q + (size_t)b * Sc * Ec + (size_t)p * 32 * Ec;
    float4 acc = make_float4(0.f, 0.f, 0.f, 0.f);
#pragma unroll 4
    for (int s = 0; s < 32; ++s) {
        float4 v = ((const float4*)(base + (size_t)s * Ec))[tid];
        acc.x += v.x; acc.y += v.y; acc.z += v.z; acc.w += v.w;
    }
    ((float4*)(part + (size_t)(b * 64 + p) * Ec))[tid] = acc;
}
__global__ void colmean_fin_kernel(const float* __restrict__ part, float* __restrict__ xavg)
{
    const int b = blockIdx.x, tid = threadIdx.x;
    float4 acc = make_float4(0.f, 0.f, 0.f, 0.f);
#pragma unroll
    for (int p = 0; p < 64; ++p) {
        float4 v = ((const float4*)(part + (size_t)(b * 64 + p) * Ec))[tid];
        acc.x += v.x; acc.y += v.y; acc.z += v.z; acc.w += v.w;
    }
    const float inv = 1.0f / (float)Sc;
    ((float4*)(xavg + (size_t)b * Ec))[tid] =
        make_float4(acc.x * inv, acc.y * inv, acc.z * inv, acc.w * inv);
}
__global__ void gate_part_kernel(const float* __restrict__ xavg, const float* __restrict__ Wg,
                                 float* __restrict__ gp)
{
    const int idx = blockIdx.x * 256 + threadIdx.x;
    const int b = idx >> 10, e = idx & (Ec - 1);
    const int k0 = blockIdx.y * 128;
    const float* xa = xavg + (size_t)b * Ec;
    float acc = 0.f;
#pragma unroll 8
    for (int k = 0; k < 128; ++k)
        acc = fmaf(xa[k0 + k], Wg[(size_t)(k0 + k) * Ec + e], acc);
    gp[(size_t)blockIdx.y * (Bc * Ec) + idx] = acc;
}
__global__ void gate_fin_kernel(const float* __restrict__ gp, const float* __restrict__ bg,
                                float* __restrict__ gate)
{
    const int idx = blockIdx.x * 256 + threadIdx.x;
    const int e = idx & (Ec - 1);
    float acc = bg[e];
#pragma unroll
    for (int ky = 0; ky < 8; ++ky) acc += gp[(size_t)ky * (Bc * Ec) + idx];
    gate[idx] = 1.0f / (1.0f + expf(-acc));
}

// ---------------------------------------------------------------------------
// Causal flash attention via mma.sync, fp16 2-product (Q/P rounded fp16;
// K/V split to fp16 hi+lo), fp32 softmax. Block = 128 threads, 64x64 tiles.
// ---------------------------------------------------------------------------
#define AP 72   // smem pitch in fp16 for K / Vt tiles

__global__ __launch_bounds__(128)
void flash_attn_mma_kernel(const float* __restrict__ Q, const float* __restrict__ K,
                           const float* __restrict__ V, __half* __restrict__ O)
{
    __shared__ __align__(16) __half sKh[64 * AP];
    __shared__ __align__(16) __half sKl[64 * AP];
    __shared__ __align__(16) __half sVh[64 * AP];  // transposed: [d][kv]
    __shared__ __align__(16) __half sVl[64 * AP];

    const int qt = blockIdx.x;
    const int bh = blockIdx.y;
    const int b = bh >> 4, h = bh & 15;
    const int tid = threadIdx.x;
    const int w = tid >> 5, lane = tid & 31;
    const int g = lane >> 2, t = lane & 3;
    const size_t headoff = (size_t)b * Sc * Ec + (size_t)h * Dc;

    // Q fragments (fp16 single), resident in registers for the whole CTA
    uint32_t qh[4][4];
    {
        const int r0 = qt * 64 + w * 16 + g;
#pragma unroll
        for (int ks = 0; ks < 4; ++ks) {
#pragma unroll
            for (int p = 0; p < 4; ++p) {
                const int row = r0 + (p & 1) * 8;
                const int k = ks * 16 + (p >> 1) * 8 + 2 * t;
                float2 qv = *(const float2*)(Q + headoff + (size_t)row * Ec + k);
                qh[ks][p] = pack2h(qv.x, qv.y);
            }
        }
    }

    float Oacc[8][4];
    float m0 = -1e30f, m1 = -1e30f, l0 = 0.f, l1 = 0.f;
#pragma unroll
    for (int ni = 0; ni < 8; ++ni)
#pragma unroll
        for (int q = 0; q < 4; ++q) Oacc[ni][q] = 0.f;

    const int r0g = qt * 64 + w * 16 + g;
    const int r1g = r0g + 8;

    for (int kt = 0; kt <= qt; ++kt) {
        __syncthreads();
        {
            const float* Kp = K + headoff + (size_t)(kt * 64) * Ec;
            const float* Vp = V + headoff + (size_t)(kt * 64) * Ec;
#pragma unroll
            for (int i = 0; i < 8; ++i) {
                const int e = tid + 128 * i;
                const int r = e >> 4, c4 = (e & 15) << 2;
                float4 kf = *(const float4*)(Kp + (size_t)r * Ec + c4);
                float ka[4] = {kf.x, kf.y, kf.z, kf.w};
                float kl[4];
#pragma unroll
                for (int j = 0; j < 4; ++j)
                    kl[j] = ka[j] - __half2float(__float2half_rn(ka[j]));
                *(uint32_t*)&sKh[r * AP + c4]     = pack2h(ka[0], ka[1]);
                *(uint32_t*)&sKh[r * AP + c4 + 2] = pack2h(ka[2], ka[3]);
                *(uint32_t*)&sKl[r * AP + c4]     = pack2h(kl[0], kl[1]);
                *(uint32_t*)&sKl[r * AP + c4 + 2] = pack2h(kl[2], kl[3]);
                float4 vf = *(const float4*)(Vp + (size_t)r * Ec + c4);
                float va[4] = {vf.x, vf.y, vf.z, vf.w};
#pragma unroll
                for (int j = 0; j < 4; ++j) {
                    __half hv = __float2half_rn(va[j]);
                    sVh[(c4 + j) * AP + r] = hv;
                    sVl[(c4 + j) * AP + r] = __float2half_rn(va[j] - __half2float(hv));
                }
            }
        }
        __syncthreads();

        // S = Q K^T (2 products: Q16*Kh + Q16*Kl)
        float Sacc[8][4];
#pragma unroll
        for (int ni = 0; ni < 8; ++ni)
#pragma unroll
            for (int q = 0; q < 4; ++q) Sacc[ni][q] = 0.f;

#pragma unroll
        for (int ks = 0; ks < 4; ++ks) {
#pragma unroll
            for (int ni = 0; ni < 8; ++ni) {
                const int bo = (ni * 8 + g) * AP + ks * 16 + 2 * t;
                uint32_t bhf[2], blf[2];
                bhf[0] = *(const uint32_t*)&sKh[bo];
                bhf[1] = *(const uint32_t*)&sKh[bo + 8];
                blf[0] = *(const uint32_t*)&sKl[bo];
                blf[1] = *(const uint32_t*)&sKl[bo + 8];
                mma_f16(Sacc[ni], qh[ks], bhf);
                mma_f16(Sacc[ni], qh[ks], blf);
            }
        }

        const bool diag = (kt == qt);
#pragma unroll
        for (int ni = 0; ni < 8; ++ni) {
#pragma unroll
            for (int q = 0; q < 4; ++q) {
                float v = Sacc[ni][q] * 0.125f;
                if (diag) {
                    const int col = kt * 64 + ni * 8 + 2 * t + (q & 1);
                    const int row = (q < 2) ? r0g : r1g;
                    if (col > row) v = -1e30f;
                }
                Sacc[ni][q] = v;
            }
        }

        float mx0 = -1e30f, mx1 = -1e30f;
#pragma unroll
        for (int ni = 0; ni < 8; ++ni) {
            mx0 = fmaxf(mx0, fmaxf(Sacc[ni][0], Sacc[ni][1]));
            mx1 = fmaxf(mx1, fmaxf(Sacc[ni][2], Sacc[ni][3]));
        }
        mx0 = fmaxf(mx0, __shfl_xor_sync(0xffffffffu, mx0, 1));
        mx0 = fmaxf(mx0, __shfl_xor_sync(0xffffffffu, mx0, 2));
        mx1 = fmaxf(mx1, __shfl_xor_sync(0xffffffffu, mx1, 1));
        mx1 = fmaxf(mx1, __shfl_xor_sync(0xffffffffu, mx1, 2));
        const float mn0 = fmaxf(m0, mx0), mn1 = fmaxf(m1, mx1);
        const float corr0 = __expf(m0 - mn0), corr1 = __expf(m1 - mn1);
        float rs0 = 0.f, rs1 = 0.f;
        uint32_t PH[8][2];
#pragma unroll
        for (int ni = 0; ni < 8; ++ni) {
            float p0 = __expf(Sacc[ni][0] - mn0);
            float p1 = __expf(Sacc[ni][1] - mn0);
            float p2 = __expf(Sacc[ni][2] - mn1);
            float p3 = __expf(Sacc[ni][3] - mn1);
            rs0 += p0 + p1; rs1 += p2 + p3;
            PH[ni][0] = pack2h(p0, p1);
            PH[ni][1] = pack2h(p2, p3);
        }
        rs0 += __shfl_xor_sync(0xffffffffu, rs0, 1);
        rs0 += __shfl_xor_sync(0xffffffffu, rs0, 2);
        rs1 += __shfl_xor_sync(0xffffffffu, rs1, 1);
        rs1 += __shfl_xor_sync(0xffffffffu, rs1, 2);
        l0 = l0 * corr0 + rs0;  m0 = mn0;
        l1 = l1 * corr1 + rs1;  m1 = mn1;
#pragma unroll
        for (int ni = 0; ni < 8; ++ni) {
            Oacc[ni][0] *= corr0; Oacc[ni][1] *= corr0;
            Oacc[ni][2] *= corr1; Oacc[ni][3] *= corr1;
        }

        // O += P V (2 products: P16*Vh + P16*Vl)
#pragma unroll
        for (int ks = 0; ks < 4; ++ks) {
            uint32_t aH[4] = {PH[2 * ks][0], PH[2 * ks][1], PH[2 * ks + 1][0], PH[2 * ks + 1][1]};
#pragma unroll
            for (int ni = 0; ni < 8; ++ni) {
                const int bo = (ni * 8 + g) * AP + ks * 16 + 2 * t;
                uint32_t bhf[2], blf[2];
                bhf[0] = *(const uint32_t*)&sVh[bo];
                bhf[1] = *(const uint32_t*)&sVh[bo + 8];
                blf[0] = *(const uint32_t*)&sVl[bo];
                blf[1] = *(const uint32_t*)&sVl[bo + 8];
                mma_f16(Oacc[ni], aH, bhf);
                mma_f16(Oacc[ni], aH, blf);
            }
        }
    }

    const float inv0 = 1.0f / l0, inv1 = 1.0f / l1;
#pragma unroll
    for (int ni = 0; ni < 8; ++ni) {
        const int c = ni * 8 + 2 * t;
        *(uint32_t*)(O + headoff + (size_t)r0g * Ec + c) =
            pack2h(Oacc[ni][0] * inv0, Oacc[ni][1] * inv0);
        *(uint32_t*)(O + headoff + (size_t)r1g * Ec + c) =
            pack2h(Oacc[ni][2] * inv1, Oacc[ni][3] * inv1);
    }
}

// ---------------------------------------------------------------------------
// fp16 2-product GEMM via mma.sync + ldmatrix:
//   C(M x N) = A16(M x K) @ (Wh + Wl)(N x K)^T, fp32 accumulate.
// 128x128 tile, K-slab 32, 3-stage cp.async pipeline, 2 CTAs/SM.
// Smem/stage: A@0, Bh@10240, Bl@20480 (128 rows x 80B pitch) = 30720 B.
// EPI 0: Cf = gate[b][n]*(acc+bias[n]) + aux2[m*N+n]
// EPI 1: Ch = fp16( gelu(acc + bias[n]) )
// EPI 2: Cf = acc + bias[n] + aux1[m*N+n]
// ---------------------------------------------------------------------------
#define TG_STAGE 30720
#define TG_SMEM  (3 * TG_STAGE)   // 92160

template <int EPI>
__global__ __launch_bounds__(256, 2)
void tgemm_kernel(const __half* __restrict__ A,
                  const __half* __restrict__ Bh, const __half* __restrict__ Bl,
                  int N, int K,
                  const float* __restrict__ bias,
                  const float* __restrict__ aux1, const float* __restrict__ aux2,
                  float* __restrict__ Cf, __half* __restrict__ Ch)
{
    extern __shared__ __align__(1024) char smc[];
    const uint32_t smem_base = smem_to_u32(smc);
    const int tid = threadIdx.x;
    const int wid = tid >> 5, lid = tid & 31;
    const int g = lid >> 2, t = lid & 3;
    const int wm = wid & 3, wn = wid >> 2;      // warp tile 32(m) x 64(n)
    const int bm = blockIdx.y * 128, bn = blockIdx.x * 128;

    const char* g0 = (const char*)(A  + (size_t)bm * K);
    const char* g1 = (const char*)(Bh + (size_t)bn * K);
    const char* g2 = (const char*)(Bl + (size_t)bn * K);

    auto issue_stage = [&](int st, int kc) {
#pragma unroll
        for (int j = 0; j < 6; ++j) {
            const int linear = j * 256 + tid;         // 0..1535
            const int buf = linear >> 9;              // 0..2
            const int rem = linear & 511;
            const int row = rem >> 2, c16 = rem & 3;
            const char* gb = (buf == 0) ? g0 : (buf == 1) ? g1 : g2;
            const char* src = gb + ((size_t)row * K) * 2 + (size_t)kc * 64 + c16 * 16;
            const uint32_t dst = smem_base + st * TG_STAGE + buf * 10240 + row * 80 + c16 * 16;
            asm volatile("cp.async.cg.shared.global [%0], [%1], 16;"
                         :: "r"(dst), "l"(src) : "memory");
        }
        asm volatile("cp.async.commit_group;" ::: "memory");
    };

    float acc[2][8][4];
#pragma unroll
    for (int mi = 0; mi < 2; ++mi)
#pragma unroll
        for (int ni = 0; ni < 8; ++ni)
#pragma unroll
            for (int q = 0; q < 4; ++q) acc[mi][ni][q] = 0.f;

    const int nt = K >> 5;
    issue_stage(0, 0);
    issue_stage(1, 1);          // nt >= 2 always (K >= 64)

    for (int kc = 0; kc < nt; ++kc) {
        if (kc + 1 < nt) asm volatile("cp.async.wait_group 1;" ::: "memory");
        else             asm volatile("cp.async.wait_group 0;" ::: "memory");
        __syncthreads();
        const uint32_t sb = smem_base + (kc % 3) * TG_STAGE;
#pragma unroll
        for (int ks = 0; ks < 2; ++ks) {
            uint32_t bh_[8][2], bl_[8][2];
#pragma unroll
            for (int p = 0; p < 4; ++p) {
                const uint32_t baddr = sb + 10240 +
                    (uint32_t)(wn * 64 + p * 16 + (lid & 7) + ((lid >> 4) & 1) * 8) * 80 +
                    (uint32_t)(ks * 32 + ((lid >> 3) & 1) * 16);
                ldm_x4(bh_[2 * p][0], bh_[2 * p][1], bh_[2 * p + 1][0], bh_[2 * p + 1][1],
                       baddr);
                ldm_x4(bl_[2 * p][0], bl_[2 * p][1], bl_[2 * p + 1][0], bl_[2 * p + 1][1],
                       baddr + 10240);
            }
#pragma unroll
            for (int mi = 0; mi < 2; ++mi) {
                const uint32_t aaddr = sb +
                    (uint32_t)(wm * 32 + mi * 16 + (lid & 15)) * 80 +
                    (uint32_t)(ks * 32 + ((lid >> 4) & 1) * 16);
                uint32_t a_[4];
                ldm_x4(a_[0], a_[1], a_[2], a_[3], aaddr);
#pragma unroll
                for (int ni = 0; ni < 8; ++ni) {
                    mma_f16(acc[mi][ni], a_, bh_[ni]);
                    mma_f16(acc[mi][ni], a_, bl_[ni]);
                }
            }
        }
        if (kc + 2 < nt) issue_stage((kc + 2) % 3, kc + 2);
    }

    // Epilogue
#pragma unroll
    for (int mi = 0; mi < 2; ++mi) {
#pragma unroll
        for (int ni = 0; ni < 8; ++ni) {
            const int r0 = bm + wm * 32 + mi * 16 + g;
            const int c  = bn + wn * 64 + ni * 8 + 2 * t;
#pragma unroll
            for (int hh = 0; hh < 2; ++hh) {
                const int r = r0 + hh * 8;
                const float v0 = acc[mi][ni][hh * 2 + 0];
                const float v1 = acc[mi][ni][hh * 2 + 1];
                if (EPI == 0) {
                    const float* grow = aux1 + ((r >> 11) << 10);
                    float2 ov;
                    ov.x = grow[c + 0] * (v0 + bias[c + 0]) + aux2[(size_t)r * N + c + 0];
                    ov.y = grow[c + 1] * (v1 + bias[c + 1]) + aux2[(size_t)r * N + c + 1];
                    *(float2*)(Cf + (size_t)r * N + c) = ov;
                } else if (EPI == 1) {
                    float x0 = v0 + bias[c + 0];
                    float x1 = v1 + bias[c + 1];
                    float y0 = 0.5f * x0 * (1.0f + erff(x0 * 0.70710678118654752f));
                    float y1 = 0.5f * x1 * (1.0f + erff(x1 * 0.70710678118654752f));
                    *(uint32_t*)(Ch + (size_t)r * N + c) = pack2h(y0, y1);
                } else {
                    float2 ov;
                    ov.x = v0 + bias[c + 0] + aux1[(size_t)r * N + c + 0];
                    ov.y = v1 + bias[c + 1] + aux1[(size_t)r * N + c + 1];
                    *(float2*)(Cf + (size_t)r * N + c) = ov;
                }
            }
        }
    }
}

// ---------------------------------------------------------------------------
// LayerNorm(1024); optionally emits fp16 alongside fp32
// ---------------------------------------------------------------------------
template <int EMIT>
__global__ void ln1024_kernel(const float* __restrict__ in, const float* __restrict__ g,
                              const float* __restrict__ be, float* __restrict__ out,
                              __half* __restrict__ o16)
{
    __shared__ float red[16];
    const int row = blockIdx.x, tid = threadIdx.x;
    float4 v = ((const float4*)(in + (size_t)row * Ec))[tid];
    float s = v.x + v.y + v.z + v.w;
    float q = v.x * v.x + v.y * v.y + v.z * v.z + v.w * v.w;
#pragma unroll
    for (int ofs = 16; ofs > 0; ofs >>= 1) {
        s += __shfl_xor_sync(0xffffffffu, s, ofs);
        q += __shfl_xor_sync(0xffffffffu, q, ofs);
    }
    const int w = tid >> 5;
    if ((tid & 31) == 0) { red[w] = s; red[8 + w] = q; }
    __syncthreads();
    s = 0.f; q = 0.f;
#pragma unroll
    for (int i = 0; i < 8; ++i) { s += red[i]; q += red[8 + i]; }
    const float mu = s * (1.0f / 1024.0f);
    const float var = q * (1.0f / 1024.0f) - mu * mu;
    const float rs = rsqrtf(var + 1e-5f);
    float4 gg = ((const float4*)g)[tid];
    float4 bb = ((const float4*)be)[tid];
    float4 o;
    o.x = (v.x - mu) * rs * gg.x + bb.x;
    o.y = (v.y - mu) * rs * gg.y + bb.y;
    o.z = (v.z - mu) * rs * gg.z + bb.z;
    o.w = (v.w - mu) * rs * gg.w + bb.w;
    ((float4*)(out + (size_t)row * Ec))[tid] = o;
    if (EMIT) {
        size_t off = (size_t)row * Ec + tid * 4;
        *(uint2*)(o16 + off) = make_uint2(pack2h(o.x, o.y), pack2h(o.z, o.w));
    }
}

// ---------------------------------------------------------------------------
// kernel_launch
// ---------------------------------------------------------------------------
extern "C" void kernel_launch(void* const* d_in, const int* in_sizes, int n_in,
                              void* d_out, int out_size)
{
    (void)in_sizes; (void)n_in; (void)out_size;
    const float* Vv  = (const float*)d_in[0];
    const float* Kk  = (const float*)d_in[1];
    const float* Qq  = (const float*)d_in[2];
    const float* Wo  = (const float*)d_in[4];
    const float* bo  = (const float*)d_in[5];
    const float* Wg  = (const float*)d_in[6];
    const float* bg  = (const float*)d_in[7];
    const float* g1  = (const float*)d_in[8];
    const float* b1  = (const float*)d_in[9];
    const float* g2  = (const float*)d_in[10];
    const float* b2  = (const float*)d_in[11];
    const float* W1  = (const float*)d_in[12];
    const float* bf1 = (const float*)d_in[13];
    const float* W2  = (const float*)d_in[14];
    const float* bf2 = (const float*)d_in[15];
    float* out = (float*)d_out;

    __half *p_a16, *p_x16, *p_h16;
    __half *p_woth, *p_wotl, *p_w1th, *p_w1tl, *p_w2th, *p_w2tl;
    float *p_x, *p_t, *p_part, *p_xavg, *p_gpart, *p_gate;
    cudaGetSymbolAddress((void**)&p_a16, g_a16);
    cudaGetSymbolAddress((void**)&p_x,   g_x);
    cudaGetSymbolAddress((void**)&p_x16, g_x16);
    cudaGetSymbolAddress((void**)&p_t,   g_t);
    cudaGetSymbolAddress((void**)&p_h16, g_h16);
    cudaGetSymbolAddress((void**)&p_woth, g_wot_h);
    cudaGetSymbolAddress((void**)&p_wotl, g_wot_l);
    cudaGetSymbolAddress((void**)&p_w1th, g_w1t_h);
    cudaGetSymbolAddress((void**)&p_w1tl, g_w1t_l);
    cudaGetSymbolAddress((void**)&p_w2th, g_w2t_h);
    cudaGetSymbolAddress((void**)&p_w2tl, g_w2t_l);
    cudaGetSymbolAddress((void**)&p_part,  g_part);
    cudaGetSymbolAddress((void**)&p_xavg,  g_xavg);
    cudaGetSymbolAddress((void**)&p_gpart, g_gpart);
    cudaGetSymbolAddress((void**)&p_gate,  g_gate);

    cudaFuncSetAttribute(tgemm_kernel<0>,
                         cudaFuncAttributeMaxDynamicSharedMemorySize, TG_SMEM);
    cudaFuncSetAttribute(tgemm_kernel<1>,
                         cudaFuncAttributeMaxDynamicSharedMemorySize, TG_SMEM);
    cudaFuncSetAttribute(tgemm_kernel<2>,
                         cudaFuncAttributeMaxDynamicSharedMemorySize, TG_SMEM);

    // weight transpose + fp16 split
    wtrans_kernel<<<dim3(Ec / 32,  Ec / 32),  256>>>(Wo, p_woth, p_wotl, Ec,  Ec);
    wtrans_kernel<<<dim3(FFc / 32, Ec / 32),  256>>>(W1, p_w1th, p_w1tl, Ec,  FFc);
    wtrans_kernel<<<dim3(Ec / 32,  FFc / 32), 256>>>(W2, p_w2th, p_w2tl, FFc, Ec);

    // gate path
    colmean_part_kernel<<<dim3(Bc, 64), 256>>>(Qq, p_part);
    colmean_fin_kernel<<<Bc, 256>>>(p_part, p_xavg);
    gate_part_kernel<<<dim3(Bc * Ec / 256, 8), 256>>>(p_xavg, Wg, p_gpart);
    gate_fin_kernel<<<Bc * Ec / 256, 256>>>(p_gpart, bg, p_gate);

    // attention (fp16 2-product) -> fp16
    flash_attn_mma_kernel<<<dim3(Sc / 64, Bc * Hc), 128>>>(Qq, Kk, Vv, p_a16);

    // Wo proj + gate + residual -> g_t -> LN1 -> x (fp32 + fp16)
    tgemm_kernel<0><<<dim3(Ec / 128, Mrows / 128), 256, TG_SMEM>>>(
        p_a16, p_woth, p_wotl, Ec, Ec, bo, p_gate, Qq, p_t, nullptr);
    ln1024_kernel<1><<<Mrows, 256>>>(p_t, g1, b1, p_x, p_x16);

    // FFN
    tgemm_kernel<1><<<dim3(FFc / 128, Mrows / 128), 256, TG_SMEM>>>(
        p_x16, p_w1th, p_w1tl, FFc, Ec, bf1, nullptr, nullptr, nullptr, p_h16);
    tgemm_kernel<2><<<dim3(Ec / 128, Mrows / 128), 256, TG_SMEM>>>(
        p_h16, p_w2th, p_w2tl, Ec, FFc, bf2, p_x, nullptr, p_t, nullptr);

    ln1024_kernel<0><<<Mrows, 256>>>(p_t, g2, b2, out, nullptr);
}